// round 1
// baseline (speedup 1.0000x reference)
#include <cuda_runtime.h>
#include <cuda_bf16.h>
#include <math_constants.h>

#define NEDGE 320000
#define NATOM 10000
#define HID   128
#define CUT   5.0f

// ---------------- scratch (static device memory; no allocations) ----------------
__device__ __align__(16) float g_rbf[(size_t)NEDGE * 16];
__device__ __align__(16) float g_sbf[(size_t)NEDGE * 7];
__device__ __align__(16) float g_m   [(size_t)NEDGE * HID];
__device__ __align__(16) float g_radf[(size_t)NEDGE * HID];
__device__ __align__(16) float g_mkf [(size_t)NEDGE * HID];
__device__ __align__(16) float g_ang [NEDGE];
__device__ __align__(16) float g_h   [(size_t)NATOM * HID];
__device__ __align__(16) float g_agg [(size_t)NATOM * HID];
__device__ __align__(16) float g_x   [(size_t)NATOM * HID];
__device__ __align__(16) float g_tmp [(size_t)NATOM * HID];

__device__ __forceinline__ float silu_f(float x) { return x / (1.0f + __expf(-x)); }

// ---------------- prep: bessel rbf + spherical feats ----------------
__global__ void prep_kernel(const float* __restrict__ dist, const float* __restrict__ dirs)
{
    int e = blockIdx.x * blockDim.x + threadIdx.x;
    if (e >= NEDGE) return;
    float d = dist[e];
    float x = d * (1.0f / CUT);
    float x2 = x * x;
    float x6 = x2 * x2 * x2;
    float x7 = x6 * x;
    float x8 = x7 * x;
    float env = 1.0f - 28.0f * x6 + 48.0f * x7 - 21.0f * x8;
    if (!(d < CUT)) env = 0.0f;
    float s = sqrtf(2.0f / CUT) / d * env;
    float base = (float)CUDART_PI_F / CUT * d;
#pragma unroll
    for (int k = 0; k < 16; k++)
        g_rbf[(size_t)e * 16 + k] = s * sinf(base * (float)(k + 1));

    float dx = dirs[e * 3 + 0], dy = dirs[e * 3 + 1], dz = dirs[e * 3 + 2];
    float f0 = 1.0f, f1 = dy, f2 = dz, f3 = dx, f4 = dx * dy, f5 = dy * dz, f6 = 3.0f * dz * dz - 1.0f;
    size_t o = (size_t)e * 7;
    g_sbf[o + 0] = f0; g_sbf[o + 1] = f1; g_sbf[o + 2] = f2; g_sbf[o + 3] = f3;
    g_sbf[o + 4] = f4; g_sbf[o + 5] = f5; g_sbf[o + 6] = f6;
}

// ---------------- m init: m = rbf @ embed_w[:,256:384] + embed_b[256:] ----------------
__global__ void m_init_kernel(const float* __restrict__ embed_w, const float* __restrict__ embed_b)
{
    __shared__ float Ws[16 * 128];
    __shared__ float bs[128];
    __shared__ float rs[8 * 16];
    int tid = threadIdx.x;
    for (int i = tid; i < 2048; i += 256)
        Ws[i] = embed_w[(i >> 7) * 384 + 256 + (i & 127)];
    if (tid < 128) bs[tid] = embed_b[256 + tid];
    int e0 = blockIdx.x * 8;
    if (tid < 128) rs[tid] = g_rbf[(size_t)e0 * 16 + tid];
    __syncthreads();
    int w = tid >> 5, lane = tid & 31;
    int e = e0 + w;
    float4 acc = *(const float4*)&bs[lane * 4];
#pragma unroll
    for (int k = 0; k < 16; k++) {
        float a = rs[w * 16 + k];
        float4 wv = *(const float4*)&Ws[k * 128 + lane * 4];
        acc.x += a * wv.x; acc.y += a * wv.y; acc.z += a * wv.z; acc.w += a * wv.w;
    }
    ((float4*)(g_m + (size_t)e * HID))[lane] = acc;
}

// ---------------- h init: embedding gather ----------------
__global__ void h_init_kernel(const int* __restrict__ Z, const float* __restrict__ emb)
{
    int idx = blockIdx.x * blockDim.x + threadIdx.x;
    int a = idx >> 5, lane = idx & 31;
    if (a >= NATOM) return;
    int z = Z[a] - 1;
    ((float4*)(g_h + (size_t)a * HID))[lane] =
        ((const float4*)(emb + (size_t)z * HID))[lane];
}

// ---------------- per-block angle: ang[e] = sigmoid(sbf[e] . wbar + bbar) ----------------
__global__ void angle_kernel(const float* __restrict__ sphW, const float* __restrict__ sphB)
{
    __shared__ float wbar[8];
    __shared__ float bbar;
    if (threadIdx.x < 7) {
        float s = 0.0f;
#pragma unroll
        for (int j = 0; j < 8; j++) s += sphW[threadIdx.x * 8 + j];
        wbar[threadIdx.x] = s * 0.125f;
    }
    if (threadIdx.x == 7) {
        float s = 0.0f;
#pragma unroll
        for (int j = 0; j < 8; j++) s += sphB[j];
        bbar = s * 0.125f;
    }
    __syncthreads();
    int e = blockIdx.x * blockDim.x + threadIdx.x;
    if (e >= NEDGE) return;
    float acc = bbar;
    size_t o = (size_t)e * 7;
#pragma unroll
    for (int k = 0; k < 7; k++) acc += g_sbf[o + k] * wbar[k];
    g_ang[e] = 1.0f / (1.0f + __expf(-acc));
}

// ---------------- shared GEMM core: acc[8][4] += Xs[64,128] @ Ws[128,128] tile ----------------
__device__ __forceinline__ void gemm_core(const float* Ws, const float* Xs,
                                          float acc[8][4], int tx, int ty)
{
#pragma unroll 4
    for (int k = 0; k < 128; k += 4) {
        float4 b0 = *(const float4*)(Ws + (k + 0) * 128 + tx * 4);
        float4 b1 = *(const float4*)(Ws + (k + 1) * 128 + tx * 4);
        float4 b2 = *(const float4*)(Ws + (k + 2) * 128 + tx * 4);
        float4 b3 = *(const float4*)(Ws + (k + 3) * 128 + tx * 4);
#pragma unroll
        for (int i = 0; i < 8; i++) {
            float4 a = *(const float4*)(Xs + (ty * 8 + i) * 128 + k);
            acc[i][0] += a.x * b0.x + a.y * b1.x + a.z * b2.x + a.w * b3.x;
            acc[i][1] += a.x * b0.y + a.y * b1.y + a.z * b2.y + a.w * b3.y;
            acc[i][2] += a.x * b0.z + a.y * b1.z + a.z * b2.z + a.w * b3.z;
            acc[i][3] += a.x * b0.w + a.y * b1.w + a.z * b2.w + a.w * b3.w;
        }
    }
}

// ---------------- generic 128x128 GEMM: Y = epi(pre(X) @ W + b) ----------------
#define GEMM_SMEM ((16384 + 8192) * 4)
template<bool PRE_SILU, bool SILU_OUT, bool ACCUM>
__global__ void __launch_bounds__(256, 2) gemm128(const float* __restrict__ X,
                                                  const float* __restrict__ W,
                                                  const float* __restrict__ bias,
                                                  float* __restrict__ Y, int nrows)
{
    extern __shared__ float sm[];
    float* Ws = sm;            // 128*128
    float* Xs = sm + 16384;    // 64*128
    const int tid = threadIdx.x;
    const int row0 = blockIdx.x * 64;
    for (int i = tid; i < 4096; i += 256) ((float4*)Ws)[i] = ((const float4*)W)[i];
    const int rows = min(64, nrows - row0);
    for (int i = tid; i < 2048; i += 256) {
        int r = i >> 5, c = i & 31;
        float4 v = make_float4(0.f, 0.f, 0.f, 0.f);
        if (r < rows) v = ((const float4*)(X + (size_t)(row0 + r) * 128))[c];
        if (PRE_SILU) { v.x = silu_f(v.x); v.y = silu_f(v.y); v.z = silu_f(v.z); v.w = silu_f(v.w); }
        ((float4*)Xs)[i] = v;
    }
    __syncthreads();
    const int tx = tid & 31, ty = tid >> 5;
    float acc[8][4];
#pragma unroll
    for (int i = 0; i < 8; i++) { acc[i][0] = 0.f; acc[i][1] = 0.f; acc[i][2] = 0.f; acc[i][3] = 0.f; }
    gemm_core(Ws, Xs, acc, tx, ty);

    float4 bv = make_float4(0.f, 0.f, 0.f, 0.f);
    if (bias) bv = ((const float4*)bias)[tx];
#pragma unroll
    for (int i = 0; i < 8; i++) {
        int r = ty * 8 + i;
        if (r >= rows) break;
        float4 o;
        o.x = acc[i][0] + bv.x; o.y = acc[i][1] + bv.y; o.z = acc[i][2] + bv.z; o.w = acc[i][3] + bv.w;
        if (SILU_OUT) { o.x = silu_f(o.x); o.y = silu_f(o.y); o.z = silu_f(o.z); o.w = silu_f(o.w); }
        float* yp = Y + (size_t)(row0 + r) * 128 + tx * 4;
        if (ACCUM) {
            float4 old = *(float4*)yp;
            o.x += old.x; o.y += old.y; o.z += old.z; o.w += old.w;
        }
        *(float4*)yp = o;
    }
}

// ---------------- fused radial MLP: Y = silu(rbf @ W1 + b1) @ W2 + b2 ----------------
#define RAD_SMEM ((16384 + 8192 + 2048 + 128 + 1024) * 4)
__global__ void __launch_bounds__(256, 2) rad_mlp_kernel(const float* __restrict__ rW1,
                                                         const float* __restrict__ rb1,
                                                         const float* __restrict__ rW2,
                                                         const float* __restrict__ rb2,
                                                         float* __restrict__ Y, int nrows)
{
    extern __shared__ float sm[];
    float* W2s = sm;                     // 16384
    float* Hs  = sm + 16384;             // 8192
    float* W1s = sm + 16384 + 8192;      // 2048
    float* b1s = W1s + 2048;             // 128
    float* Rs  = b1s + 128;              // 1024
    const int tid = threadIdx.x;
    const int row0 = blockIdx.x * 64;
    for (int i = tid; i < 4096; i += 256) ((float4*)W2s)[i] = ((const float4*)rW2)[i];
    for (int i = tid; i < 512;  i += 256) ((float4*)W1s)[i] = ((const float4*)rW1)[i];
    if (tid < 32) ((float4*)b1s)[tid] = ((const float4*)rb1)[tid];
    const int rows = min(64, nrows - row0);
    if (tid < 256) {
        int i = tid;                     // 64*16/4 = 256 float4
        int r = i >> 2;
        float4 v = make_float4(0.f, 0.f, 0.f, 0.f);
        if (r < rows) v = ((const float4*)(g_rbf + (size_t)(row0 + r) * 16))[i & 3];
        ((float4*)Rs)[i] = v;
    }
    __syncthreads();
    const int tx = tid & 31, ty = tid >> 5;
    // hidden = silu(rbf @ W1 + b1)
    float4 b1v = *(const float4*)&b1s[tx * 4];
#pragma unroll
    for (int i = 0; i < 8; i++) {
        int r = ty * 8 + i;
        float4 acc = b1v;
#pragma unroll
        for (int k = 0; k < 16; k++) {
            float a = Rs[r * 16 + k];
            float4 w = *(const float4*)&W1s[k * 128 + tx * 4];
            acc.x += a * w.x; acc.y += a * w.y; acc.z += a * w.z; acc.w += a * w.w;
        }
        acc.x = silu_f(acc.x); acc.y = silu_f(acc.y); acc.z = silu_f(acc.z); acc.w = silu_f(acc.w);
        *(float4*)&Hs[r * 128 + tx * 4] = acc;
    }
    __syncthreads();
    float acc[8][4];
#pragma unroll
    for (int i = 0; i < 8; i++) { acc[i][0] = 0.f; acc[i][1] = 0.f; acc[i][2] = 0.f; acc[i][3] = 0.f; }
    gemm_core(W2s, Hs, acc, tx, ty);
    float4 b2v = ((const float4*)rb2)[tx];
#pragma unroll
    for (int i = 0; i < 8; i++) {
        int r = ty * 8 + i;
        if (r >= rows) break;
        float4 o;
        o.x = acc[i][0] + b2v.x; o.y = acc[i][1] + b2v.y; o.z = acc[i][2] + b2v.z; o.w = acc[i][3] + b2v.w;
        *(float4*)(Y + (size_t)(row0 + r) * 128 + tx * 4) = o;
    }
}

// ---------------- triplet: mkf[t] = m[kj]*radf[kj]*ang[ji]; agg[dst[t]] += mkf[t] ----------------
__global__ void triplet_kernel(const int* __restrict__ trip, const int* __restrict__ ei)
{
    int gw = (blockIdx.x * blockDim.x + threadIdx.x) >> 5;
    int lane = threadIdx.x & 31;
    if (gw >= NEDGE) return;
    int ji = trip[gw * 3 + 0];
    int kj = trip[gw * 3 + 1];
    float aw = g_ang[ji];
    float4 mv = ((const float4*)(g_m    + (size_t)kj * HID))[lane];
    float4 rv = ((const float4*)(g_radf + (size_t)kj * HID))[lane];
    float4 o = make_float4(mv.x * rv.x * aw, mv.y * rv.y * aw, mv.z * rv.z * aw, mv.w * rv.w * aw);
    ((float4*)(g_mkf + (size_t)gw * HID))[lane] = o;
    int dd = ei[NEDGE + gw];
    float* p = g_agg + (size_t)dd * HID + lane * 4;
    atomicAdd(p + 0, o.x); atomicAdd(p + 1, o.y); atomicAdd(p + 2, o.z); atomicAdd(p + 3, o.w);
}

// ---------------- edge scatter (output block): x[dst[e]] += h[src[e]] * radf[e] ----------------
__global__ void scatter_kernel(const int* __restrict__ ei)
{
    int gw = (blockIdx.x * blockDim.x + threadIdx.x) >> 5;
    int lane = threadIdx.x & 31;
    if (gw >= NEDGE) return;
    int s  = ei[gw];
    int dd = ei[NEDGE + gw];
    float4 hv = ((const float4*)(g_h    + (size_t)s  * HID))[lane];
    float4 wv = ((const float4*)(g_radf + (size_t)gw * HID))[lane];
    float* p = g_x + (size_t)dd * HID + lane * 4;
    atomicAdd(p + 0, hv.x * wv.x); atomicAdd(p + 1, hv.y * wv.y);
    atomicAdd(p + 2, hv.z * wv.z); atomicAdd(p + 3, hv.w * wv.w);
}

// ---------------- output projection: out[a] (+)= x[a] . w + b ----------------
template<bool ACCUM>
__global__ void outproj_kernel(const float* __restrict__ w, const float* __restrict__ b,
                               float* __restrict__ out)
{
    int idx = blockIdx.x * blockDim.x + threadIdx.x;
    int a = idx >> 5, lane = idx & 31;
    if (a >= NATOM) return;
    float4 xv = ((const float4*)(g_x + (size_t)a * HID))[lane];
    float4 wv = ((const float4*)w)[lane];
    float s = xv.x * wv.x + xv.y * wv.y + xv.z * wv.z + xv.w * wv.w;
#pragma unroll
    for (int off = 16; off > 0; off >>= 1) s += __shfl_xor_sync(0xFFFFFFFFu, s, off);
    if (lane == 0) {
        float v = s + b[0];
        if (ACCUM) out[a] += v; else out[a] = v;
    }
}

// ---------------- host launcher ----------------
extern "C" void kernel_launch(void* const* d_in, const int* in_sizes, int n_in,
                              void* d_out, int out_size)
{
    const int*   Z        = (const int*)d_in[0];
    const int*   ei       = (const int*)d_in[1];
    const float* dist     = (const float*)d_in[2];
    const float* dirs     = (const float*)d_in[3];
    const int*   trip     = (const int*)d_in[4];
    const float* atom_emb = (const float*)d_in[5];
    const float* embed_w  = (const float*)d_in[6];
    const float* embed_b  = (const float*)d_in[7];
    const float* ib_rad_w1 = (const float*)d_in[8];
    const float* ib_rad_b1 = (const float*)d_in[9];
    const float* ib_rad_w2 = (const float*)d_in[10];
    const float* ib_rad_b2 = (const float*)d_in[11];
    const float* ib_sph_w  = (const float*)d_in[12];
    const float* ib_sph_b  = (const float*)d_in[13];
    const float* ib_upd_w1 = (const float*)d_in[14];
    const float* ib_upd_b1 = (const float*)d_in[15];
    const float* ib_upd_w2 = (const float*)d_in[16];
    const float* ib_upd_b2 = (const float*)d_in[17];
    const float* ib_out_w  = (const float*)d_in[18];
    const float* ib_out_b  = (const float*)d_in[19];
    const float* ob_rad_w1 = (const float*)d_in[20];
    const float* ob_rad_b1 = (const float*)d_in[21];
    const float* ob_rad_w2 = (const float*)d_in[22];
    const float* ob_rad_b2 = (const float*)d_in[23];
    const float* ob_dense_w = (const float*)d_in[24];
    const float* ob_dense_b = (const float*)d_in[25];
    const float* ob_out_w  = (const float*)d_in[26];
    const float* ob_out_b  = (const float*)d_in[27];
    float* out = (float*)d_out;

    float *p_radf, *p_m, *p_mkf, *p_h, *p_agg, *p_x, *p_tmp;
    cudaGetSymbolAddress((void**)&p_radf, g_radf);
    cudaGetSymbolAddress((void**)&p_m,    g_m);
    cudaGetSymbolAddress((void**)&p_mkf,  g_mkf);
    cudaGetSymbolAddress((void**)&p_h,    g_h);
    cudaGetSymbolAddress((void**)&p_agg,  g_agg);
    cudaGetSymbolAddress((void**)&p_x,    g_x);
    cudaGetSymbolAddress((void**)&p_tmp,  g_tmp);

    cudaFuncSetAttribute(gemm128<false,false,false>, cudaFuncAttributeMaxDynamicSharedMemorySize, GEMM_SMEM);
    cudaFuncSetAttribute(gemm128<false,false,true >, cudaFuncAttributeMaxDynamicSharedMemorySize, GEMM_SMEM);
    cudaFuncSetAttribute(gemm128<true ,false,true >, cudaFuncAttributeMaxDynamicSharedMemorySize, GEMM_SMEM);
    cudaFuncSetAttribute(gemm128<false,true ,true >, cudaFuncAttributeMaxDynamicSharedMemorySize, GEMM_SMEM);
    cudaFuncSetAttribute(gemm128<false,true ,false>, cudaFuncAttributeMaxDynamicSharedMemorySize, GEMM_SMEM);
    cudaFuncSetAttribute(rad_mlp_kernel, cudaFuncAttributeMaxDynamicSharedMemorySize, RAD_SMEM);

    const int GE = NEDGE / 64;            // 5000
    const int GA = (NATOM + 63) / 64;     // 157
    const int GW = NEDGE * 32 / 256;      // 40000 (warp-per-edge kernels)

    prep_kernel<<<(NEDGE + 255) / 256, 256>>>(dist, dirs);
    m_init_kernel<<<NEDGE / 8, 256>>>(embed_w, embed_b);
    h_init_kernel<<<(NATOM * 32 + 255) / 256, 256>>>(Z, atom_emb);

    // ---- output block 0 (writes out) ----
    rad_mlp_kernel<<<GE, 256, RAD_SMEM>>>(ob_rad_w1, ob_rad_b1, ob_rad_w2, ob_rad_b2, p_radf, NEDGE);
    cudaMemsetAsync(p_x, 0, (size_t)NATOM * HID * sizeof(float));
    scatter_kernel<<<GW, 256>>>(ei);
    for (int j = 0; j < 3; j++)
        gemm128<false,true,false><<<GA, 256, GEMM_SMEM>>>(p_x, ob_dense_w + (size_t)j * 16384,
                                                          ob_dense_b + j * 128, p_x, NATOM);
    outproj_kernel<false><<<(NATOM * 32 + 255) / 256, 256>>>(ob_out_w, ob_out_b, out);

    for (int i = 0; i < 4; i++) {
        // radial feats + angles
        rad_mlp_kernel<<<GE, 256, RAD_SMEM>>>(ib_rad_w1 + (size_t)i * 2048, ib_rad_b1 + i * 128,
                                              ib_rad_w2 + (size_t)i * 16384, ib_rad_b2 + i * 128,
                                              p_radf, NEDGE);
        angle_kernel<<<(NEDGE + 255) / 256, 256>>>(ib_sph_w + i * 56, ib_sph_b + i * 8);
        // triplet interaction + aggregation
        cudaMemsetAsync(p_agg, 0, (size_t)NATOM * HID * sizeof(float));
        triplet_kernel<<<GW, 256>>>(trip, ei);
        // h update: h += silu([h,agg] @ W1 + b1) @ W2 + b2
        gemm128<false,false,false><<<GA, 256, GEMM_SMEM>>>(p_h,  ib_upd_w1 + (size_t)i * 32768,
                                                           ib_upd_b1 + i * 128, p_tmp, NATOM);
        gemm128<false,false,true ><<<GA, 256, GEMM_SMEM>>>(p_agg, ib_upd_w1 + (size_t)i * 32768 + 16384,
                                                           nullptr, p_tmp, NATOM);
        gemm128<true ,false,true ><<<GA, 256, GEMM_SMEM>>>(p_tmp, ib_upd_w2 + (size_t)i * 16384,
                                                           ib_upd_b2 + i * 128, p_h, NATOM);
        // m update: m += sum_j silu(mkf @ Wj + bj)
        for (int j = 0; j < 3; j++)
            gemm128<false,true,true><<<GE, 256, GEMM_SMEM>>>(p_mkf,
                ib_out_w + ((size_t)(i * 3 + j)) * 16384, ib_out_b + (i * 3 + j) * 128, p_m, NEDGE);
        // ---- output block i+1 (accumulates into out) ----
        int ob = i + 1;
        rad_mlp_kernel<<<GE, 256, RAD_SMEM>>>(ob_rad_w1 + (size_t)ob * 2048, ob_rad_b1 + ob * 128,
                                              ob_rad_w2 + (size_t)ob * 16384, ob_rad_b2 + ob * 128,
                                              p_radf, NEDGE);
        cudaMemsetAsync(p_x, 0, (size_t)NATOM * HID * sizeof(float));
        scatter_kernel<<<GW, 256>>>(ei);
        for (int j = 0; j < 3; j++)
            gemm128<false,true,false><<<GA, 256, GEMM_SMEM>>>(p_x,
                ob_dense_w + ((size_t)(ob * 3 + j)) * 16384, ob_dense_b + (ob * 3 + j) * 128, p_x, NATOM);
        outproj_kernel<true><<<(NATOM * 32 + 255) / 256, 256>>>(ob_out_w + ob * 128, ob_out_b + ob, out);
    }
}

// round 2
// speedup vs baseline: 1.1096x; 1.1096x over previous
#include <cuda_runtime.h>
#include <cuda_bf16.h>
#include <math_constants.h>

#define NEDGE 320000
#define NATOM 10000
#define HID   128
#define CUT   5.0f

typedef unsigned long long u64;

// ---------------- scratch (static device memory; no allocations) ----------------
__device__ __align__(16) float g_rbf[(size_t)NEDGE * 16];
__device__ __align__(16) float g_sbf[(size_t)NEDGE * 7];
__device__ __align__(16) float g_m   [(size_t)NEDGE * HID];
__device__ __align__(16) float g_radf[(size_t)NEDGE * HID];
__device__ __align__(16) float g_mkf [(size_t)NEDGE * HID];
__device__ __align__(16) float g_ang [NEDGE];
__device__ __align__(16) float g_h   [(size_t)NATOM * HID];
__device__ __align__(16) float g_agg [(size_t)NATOM * HID];
__device__ __align__(16) float g_x   [(size_t)NATOM * HID];
__device__ __align__(16) float g_tmp [(size_t)NATOM * HID];

__device__ __forceinline__ float silu_f(float x) { return x / (1.0f + __expf(-x)); }

// ---------------- packed f32x2 helpers (Blackwell 2-wide fp32 FMA) ----------------
__device__ __forceinline__ u64 pack2(float a) {
    u64 r; asm("mov.b64 %0, {%1, %1};" : "=l"(r) : "f"(a)); return r;
}
__device__ __forceinline__ void fma2(u64& d, u64 a, u64 b) {
    asm("fma.rn.f32x2 %0, %1, %2, %3;" : "=l"(d) : "l"(a), "l"(b), "l"(d));
}
__device__ __forceinline__ float2 unpack2(u64 v) {
    float2 f; asm("mov.b64 {%0, %1}, %2;" : "=f"(f.x), "=f"(f.y) : "l"(v)); return f;
}

// ---------------- prep: bessel rbf + spherical feats ----------------
__global__ void prep_kernel(const float* __restrict__ dist, const float* __restrict__ dirs)
{
    int e = blockIdx.x * blockDim.x + threadIdx.x;
    if (e >= NEDGE) return;
    float d = dist[e];
    float x = d * (1.0f / CUT);
    float x2 = x * x;
    float x6 = x2 * x2 * x2;
    float x7 = x6 * x;
    float x8 = x7 * x;
    float env = 1.0f - 28.0f * x6 + 48.0f * x7 - 21.0f * x8;
    if (!(d < CUT)) env = 0.0f;
    float s = sqrtf(2.0f / CUT) / d * env;
    float base = (float)CUDART_PI_F / CUT * d;
#pragma unroll
    for (int k = 0; k < 16; k++)
        g_rbf[(size_t)e * 16 + k] = s * sinf(base * (float)(k + 1));

    float dx = dirs[e * 3 + 0], dy = dirs[e * 3 + 1], dz = dirs[e * 3 + 2];
    size_t o = (size_t)e * 7;
    g_sbf[o + 0] = 1.0f; g_sbf[o + 1] = dy; g_sbf[o + 2] = dz; g_sbf[o + 3] = dx;
    g_sbf[o + 4] = dx * dy; g_sbf[o + 5] = dy * dz; g_sbf[o + 6] = 3.0f * dz * dz - 1.0f;
}

// ---------------- m init: m = rbf @ embed_w[:,256:384] + embed_b[256:] ----------------
__global__ void m_init_kernel(const float* __restrict__ embed_w, const float* __restrict__ embed_b)
{
    __shared__ float Ws[16 * 128];
    __shared__ float bs[128];
    __shared__ float rs[8 * 16];
    int tid = threadIdx.x;
    for (int i = tid; i < 2048; i += 256)
        Ws[i] = embed_w[(i >> 7) * 384 + 256 + (i & 127)];
    if (tid < 128) bs[tid] = embed_b[256 + tid];
    int e0 = blockIdx.x * 8;
    if (tid < 128) rs[tid] = g_rbf[(size_t)e0 * 16 + tid];
    __syncthreads();
    int w = tid >> 5, lane = tid & 31;
    int e = e0 + w;
    float4 acc = *(const float4*)&bs[lane * 4];
#pragma unroll
    for (int k = 0; k < 16; k++) {
        float a = rs[w * 16 + k];
        float4 wv = *(const float4*)&Ws[k * 128 + lane * 4];
        acc.x += a * wv.x; acc.y += a * wv.y; acc.z += a * wv.z; acc.w += a * wv.w;
    }
    ((float4*)(g_m + (size_t)e * HID))[lane] = acc;
}

// ---------------- h init: embedding gather ----------------
__global__ void h_init_kernel(const int* __restrict__ Z, const float* __restrict__ emb)
{
    int idx = blockIdx.x * blockDim.x + threadIdx.x;
    int a = idx >> 5, lane = idx & 31;
    if (a >= NATOM) return;
    int z = Z[a] - 1;
    ((float4*)(g_h + (size_t)a * HID))[lane] =
        ((const float4*)(emb + (size_t)z * HID))[lane];
}

// ---------------- per-block angle: ang[e] = sigmoid(sbf[e] . wbar + bbar) ----------------
__global__ void angle_kernel(const float* __restrict__ sphW, const float* __restrict__ sphB)
{
    __shared__ float wbar[8];
    __shared__ float bbar;
    if (threadIdx.x < 7) {
        float s = 0.0f;
#pragma unroll
        for (int j = 0; j < 8; j++) s += sphW[threadIdx.x * 8 + j];
        wbar[threadIdx.x] = s * 0.125f;
    }
    if (threadIdx.x == 7) {
        float s = 0.0f;
#pragma unroll
        for (int j = 0; j < 8; j++) s += sphB[j];
        bbar = s * 0.125f;
    }
    __syncthreads();
    int e = blockIdx.x * blockDim.x + threadIdx.x;
    if (e >= NEDGE) return;
    float acc = bbar;
    size_t o = (size_t)e * 7;
#pragma unroll
    for (int k = 0; k < 7; k++) acc += g_sbf[o + k] * wbar[k];
    g_ang[e] = 1.0f / (1.0f + __expf(-acc));
}

// ---------------- shared GEMM core (f32x2): acc2[8][2] += Xs[64,128] @ Ws[128,128] ----------------
__device__ __forceinline__ void gemm_core2(const float* Ws, const float* Xs,
                                           u64 acc2[8][2], int tx, int ty)
{
#pragma unroll 4
    for (int k = 0; k < 128; k += 4) {
        ulonglong2 b0 = *(const ulonglong2*)(Ws + (k + 0) * 128 + tx * 4);
        ulonglong2 b1 = *(const ulonglong2*)(Ws + (k + 1) * 128 + tx * 4);
        ulonglong2 b2 = *(const ulonglong2*)(Ws + (k + 2) * 128 + tx * 4);
        ulonglong2 b3 = *(const ulonglong2*)(Ws + (k + 3) * 128 + tx * 4);
#pragma unroll
        for (int i = 0; i < 8; i++) {
            float4 a = *(const float4*)(Xs + (ty * 8 + i) * 128 + k);
            u64 ax = pack2(a.x), ay = pack2(a.y), az = pack2(a.z), aw = pack2(a.w);
            fma2(acc2[i][0], ax, b0.x); fma2(acc2[i][1], ax, b0.y);
            fma2(acc2[i][0], ay, b1.x); fma2(acc2[i][1], ay, b1.y);
            fma2(acc2[i][0], az, b2.x); fma2(acc2[i][1], az, b2.y);
            fma2(acc2[i][0], aw, b3.x); fma2(acc2[i][1], aw, b3.y);
        }
    }
}

// ---------------- generic 128x128 GEMM: Y = epi(pre(X) @ W + b) ----------------
#define GEMM_SMEM ((16384 + 8192) * 4)
template<bool PRE_SILU, bool SILU_OUT, bool ACCUM>
__global__ void __launch_bounds__(256, 2) gemm128(const float* __restrict__ X,
                                                  const float* __restrict__ W,
                                                  const float* __restrict__ bias,
                                                  float* __restrict__ Y, int nrows)
{
    extern __shared__ float sm[];
    float* Ws = sm;            // 128*128
    float* Xs = sm + 16384;    // 64*128
    const int tid = threadIdx.x;
    const int row0 = blockIdx.x * 64;
    for (int i = tid; i < 4096; i += 256) ((float4*)Ws)[i] = ((const float4*)W)[i];
    const int rows = min(64, nrows - row0);
    for (int i = tid; i < 2048; i += 256) {
        int r = i >> 5, c = i & 31;
        float4 v = make_float4(0.f, 0.f, 0.f, 0.f);
        if (r < rows) v = ((const float4*)(X + (size_t)(row0 + r) * 128))[c];
        if (PRE_SILU) { v.x = silu_f(v.x); v.y = silu_f(v.y); v.z = silu_f(v.z); v.w = silu_f(v.w); }
        ((float4*)Xs)[i] = v;
    }
    __syncthreads();
    const int tx = tid & 31, ty = tid >> 5;
    u64 acc2[8][2];
    u64 z = pack2(0.0f);
#pragma unroll
    for (int i = 0; i < 8; i++) { acc2[i][0] = z; acc2[i][1] = z; }
    gemm_core2(Ws, Xs, acc2, tx, ty);

    float4 bv = make_float4(0.f, 0.f, 0.f, 0.f);
    if (bias) bv = ((const float4*)bias)[tx];
#pragma unroll
    for (int i = 0; i < 8; i++) {
        int r = ty * 8 + i;
        if (r >= rows) break;
        float2 lo = unpack2(acc2[i][0]);
        float2 hi = unpack2(acc2[i][1]);
        float4 o;
        o.x = lo.x + bv.x; o.y = lo.y + bv.y; o.z = hi.x + bv.z; o.w = hi.y + bv.w;
        if (SILU_OUT) { o.x = silu_f(o.x); o.y = silu_f(o.y); o.z = silu_f(o.z); o.w = silu_f(o.w); }
        float* yp = Y + (size_t)(row0 + r) * 128 + tx * 4;
        if (ACCUM) {
            float4 old = *(float4*)yp;
            o.x += old.x; o.y += old.y; o.z += old.z; o.w += old.w;
        }
        *(float4*)yp = o;
    }
}

// ---------------- fused radial MLP: Y = silu(rbf @ W1 + b1) @ W2 + b2 ----------------
#define RAD_SMEM ((16384 + 8192 + 2048 + 128 + 1024) * 4)
__global__ void __launch_bounds__(256, 2) rad_mlp_kernel(const float* __restrict__ rW1,
                                                         const float* __restrict__ rb1,
                                                         const float* __restrict__ rW2,
                                                         const float* __restrict__ rb2,
                                                         float* __restrict__ Y, int nrows)
{
    extern __shared__ float sm[];
    float* W2s = sm;                     // 16384
    float* Hs  = sm + 16384;             // 8192
    float* W1s = sm + 16384 + 8192;      // 2048
    float* b1s = W1s + 2048;             // 128
    float* Rs  = b1s + 128;              // 1024
    const int tid = threadIdx.x;
    const int row0 = blockIdx.x * 64;
    for (int i = tid; i < 4096; i += 256) ((float4*)W2s)[i] = ((const float4*)rW2)[i];
    for (int i = tid; i < 512;  i += 256) ((float4*)W1s)[i] = ((const float4*)rW1)[i];
    if (tid < 32) ((float4*)b1s)[tid] = ((const float4*)rb1)[tid];
    const int rows = min(64, nrows - row0);
    if (tid < 256) {
        int i = tid;                     // 64*16/4 = 256 float4
        int r = i >> 2;
        float4 v = make_float4(0.f, 0.f, 0.f, 0.f);
        if (r < rows) v = ((const float4*)(g_rbf + (size_t)(row0 + r) * 16))[i & 3];
        ((float4*)Rs)[i] = v;
    }
    __syncthreads();
    const int tx = tid & 31, ty = tid >> 5;
    // hidden = silu(rbf @ W1 + b1)
    float4 b1v = *(const float4*)&b1s[tx * 4];
#pragma unroll
    for (int i = 0; i < 8; i++) {
        int r = ty * 8 + i;
        float4 acc = b1v;
#pragma unroll
        for (int k = 0; k < 16; k++) {
            float a = Rs[r * 16 + k];
            float4 w = *(const float4*)&W1s[k * 128 + tx * 4];
            acc.x += a * w.x; acc.y += a * w.y; acc.z += a * w.z; acc.w += a * w.w;
        }
        acc.x = silu_f(acc.x); acc.y = silu_f(acc.y); acc.z = silu_f(acc.z); acc.w = silu_f(acc.w);
        *(float4*)&Hs[r * 128 + tx * 4] = acc;
    }
    __syncthreads();
    u64 acc2[8][2];
    u64 z = pack2(0.0f);
#pragma unroll
    for (int i = 0; i < 8; i++) { acc2[i][0] = z; acc2[i][1] = z; }
    gemm_core2(W2s, Hs, acc2, tx, ty);
    float4 b2v = ((const float4*)rb2)[tx];
#pragma unroll
    for (int i = 0; i < 8; i++) {
        int r = ty * 8 + i;
        if (r >= rows) break;
        float2 lo = unpack2(acc2[i][0]);
        float2 hi = unpack2(acc2[i][1]);
        float4 o;
        o.x = lo.x + b2v.x; o.y = lo.y + b2v.y; o.z = hi.x + b2v.z; o.w = hi.y + b2v.w;
        *(float4*)(Y + (size_t)(row0 + r) * 128 + tx * 4) = o;
    }
}

// ---------------- triplet: mkf[t] = m[kj]*radf[kj]*ang[ji]; agg[dst[t]] += mkf[t] ----------------
__global__ void triplet_kernel(const int* __restrict__ trip, const int* __restrict__ ei)
{
    int gw = (blockIdx.x * blockDim.x + threadIdx.x) >> 5;
    int lane = threadIdx.x & 31;
    if (gw >= NEDGE) return;
    int ji = trip[gw * 3 + 0];
    int kj = trip[gw * 3 + 1];
    float aw = g_ang[ji];
    float4 mv = ((const float4*)(g_m    + (size_t)kj * HID))[lane];
    float4 rv = ((const float4*)(g_radf + (size_t)kj * HID))[lane];
    float4 o = make_float4(mv.x * rv.x * aw, mv.y * rv.y * aw, mv.z * rv.z * aw, mv.w * rv.w * aw);
    ((float4*)(g_mkf + (size_t)gw * HID))[lane] = o;
    int dd = ei[NEDGE + gw];
    float* p = g_agg + (size_t)dd * HID + lane * 4;
    atomicAdd(p + 0, o.x); atomicAdd(p + 1, o.y); atomicAdd(p + 2, o.z); atomicAdd(p + 3, o.w);
}

// ---------------- edge scatter (output block): x[dst[e]] += h[src[e]] * radf[e] ----------------
__global__ void scatter_kernel(const int* __restrict__ ei)
{
    int gw = (blockIdx.x * blockDim.x + threadIdx.x) >> 5;
    int lane = threadIdx.x & 31;
    if (gw >= NEDGE) return;
    int s  = ei[gw];
    int dd = ei[NEDGE + gw];
    float4 hv = ((const float4*)(g_h    + (size_t)s  * HID))[lane];
    float4 wv = ((const float4*)(g_radf + (size_t)gw * HID))[lane];
    float* p = g_x + (size_t)dd * HID + lane * 4;
    atomicAdd(p + 0, hv.x * wv.x); atomicAdd(p + 1, hv.y * wv.y);
    atomicAdd(p + 2, hv.z * wv.z); atomicAdd(p + 3, hv.w * wv.w);
}

// ---------------- output projection: out[a] (+)= x[a] . w + b ----------------
template<bool ACCUM>
__global__ void outproj_kernel(const float* __restrict__ w, const float* __restrict__ b,
                               float* __restrict__ out)
{
    int idx = blockIdx.x * blockDim.x + threadIdx.x;
    int a = idx >> 5, lane = idx & 31;
    if (a >= NATOM) return;
    float4 xv = ((const float4*)(g_x + (size_t)a * HID))[lane];
    float4 wv = ((const float4*)w)[lane];
    float s = xv.x * wv.x + xv.y * wv.y + xv.z * wv.z + xv.w * wv.w;
#pragma unroll
    for (int off = 16; off > 0; off >>= 1) s += __shfl_xor_sync(0xFFFFFFFFu, s, off);
    if (lane == 0) {
        float v = s + b[0];
        if (ACCUM) out[a] += v; else out[a] = v;
    }
}

// ---------------- host launcher ----------------
extern "C" void kernel_launch(void* const* d_in, const int* in_sizes, int n_in,
                              void* d_out, int out_size)
{
    const int*   Z        = (const int*)d_in[0];
    const int*   ei       = (const int*)d_in[1];
    const float* dist     = (const float*)d_in[2];
    const float* dirs     = (const float*)d_in[3];
    const int*   trip     = (const int*)d_in[4];
    const float* atom_emb = (const float*)d_in[5];
    const float* embed_w  = (const float*)d_in[6];
    const float* embed_b  = (const float*)d_in[7];
    const float* ib_rad_w1 = (const float*)d_in[8];
    const float* ib_rad_b1 = (const float*)d_in[9];
    const float* ib_rad_w2 = (const float*)d_in[10];
    const float* ib_rad_b2 = (const float*)d_in[11];
    const float* ib_sph_w  = (const float*)d_in[12];
    const float* ib_sph_b  = (const float*)d_in[13];
    const float* ib_upd_w1 = (const float*)d_in[14];
    const float* ib_upd_b1 = (const float*)d_in[15];
    const float* ib_upd_w2 = (const float*)d_in[16];
    const float* ib_upd_b2 = (const float*)d_in[17];
    const float* ib_out_w  = (const float*)d_in[18];
    const float* ib_out_b  = (const float*)d_in[19];
    const float* ob_rad_w1 = (const float*)d_in[20];
    const float* ob_rad_b1 = (const float*)d_in[21];
    const float* ob_rad_w2 = (const float*)d_in[22];
    const float* ob_rad_b2 = (const float*)d_in[23];
    const float* ob_dense_w = (const float*)d_in[24];
    const float* ob_dense_b = (const float*)d_in[25];
    const float* ob_out_w  = (const float*)d_in[26];
    const float* ob_out_b  = (const float*)d_in[27];
    float* out = (float*)d_out;

    float *p_radf, *p_m, *p_mkf, *p_h, *p_agg, *p_x, *p_tmp;
    cudaGetSymbolAddress((void**)&p_radf, g_radf);
    cudaGetSymbolAddress((void**)&p_m,    g_m);
    cudaGetSymbolAddress((void**)&p_mkf,  g_mkf);
    cudaGetSymbolAddress((void**)&p_h,    g_h);
    cudaGetSymbolAddress((void**)&p_agg,  g_agg);
    cudaGetSymbolAddress((void**)&p_x,    g_x);
    cudaGetSymbolAddress((void**)&p_tmp,  g_tmp);

    cudaFuncSetAttribute(gemm128<false,false,false>, cudaFuncAttributeMaxDynamicSharedMemorySize, GEMM_SMEM);
    cudaFuncSetAttribute(gemm128<false,false,true >, cudaFuncAttributeMaxDynamicSharedMemorySize, GEMM_SMEM);
    cudaFuncSetAttribute(gemm128<true ,false,true >, cudaFuncAttributeMaxDynamicSharedMemorySize, GEMM_SMEM);
    cudaFuncSetAttribute(gemm128<false,true ,true >, cudaFuncAttributeMaxDynamicSharedMemorySize, GEMM_SMEM);
    cudaFuncSetAttribute(gemm128<false,true ,false>, cudaFuncAttributeMaxDynamicSharedMemorySize, GEMM_SMEM);
    cudaFuncSetAttribute(rad_mlp_kernel, cudaFuncAttributeMaxDynamicSharedMemorySize, RAD_SMEM);

    const int GE = NEDGE / 64;            // 5000
    const int GA = (NATOM + 63) / 64;     // 157
    const int GW = NEDGE * 32 / 256;      // 40000 (warp-per-edge kernels)

    prep_kernel<<<(NEDGE + 255) / 256, 256>>>(dist, dirs);
    m_init_kernel<<<NEDGE / 8, 256>>>(embed_w, embed_b);
    h_init_kernel<<<(NATOM * 32 + 255) / 256, 256>>>(Z, atom_emb);

    // ---- output block 0 (writes out) ----
    rad_mlp_kernel<<<GE, 256, RAD_SMEM>>>(ob_rad_w1, ob_rad_b1, ob_rad_w2, ob_rad_b2, p_radf, NEDGE);
    cudaMemsetAsync(p_x, 0, (size_t)NATOM * HID * sizeof(float));
    scatter_kernel<<<GW, 256>>>(ei);
    for (int j = 0; j < 3; j++)
        gemm128<false,true,false><<<GA, 256, GEMM_SMEM>>>(p_x, ob_dense_w + (size_t)j * 16384,
                                                          ob_dense_b + j * 128, p_x, NATOM);
    outproj_kernel<false><<<(NATOM * 32 + 255) / 256, 256>>>(ob_out_w, ob_out_b, out);

    for (int i = 0; i < 4; i++) {
        // radial feats + angles
        rad_mlp_kernel<<<GE, 256, RAD_SMEM>>>(ib_rad_w1 + (size_t)i * 2048, ib_rad_b1 + i * 128,
                                              ib_rad_w2 + (size_t)i * 16384, ib_rad_b2 + i * 128,
                                              p_radf, NEDGE);
        angle_kernel<<<(NEDGE + 255) / 256, 256>>>(ib_sph_w + i * 56, ib_sph_b + i * 8);
        // triplet interaction + aggregation
        cudaMemsetAsync(p_agg, 0, (size_t)NATOM * HID * sizeof(float));
        triplet_kernel<<<GW, 256>>>(trip, ei);
        // h update: h += silu([h,agg] @ W1 + b1) @ W2 + b2
        gemm128<false,false,false><<<GA, 256, GEMM_SMEM>>>(p_h,  ib_upd_w1 + (size_t)i * 32768,
                                                           ib_upd_b1 + i * 128, p_tmp, NATOM);
        gemm128<false,false,true ><<<GA, 256, GEMM_SMEM>>>(p_agg, ib_upd_w1 + (size_t)i * 32768 + 16384,
                                                           nullptr, p_tmp, NATOM);
        gemm128<true ,false,true ><<<GA, 256, GEMM_SMEM>>>(p_tmp, ib_upd_w2 + (size_t)i * 16384,
                                                           ib_upd_b2 + i * 128, p_h, NATOM);
        // m update: m += sum_j silu(mkf @ Wj + bj)
        for (int j = 0; j < 3; j++)
            gemm128<false,true,true><<<GE, 256, GEMM_SMEM>>>(p_mkf,
                ib_out_w + ((size_t)(i * 3 + j)) * 16384, ib_out_b + (i * 3 + j) * 128, p_m, NEDGE);
        // ---- output block i+1 (accumulates into out) ----
        int ob = i + 1;
        rad_mlp_kernel<<<GE, 256, RAD_SMEM>>>(ob_rad_w1 + (size_t)ob * 2048, ob_rad_b1 + ob * 128,
                                              ob_rad_w2 + (size_t)ob * 16384, ob_rad_b2 + ob * 128,
                                              p_radf, NEDGE);
        cudaMemsetAsync(p_x, 0, (size_t)NATOM * HID * sizeof(float));
        scatter_kernel<<<GW, 256>>>(ei);
        for (int j = 0; j < 3; j++)
            gemm128<false,true,false><<<GA, 256, GEMM_SMEM>>>(p_x,
                ob_dense_w + ((size_t)(ob * 3 + j)) * 16384, ob_dense_b + (ob * 3 + j) * 128, p_x, NATOM);
        outproj_kernel<true><<<(NATOM * 32 + 255) / 256, 256>>>(ob_out_w + ob * 128, ob_out_b + ob, out);
    }
}

// round 3
// speedup vs baseline: 1.2561x; 1.1321x over previous
#include <cuda_runtime.h>
#include <cuda_bf16.h>
#include <math_constants.h>

#define NEDGE 320000
#define NATOM 10000
#define HID   128
#define CUT   5.0f
#define NTAB  16384

typedef unsigned long long u64;

// ---------------- scratch (static device memory; no allocations) ----------------
__device__ __align__(16) float g_rbf[(size_t)NEDGE * 16];
__device__ __align__(16) float g_sbf[(size_t)NEDGE * 7];
__device__ __align__(16) float g_m   [(size_t)NEDGE * HID];
__device__ __align__(16) float g_radf[(size_t)NEDGE * HID];
__device__ __align__(16) float g_mkf [(size_t)NEDGE * HID];
__device__ __align__(16) float g_ang [NEDGE];
__device__ __align__(16) float g_h   [(size_t)NATOM * HID];
__device__ __align__(16) float g_agg [(size_t)NATOM * HID];
__device__ __align__(16) float g_x   [(size_t)NATOM * HID];
__device__ __align__(16) float g_tmp [(size_t)NATOM * HID];
__device__ __align__(16) float g_tabrbf[(size_t)NTAB * 16];
__device__ __align__(16) float g_tab [(size_t)NTAB * HID];

__device__ __forceinline__ float silu_f(float x) { return x / (1.0f + __expf(-x)); }

// ---------------- packed f32x2 helpers (Blackwell 2-wide fp32 FMA) ----------------
__device__ __forceinline__ u64 pack2(float a) {
    u64 r; asm("mov.b64 %0, {%1, %1};" : "=l"(r) : "f"(a)); return r;
}
__device__ __forceinline__ void fma2(u64& d, u64 a, u64 b) {
    asm("fma.rn.f32x2 %0, %1, %2, %3;" : "=l"(d) : "l"(a), "l"(b), "l"(d));
}
__device__ __forceinline__ float2 unpack2(u64 v) {
    float2 f; asm("mov.b64 {%0, %1}, %2;" : "=f"(f.x), "=f"(f.y) : "l"(v)); return f;
}

// ---------------- bessel rbf evaluation (shared by edge prep and table prep) ----------------
__device__ __forceinline__ void rbf_eval(float d, float* out16)
{
    float x = d * (1.0f / CUT);
    float x2 = x * x;
    float x6 = x2 * x2 * x2;
    float x7 = x6 * x;
    float x8 = x7 * x;
    float env = 1.0f - 28.0f * x6 + 48.0f * x7 - 21.0f * x8;
    if (!(d < CUT)) env = 0.0f;
    float s = sqrtf(2.0f / CUT) / d * env;
    float base = (float)CUDART_PI_F / CUT * d;
#pragma unroll
    for (int k = 0; k < 16; k++)
        out16[k] = s * sinf(base * (float)(k + 1));
}

// ---------------- prep: per-edge bessel rbf + spherical feats ----------------
__global__ void prep_kernel(const float* __restrict__ dist, const float* __restrict__ dirs)
{
    int e = blockIdx.x * blockDim.x + threadIdx.x;
    if (e >= NEDGE) return;
    float r16[16];
    rbf_eval(dist[e], r16);
#pragma unroll
    for (int k = 0; k < 16; k++) g_rbf[(size_t)e * 16 + k] = r16[k];

    float dx = dirs[e * 3 + 0], dy = dirs[e * 3 + 1], dz = dirs[e * 3 + 2];
    size_t o = (size_t)e * 7;
    g_sbf[o + 0] = 1.0f; g_sbf[o + 1] = dy; g_sbf[o + 2] = dz; g_sbf[o + 3] = dx;
    g_sbf[o + 4] = dx * dy; g_sbf[o + 5] = dy * dz; g_sbf[o + 6] = 3.0f * dz * dz - 1.0f;
}

// ---------------- table grid rbf ----------------
__global__ void tab_prep_kernel()
{
    int i = blockIdx.x * blockDim.x + threadIdx.x;
    if (i >= NTAB) return;
    float d = fmaxf((float)i * (CUT / (float)(NTAB - 1)), 1e-4f);
    float r16[16];
    rbf_eval(d, r16);
#pragma unroll
    for (int k = 0; k < 16; k++) g_tabrbf[(size_t)i * 16 + k] = r16[k];
}

// ---------------- interp: radf[e] = lerp(g_tab, d[e]) ----------------
__global__ void interp_kernel(const float* __restrict__ dist, float* __restrict__ Y)
{
    int gw = (blockIdx.x * blockDim.x + threadIdx.x) >> 5;
    int lane = threadIdx.x & 31;
    if (gw >= NEDGE) return;
    float t = dist[gw] * ((float)(NTAB - 1) / CUT);
    int i0 = min((int)t, NTAB - 2);
    float f = t - (float)i0;
    float4 lo = ((const float4*)(g_tab + (size_t)i0 * HID))[lane];
    float4 hi = ((const float4*)(g_tab + (size_t)(i0 + 1) * HID))[lane];
    float4 o;
    o.x = lo.x + (hi.x - lo.x) * f;
    o.y = lo.y + (hi.y - lo.y) * f;
    o.z = lo.z + (hi.z - lo.z) * f;
    o.w = lo.w + (hi.w - lo.w) * f;
    ((float4*)(Y + (size_t)gw * HID))[lane] = o;
}

// ---------------- m init: m = rbf @ embed_w[:,256:384] + embed_b[256:] ----------------
__global__ void m_init_kernel(const float* __restrict__ embed_w, const float* __restrict__ embed_b)
{
    __shared__ float Ws[16 * 128];
    __shared__ float bs[128];
    __shared__ float rs[8 * 16];
    int tid = threadIdx.x;
    for (int i = tid; i < 2048; i += 256)
        Ws[i] = embed_w[(i >> 7) * 384 + 256 + (i & 127)];
    if (tid < 128) bs[tid] = embed_b[256 + tid];
    int e0 = blockIdx.x * 8;
    if (tid < 128) rs[tid] = g_rbf[(size_t)e0 * 16 + tid];
    __syncthreads();
    int w = tid >> 5, lane = tid & 31;
    int e = e0 + w;
    float4 acc = *(const float4*)&bs[lane * 4];
#pragma unroll
    for (int k = 0; k < 16; k++) {
        float a = rs[w * 16 + k];
        float4 wv = *(const float4*)&Ws[k * 128 + lane * 4];
        acc.x += a * wv.x; acc.y += a * wv.y; acc.z += a * wv.z; acc.w += a * wv.w;
    }
    ((float4*)(g_m + (size_t)e * HID))[lane] = acc;
}

// ---------------- h init: embedding gather ----------------
__global__ void h_init_kernel(const int* __restrict__ Z, const float* __restrict__ emb)
{
    int idx = blockIdx.x * blockDim.x + threadIdx.x;
    int a = idx >> 5, lane = idx & 31;
    if (a >= NATOM) return;
    int z = Z[a] - 1;
    ((float4*)(g_h + (size_t)a * HID))[lane] =
        ((const float4*)(emb + (size_t)z * HID))[lane];
}

// ---------------- per-block angle: ang[e] = sigmoid(sbf[e] . wbar + bbar) ----------------
__global__ void angle_kernel(const float* __restrict__ sphW, const float* __restrict__ sphB)
{
    __shared__ float wbar[8];
    __shared__ float bbar;
    if (threadIdx.x < 7) {
        float s = 0.0f;
#pragma unroll
        for (int j = 0; j < 8; j++) s += sphW[threadIdx.x * 8 + j];
        wbar[threadIdx.x] = s * 0.125f;
    }
    if (threadIdx.x == 7) {
        float s = 0.0f;
#pragma unroll
        for (int j = 0; j < 8; j++) s += sphB[j];
        bbar = s * 0.125f;
    }
    __syncthreads();
    int e = blockIdx.x * blockDim.x + threadIdx.x;
    if (e >= NEDGE) return;
    float acc = bbar;
    size_t o = (size_t)e * 7;
#pragma unroll
    for (int k = 0; k < 7; k++) acc += g_sbf[o + k] * wbar[k];
    g_ang[e] = 1.0f / (1.0f + __expf(-acc));
}

// ---------------- GEMM core (f32x2, 4 rows x 8 cols per thread) ----------------
// tx in [0,16): cols tx*8..tx*8+7 ; ty in [0,16): rows ty*4..ty*4+3
__device__ __forceinline__ void gemm_core8(const float* __restrict__ Ws,
                                           const float* __restrict__ Xs,
                                           u64 acc[4][4], int tx, int ty)
{
#pragma unroll 2
    for (int k0 = 0; k0 < 128; k0 += 4) {
        float4 av[4];
#pragma unroll
        for (int r = 0; r < 4; r++)
            av[r] = *(const float4*)(Xs + (ty * 4 + r) * 128 + k0);
#pragma unroll
        for (int kk = 0; kk < 4; kk++) {
            ulonglong2 b01 = *(const ulonglong2*)(Ws + (k0 + kk) * 128 + tx * 8);
            ulonglong2 b23 = *(const ulonglong2*)(Ws + (k0 + kk) * 128 + tx * 8 + 4);
#pragma unroll
            for (int r = 0; r < 4; r++) {
                float aval = ((const float*)&av[r])[kk];
                u64 ap = pack2(aval);
                fma2(acc[r][0], ap, b01.x);
                fma2(acc[r][1], ap, b01.y);
                fma2(acc[r][2], ap, b23.x);
                fma2(acc[r][3], ap, b23.y);
            }
        }
    }
}

// ---------------- generic 128x128 GEMM: Y = epi(pre(X) @ W + b) ----------------
#define GEMM_SMEM ((16384 + 8192) * 4)
template<bool PRE_SILU, bool SILU_OUT, bool ACCUM>
__global__ void __launch_bounds__(256, 2) gemm128(const float* __restrict__ X,
                                                  const float* __restrict__ W,
                                                  const float* __restrict__ bias,
                                                  float* __restrict__ Y, int nrows)
{
    extern __shared__ float sm[];
    float* Ws = sm;            // 128*128
    float* Xs = sm + 16384;    // 64*128
    const int tid = threadIdx.x;
    const int row0 = blockIdx.x * 64;
    for (int i = tid; i < 4096; i += 256) ((float4*)Ws)[i] = ((const float4*)W)[i];
    const int rows = min(64, nrows - row0);
    for (int i = tid; i < 2048; i += 256) {
        int r = i >> 5, c = i & 31;
        float4 v = make_float4(0.f, 0.f, 0.f, 0.f);
        if (r < rows) v = ((const float4*)(X + (size_t)(row0 + r) * 128))[c];
        if (PRE_SILU) { v.x = silu_f(v.x); v.y = silu_f(v.y); v.z = silu_f(v.z); v.w = silu_f(v.w); }
        ((float4*)Xs)[i] = v;
    }
    __syncthreads();
    const int tx = tid & 15, ty = tid >> 4;
    u64 acc[4][4];
#pragma unroll
    for (int r = 0; r < 4; r++)
#pragma unroll
        for (int c = 0; c < 4; c++) acc[r][c] = 0ull;
    gemm_core8(Ws, Xs, acc, tx, ty);

    float4 blo = make_float4(0.f, 0.f, 0.f, 0.f), bhi = blo;
    if (bias) {
        blo = *(const float4*)(bias + tx * 8);
        bhi = *(const float4*)(bias + tx * 8 + 4);
    }
#pragma unroll
    for (int r = 0; r < 4; r++) {
        int row = ty * 4 + r;
        if (row >= rows) break;
        float2 p0 = unpack2(acc[r][0]);
        float2 p1 = unpack2(acc[r][1]);
        float2 p2 = unpack2(acc[r][2]);
        float2 p3 = unpack2(acc[r][3]);
        float4 o0 = make_float4(p0.x + blo.x, p0.y + blo.y, p1.x + blo.z, p1.y + blo.w);
        float4 o1 = make_float4(p2.x + bhi.x, p2.y + bhi.y, p3.x + bhi.z, p3.y + bhi.w);
        if (SILU_OUT) {
            o0.x = silu_f(o0.x); o0.y = silu_f(o0.y); o0.z = silu_f(o0.z); o0.w = silu_f(o0.w);
            o1.x = silu_f(o1.x); o1.y = silu_f(o1.y); o1.z = silu_f(o1.z); o1.w = silu_f(o1.w);
        }
        float* yp = Y + (size_t)(row0 + row) * 128 + tx * 8;
        if (ACCUM) {
            float4 u0 = *(float4*)yp;
            float4 u1 = *(float4*)(yp + 4);
            o0.x += u0.x; o0.y += u0.y; o0.z += u0.z; o0.w += u0.w;
            o1.x += u1.x; o1.y += u1.y; o1.z += u1.z; o1.w += u1.w;
        }
        *(float4*)yp = o0;
        *(float4*)(yp + 4) = o1;
    }
}

// ---------------- fused radial MLP: Y = silu(rbf @ W1 + b1) @ W2 + b2 ----------------
#define RAD_SMEM ((16384 + 8192 + 2048 + 128 + 1024) * 4)
__global__ void __launch_bounds__(256, 2) rad_mlp_kernel(const float* __restrict__ rbf_in,
                                                         const float* __restrict__ rW1,
                                                         const float* __restrict__ rb1,
                                                         const float* __restrict__ rW2,
                                                         const float* __restrict__ rb2,
                                                         float* __restrict__ Y, int nrows)
{
    extern __shared__ float sm[];
    float* W2s = sm;                     // 16384
    float* Hs  = sm + 16384;             // 8192
    float* W1s = sm + 16384 + 8192;      // 2048
    float* b1s = W1s + 2048;             // 128
    float* Rs  = b1s + 128;              // 1024
    const int tid = threadIdx.x;
    const int row0 = blockIdx.x * 64;
    for (int i = tid; i < 4096; i += 256) ((float4*)W2s)[i] = ((const float4*)rW2)[i];
    for (int i = tid; i < 512;  i += 256) ((float4*)W1s)[i] = ((const float4*)rW1)[i];
    if (tid < 32) ((float4*)b1s)[tid] = ((const float4*)rb1)[tid];
    const int rows = min(64, nrows - row0);
    if (tid < 256) {
        int i = tid;                     // 64*16/4 = 256 float4
        int r = i >> 2;
        float4 v = make_float4(0.f, 0.f, 0.f, 0.f);
        if (r < rows) v = ((const float4*)(rbf_in + (size_t)(row0 + r) * 16))[i & 3];
        ((float4*)Rs)[i] = v;
    }
    __syncthreads();
    {
        const int tx5 = tid & 31, ty5 = tid >> 5;
        float4 b1v = *(const float4*)&b1s[tx5 * 4];
#pragma unroll
        for (int i = 0; i < 8; i++) {
            int r = ty5 * 8 + i;
            float4 a4 = b1v;
#pragma unroll
            for (int k = 0; k < 16; k++) {
                float a = Rs[r * 16 + k];
                float4 w = *(const float4*)&W1s[k * 128 + tx5 * 4];
                a4.x += a * w.x; a4.y += a * w.y; a4.z += a * w.z; a4.w += a * w.w;
            }
            a4.x = silu_f(a4.x); a4.y = silu_f(a4.y); a4.z = silu_f(a4.z); a4.w = silu_f(a4.w);
            *(float4*)&Hs[r * 128 + tx5 * 4] = a4;
        }
    }
    __syncthreads();
    const int tx = tid & 15, ty = tid >> 4;
    u64 acc[4][4];
#pragma unroll
    for (int r = 0; r < 4; r++)
#pragma unroll
        for (int c = 0; c < 4; c++) acc[r][c] = 0ull;
    gemm_core8(W2s, Hs, acc, tx, ty);
    float4 blo = *(const float4*)(rb2 + tx * 8);
    float4 bhi = *(const float4*)(rb2 + tx * 8 + 4);
#pragma unroll
    for (int r = 0; r < 4; r++) {
        int row = ty * 4 + r;
        if (row >= rows) break;
        float2 p0 = unpack2(acc[r][0]);
        float2 p1 = unpack2(acc[r][1]);
        float2 p2 = unpack2(acc[r][2]);
        float2 p3 = unpack2(acc[r][3]);
        float* yp = Y + (size_t)(row0 + row) * 128 + tx * 8;
        *(float4*)yp       = make_float4(p0.x + blo.x, p0.y + blo.y, p1.x + blo.z, p1.y + blo.w);
        *(float4*)(yp + 4) = make_float4(p2.x + bhi.x, p2.y + bhi.y, p3.x + bhi.z, p3.y + bhi.w);
    }
}

// ---------------- triplet: mkf[t] = m[kj]*radf[kj]*ang[ji]; agg[dst[t]] += mkf[t] ----------------
__global__ void triplet_kernel(const int* __restrict__ trip, const int* __restrict__ ei)
{
    int gw = (blockIdx.x * blockDim.x + threadIdx.x) >> 5;
    int lane = threadIdx.x & 31;
    if (gw >= NEDGE) return;
    int ji = trip[gw * 3 + 0];
    int kj = trip[gw * 3 + 1];
    float aw = g_ang[ji];
    float4 mv = ((const float4*)(g_m    + (size_t)kj * HID))[lane];
    float4 rv = ((const float4*)(g_radf + (size_t)kj * HID))[lane];
    float4 o = make_float4(mv.x * rv.x * aw, mv.y * rv.y * aw, mv.z * rv.z * aw, mv.w * rv.w * aw);
    ((float4*)(g_mkf + (size_t)gw * HID))[lane] = o;
    int dd = ei[NEDGE + gw];
    float* p = g_agg + (size_t)dd * HID + lane * 4;
    atomicAdd(p + 0, o.x); atomicAdd(p + 1, o.y); atomicAdd(p + 2, o.z); atomicAdd(p + 3, o.w);
}

// ---------------- edge scatter (output block): x[dst[e]] += h[src[e]] * radf[e] ----------------
__global__ void scatter_kernel(const int* __restrict__ ei)
{
    int gw = (blockIdx.x * blockDim.x + threadIdx.x) >> 5;
    int lane = threadIdx.x & 31;
    if (gw >= NEDGE) return;
    int s  = ei[gw];
    int dd = ei[NEDGE + gw];
    float4 hv = ((const float4*)(g_h    + (size_t)s  * HID))[lane];
    float4 wv = ((const float4*)(g_radf + (size_t)gw * HID))[lane];
    float* p = g_x + (size_t)dd * HID + lane * 4;
    atomicAdd(p + 0, hv.x * wv.x); atomicAdd(p + 1, hv.y * wv.y);
    atomicAdd(p + 2, hv.z * wv.z); atomicAdd(p + 3, hv.w * wv.w);
}

// ---------------- output projection: out[a] (+)= x[a] . w + b ----------------
template<bool ACCUM>
__global__ void outproj_kernel(const float* __restrict__ w, const float* __restrict__ b,
                               float* __restrict__ out)
{
    int idx = blockIdx.x * blockDim.x + threadIdx.x;
    int a = idx >> 5, lane = idx & 31;
    if (a >= NATOM) return;
    float4 xv = ((const float4*)(g_x + (size_t)a * HID))[lane];
    float4 wv = ((const float4*)w)[lane];
    float s = xv.x * wv.x + xv.y * wv.y + xv.z * wv.z + xv.w * wv.w;
#pragma unroll
    for (int off = 16; off > 0; off >>= 1) s += __shfl_xor_sync(0xFFFFFFFFu, s, off);
    if (lane == 0) {
        float v = s + b[0];
        if (ACCUM) out[a] += v; else out[a] = v;
    }
}

// ---------------- host launcher ----------------
extern "C" void kernel_launch(void* const* d_in, const int* in_sizes, int n_in,
                              void* d_out, int out_size)
{
    const int*   Z        = (const int*)d_in[0];
    const int*   ei       = (const int*)d_in[1];
    const float* dist     = (const float*)d_in[2];
    const float* dirs     = (const float*)d_in[3];
    const int*   trip     = (const int*)d_in[4];
    const float* atom_emb = (const float*)d_in[5];
    const float* embed_w  = (const float*)d_in[6];
    const float* embed_b  = (const float*)d_in[7];
    const float* ib_rad_w1 = (const float*)d_in[8];
    const float* ib_rad_b1 = (const float*)d_in[9];
    const float* ib_rad_w2 = (const float*)d_in[10];
    const float* ib_rad_b2 = (const float*)d_in[11];
    const float* ib_sph_w  = (const float*)d_in[12];
    const float* ib_sph_b  = (const float*)d_in[13];
    const float* ib_upd_w1 = (const float*)d_in[14];
    const float* ib_upd_b1 = (const float*)d_in[15];
    const float* ib_upd_w2 = (const float*)d_in[16];
    const float* ib_upd_b2 = (const float*)d_in[17];
    const float* ib_out_w  = (const float*)d_in[18];
    const float* ib_out_b  = (const float*)d_in[19];
    const float* ob_rad_w1 = (const float*)d_in[20];
    const float* ob_rad_b1 = (const float*)d_in[21];
    const float* ob_rad_w2 = (const float*)d_in[22];
    const float* ob_rad_b2 = (const float*)d_in[23];
    const float* ob_dense_w = (const float*)d_in[24];
    const float* ob_dense_b = (const float*)d_in[25];
    const float* ob_out_w  = (const float*)d_in[26];
    const float* ob_out_b  = (const float*)d_in[27];
    float* out = (float*)d_out;

    float *p_radf, *p_m, *p_mkf, *p_h, *p_agg, *p_x, *p_tmp, *p_tabrbf, *p_tab;
    cudaGetSymbolAddress((void**)&p_radf, g_radf);
    cudaGetSymbolAddress((void**)&p_m,    g_m);
    cudaGetSymbolAddress((void**)&p_mkf,  g_mkf);
    cudaGetSymbolAddress((void**)&p_h,    g_h);
    cudaGetSymbolAddress((void**)&p_agg,  g_agg);
    cudaGetSymbolAddress((void**)&p_x,    g_x);
    cudaGetSymbolAddress((void**)&p_tmp,  g_tmp);
    cudaGetSymbolAddress((void**)&p_tabrbf, g_tabrbf);
    cudaGetSymbolAddress((void**)&p_tab,  g_tab);

    cudaFuncSetAttribute(gemm128<false,false,false>, cudaFuncAttributeMaxDynamicSharedMemorySize, GEMM_SMEM);
    cudaFuncSetAttribute(gemm128<false,false,true >, cudaFuncAttributeMaxDynamicSharedMemorySize, GEMM_SMEM);
    cudaFuncSetAttribute(gemm128<true ,false,true >, cudaFuncAttributeMaxDynamicSharedMemorySize, GEMM_SMEM);
    cudaFuncSetAttribute(gemm128<false,true ,true >, cudaFuncAttributeMaxDynamicSharedMemorySize, GEMM_SMEM);
    cudaFuncSetAttribute(gemm128<false,true ,false>, cudaFuncAttributeMaxDynamicSharedMemorySize, GEMM_SMEM);
    cudaFuncSetAttribute(rad_mlp_kernel, cudaFuncAttributeMaxDynamicSharedMemorySize, RAD_SMEM);

    const int GE = NEDGE / 64;            // 5000 (edge gemm blocks)
    const int GT = NTAB / 64;             // 256  (table gemm blocks)
    const int GA = (NATOM + 63) / 64;     // 157
    const int GW = NEDGE * 32 / 256;      // 40000 (warp-per-edge kernels)

    prep_kernel<<<(NEDGE + 255) / 256, 256>>>(dist, dirs);
    tab_prep_kernel<<<NTAB / 256, 256>>>();
    m_init_kernel<<<NEDGE / 8, 256>>>(embed_w, embed_b);
    h_init_kernel<<<(NATOM * 32 + 255) / 256, 256>>>(Z, atom_emb);

    // ---- output block 0 (writes out) ----
    rad_mlp_kernel<<<GT, 256, RAD_SMEM>>>(p_tabrbf, ob_rad_w1, ob_rad_b1, ob_rad_w2, ob_rad_b2, p_tab, NTAB);
    interp_kernel<<<GW, 256>>>(dist, p_radf);
    cudaMemsetAsync(p_x, 0, (size_t)NATOM * HID * sizeof(float));
    scatter_kernel<<<GW, 256>>>(ei);
    for (int j = 0; j < 3; j++)
        gemm128<false,true,false><<<GA, 256, GEMM_SMEM>>>(p_x, ob_dense_w + (size_t)j * 16384,
                                                          ob_dense_b + j * 128, p_x, NATOM);
    outproj_kernel<false><<<(NATOM * 32 + 255) / 256, 256>>>(ob_out_w, ob_out_b, out);

    for (int i = 0; i < 4; i++) {
        // radial feats (tabulated) + angles
        rad_mlp_kernel<<<GT, 256, RAD_SMEM>>>(p_tabrbf,
                                              ib_rad_w1 + (size_t)i * 2048, ib_rad_b1 + i * 128,
                                              ib_rad_w2 + (size_t)i * 16384, ib_rad_b2 + i * 128,
                                              p_tab, NTAB);
        interp_kernel<<<GW, 256>>>(dist, p_radf);
        angle_kernel<<<(NEDGE + 255) / 256, 256>>>(ib_sph_w + i * 56, ib_sph_b + i * 8);
        // triplet interaction + aggregation
        cudaMemsetAsync(p_agg, 0, (size_t)NATOM * HID * sizeof(float));
        triplet_kernel<<<GW, 256>>>(trip, ei);
        // h update: h += silu([h,agg] @ W1 + b1) @ W2 + b2
        gemm128<false,false,false><<<GA, 256, GEMM_SMEM>>>(p_h,  ib_upd_w1 + (size_t)i * 32768,
                                                           ib_upd_b1 + i * 128, p_tmp, NATOM);
        gemm128<false,false,true ><<<GA, 256, GEMM_SMEM>>>(p_agg, ib_upd_w1 + (size_t)i * 32768 + 16384,
                                                           nullptr, p_tmp, NATOM);
        gemm128<true ,false,true ><<<GA, 256, GEMM_SMEM>>>(p_tmp, ib_upd_w2 + (size_t)i * 16384,
                                                           ib_upd_b2 + i * 128, p_h, NATOM);
        // m update: m += sum_j silu(mkf @ Wj + bj)
        for (int j = 0; j < 3; j++)
            gemm128<false,true,true><<<GE, 256, GEMM_SMEM>>>(p_mkf,
                ib_out_w + ((size_t)(i * 3 + j)) * 16384, ib_out_b + (i * 3 + j) * 128, p_m, NEDGE);
        // ---- output block i+1 (accumulates into out) ----
        int ob = i + 1;
        rad_mlp_kernel<<<GT, 256, RAD_SMEM>>>(p_tabrbf,
                                              ob_rad_w1 + (size_t)ob * 2048, ob_rad_b1 + ob * 128,
                                              ob_rad_w2 + (size_t)ob * 16384, ob_rad_b2 + ob * 128,
                                              p_tab, NTAB);
        interp_kernel<<<GW, 256>>>(dist, p_radf);
        cudaMemsetAsync(p_x, 0, (size_t)NATOM * HID * sizeof(float));
        scatter_kernel<<<GW, 256>>>(ei);
        for (int j = 0; j < 3; j++)
            gemm128<false,true,false><<<GA, 256, GEMM_SMEM>>>(p_x,
                ob_dense_w + ((size_t)(ob * 3 + j)) * 16384, ob_dense_b + (ob * 3 + j) * 128, p_x, NATOM);
        outproj_kernel<true><<<(NATOM * 32 + 255) / 256, 256>>>(ob_out_w + ob * 128, ob_out_b + ob, out);
    }
}

// round 4
// speedup vs baseline: 1.4431x; 1.1488x over previous
#include <cuda_runtime.h>
#include <cuda_bf16.h>
#include <math_constants.h>

#define NEDGE 320000
#define NATOM 10000
#define HID   128
#define CUT   5.0f
#define NTAB  16384

typedef unsigned long long u64;
typedef unsigned int u32;

// ---------------- scratch (static device memory; no allocations) ----------------
__device__ __align__(16) float g_rbf[(size_t)NEDGE * 16];
__device__ __align__(16) float g_sbf[(size_t)NEDGE * 7];
__device__ __align__(16) float g_m   [(size_t)NEDGE * HID];
__device__ __align__(16) __nv_bfloat16 g_mkf_hi[(size_t)NEDGE * HID];
__device__ __align__(16) __nv_bfloat16 g_mkf_lo[(size_t)NEDGE * HID];
__device__ __align__(16) float g_ang [NEDGE];
__device__ __align__(16) float g_h   [(size_t)NATOM * HID];
__device__ __align__(16) float g_agg [(size_t)NATOM * HID];
__device__ __align__(16) float g_x   [(size_t)NATOM * HID];
__device__ __align__(16) float g_tmp [(size_t)NATOM * HID];
__device__ __align__(16) float g_tabrbf[(size_t)NTAB * 16];
__device__ __align__(16) float g_tab [(size_t)NTAB * HID];

__device__ __forceinline__ float silu_f(float x) { return x / (1.0f + __expf(-x)); }

// ---------------- packed f32x2 helpers (Blackwell 2-wide fp32 FMA) ----------------
__device__ __forceinline__ u64 pack2(float a) {
    u64 r; asm("mov.b64 %0, {%1, %1};" : "=l"(r) : "f"(a)); return r;
}
__device__ __forceinline__ void fma2(u64& d, u64 a, u64 b) {
    asm("fma.rn.f32x2 %0, %1, %2, %3;" : "=l"(d) : "l"(a), "l"(b), "l"(d));
}
__device__ __forceinline__ float2 unpack2(u64 v) {
    float2 f; asm("mov.b64 {%0, %1}, %2;" : "=f"(f.x), "=f"(f.y) : "l"(v)); return f;
}

// ---------------- bessel rbf ----------------
__device__ __forceinline__ void rbf_eval(float d, float* out16)
{
    float x = d * (1.0f / CUT);
    float x2 = x * x;
    float x6 = x2 * x2 * x2;
    float x7 = x6 * x;
    float x8 = x7 * x;
    float env = 1.0f - 28.0f * x6 + 48.0f * x7 - 21.0f * x8;
    if (!(d < CUT)) env = 0.0f;
    float s = sqrtf(2.0f / CUT) / d * env;
    float base = (float)CUDART_PI_F / CUT * d;
#pragma unroll
    for (int k = 0; k < 16; k++)
        out16[k] = s * sinf(base * (float)(k + 1));
}

__global__ void prep_kernel(const float* __restrict__ dist, const float* __restrict__ dirs)
{
    int e = blockIdx.x * blockDim.x + threadIdx.x;
    if (e >= NEDGE) return;
    float r16[16];
    rbf_eval(dist[e], r16);
#pragma unroll
    for (int k = 0; k < 16; k++) g_rbf[(size_t)e * 16 + k] = r16[k];

    float dx = dirs[e * 3 + 0], dy = dirs[e * 3 + 1], dz = dirs[e * 3 + 2];
    size_t o = (size_t)e * 7;
    g_sbf[o + 0] = 1.0f; g_sbf[o + 1] = dy; g_sbf[o + 2] = dz; g_sbf[o + 3] = dx;
    g_sbf[o + 4] = dx * dy; g_sbf[o + 5] = dy * dz; g_sbf[o + 6] = 3.0f * dz * dz - 1.0f;
}

__global__ void tab_prep_kernel()
{
    int i = blockIdx.x * blockDim.x + threadIdx.x;
    if (i >= NTAB) return;
    float d = fmaxf((float)i * (CUT / (float)(NTAB - 1)), 1e-4f);
    float r16[16];
    rbf_eval(d, r16);
#pragma unroll
    for (int k = 0; k < 16; k++) g_tabrbf[(size_t)i * 16 + k] = r16[k];
}

// lerp a float4 slice of the radial table at distance d (lane = 16B slice index)
__device__ __forceinline__ float4 tab_lerp(float d, int lane)
{
    float t = d * ((float)(NTAB - 1) / CUT);
    int i0 = min((int)t, NTAB - 2);
    float f = t - (float)i0;
    float4 lo = ((const float4*)(g_tab + (size_t)i0 * HID))[lane];
    float4 hi = ((const float4*)(g_tab + (size_t)(i0 + 1) * HID))[lane];
    float4 o;
    o.x = lo.x + (hi.x - lo.x) * f;
    o.y = lo.y + (hi.y - lo.y) * f;
    o.z = lo.z + (hi.z - lo.z) * f;
    o.w = lo.w + (hi.w - lo.w) * f;
    return o;
}

// ---------------- m init ----------------
__global__ void m_init_kernel(const float* __restrict__ embed_w, const float* __restrict__ embed_b)
{
    __shared__ float Ws[16 * 128];
    __shared__ float bs[128];
    __shared__ float rs[8 * 16];
    int tid = threadIdx.x;
    for (int i = tid; i < 2048; i += 256)
        Ws[i] = embed_w[(i >> 7) * 384 + 256 + (i & 127)];
    if (tid < 128) bs[tid] = embed_b[256 + tid];
    int e0 = blockIdx.x * 8;
    if (tid < 128) rs[tid] = g_rbf[(size_t)e0 * 16 + tid];
    __syncthreads();
    int w = tid >> 5, lane = tid & 31;
    int e = e0 + w;
    float4 acc = *(const float4*)&bs[lane * 4];
#pragma unroll
    for (int k = 0; k < 16; k++) {
        float a = rs[w * 16 + k];
        float4 wv = *(const float4*)&Ws[k * 128 + lane * 4];
        acc.x += a * wv.x; acc.y += a * wv.y; acc.z += a * wv.z; acc.w += a * wv.w;
    }
    ((float4*)(g_m + (size_t)e * HID))[lane] = acc;
}

__global__ void h_init_kernel(const int* __restrict__ Z, const float* __restrict__ emb)
{
    int idx = blockIdx.x * blockDim.x + threadIdx.x;
    int a = idx >> 5, lane = idx & 31;
    if (a >= NATOM) return;
    int z = Z[a] - 1;
    ((float4*)(g_h + (size_t)a * HID))[lane] =
        ((const float4*)(emb + (size_t)z * HID))[lane];
}

__global__ void angle_kernel(const float* __restrict__ sphW, const float* __restrict__ sphB)
{
    __shared__ float wbar[8];
    __shared__ float bbar;
    if (threadIdx.x < 7) {
        float s = 0.0f;
#pragma unroll
        for (int j = 0; j < 8; j++) s += sphW[threadIdx.x * 8 + j];
        wbar[threadIdx.x] = s * 0.125f;
    }
    if (threadIdx.x == 7) {
        float s = 0.0f;
#pragma unroll
        for (int j = 0; j < 8; j++) s += sphB[j];
        bbar = s * 0.125f;
    }
    __syncthreads();
    int e = blockIdx.x * blockDim.x + threadIdx.x;
    if (e >= NEDGE) return;
    float acc = bbar;
    size_t o = (size_t)e * 7;
#pragma unroll
    for (int k = 0; k < 7; k++) acc += g_sbf[o + k] * wbar[k];
    g_ang[e] = 1.0f / (1.0f + __expf(-acc));
}

// ---------------- SIMT GEMM core (f32x2, 4 rows x 8 cols per thread) ----------------
__device__ __forceinline__ void gemm_core8(const float* __restrict__ Ws,
                                           const float* __restrict__ Xs,
                                           u64 acc[4][4], int tx, int ty)
{
#pragma unroll 2
    for (int k0 = 0; k0 < 128; k0 += 4) {
        float4 av[4];
#pragma unroll
        for (int r = 0; r < 4; r++)
            av[r] = *(const float4*)(Xs + (ty * 4 + r) * 128 + k0);
#pragma unroll
        for (int kk = 0; kk < 4; kk++) {
            ulonglong2 b01 = *(const ulonglong2*)(Ws + (k0 + kk) * 128 + tx * 8);
            ulonglong2 b23 = *(const ulonglong2*)(Ws + (k0 + kk) * 128 + tx * 8 + 4);
#pragma unroll
            for (int r = 0; r < 4; r++) {
                float aval = ((const float*)&av[r])[kk];
                u64 ap = pack2(aval);
                fma2(acc[r][0], ap, b01.x);
                fma2(acc[r][1], ap, b01.y);
                fma2(acc[r][2], ap, b23.x);
                fma2(acc[r][3], ap, b23.y);
            }
        }
    }
}

// ---------------- generic SIMT 128x128 GEMM (atom-level work) ----------------
#define GEMM_SMEM ((16384 + 8192) * 4)
template<bool PRE_SILU, bool SILU_OUT, bool ACCUM>
__global__ void __launch_bounds__(256, 2) gemm128(const float* __restrict__ X,
                                                  const float* __restrict__ W,
                                                  const float* __restrict__ bias,
                                                  float* __restrict__ Y, int nrows)
{
    extern __shared__ float sm[];
    float* Ws = sm;            // 128*128
    float* Xs = sm + 16384;    // 64*128
    const int tid = threadIdx.x;
    const int row0 = blockIdx.x * 64;
    for (int i = tid; i < 4096; i += 256) ((float4*)Ws)[i] = ((const float4*)W)[i];
    const int rows = min(64, nrows - row0);
    for (int i = tid; i < 2048; i += 256) {
        int r = i >> 5, c = i & 31;
        float4 v = make_float4(0.f, 0.f, 0.f, 0.f);
        if (r < rows) v = ((const float4*)(X + (size_t)(row0 + r) * 128))[c];
        if (PRE_SILU) { v.x = silu_f(v.x); v.y = silu_f(v.y); v.z = silu_f(v.z); v.w = silu_f(v.w); }
        ((float4*)Xs)[i] = v;
    }
    __syncthreads();
    const int tx = tid & 15, ty = tid >> 4;
    u64 acc[4][4];
#pragma unroll
    for (int r = 0; r < 4; r++)
#pragma unroll
        for (int c = 0; c < 4; c++) acc[r][c] = 0ull;
    gemm_core8(Ws, Xs, acc, tx, ty);

    float4 blo = make_float4(0.f, 0.f, 0.f, 0.f), bhi = blo;
    if (bias) {
        blo = *(const float4*)(bias + tx * 8);
        bhi = *(const float4*)(bias + tx * 8 + 4);
    }
#pragma unroll
    for (int r = 0; r < 4; r++) {
        int row = ty * 4 + r;
        if (row >= rows) break;
        float2 p0 = unpack2(acc[r][0]);
        float2 p1 = unpack2(acc[r][1]);
        float2 p2 = unpack2(acc[r][2]);
        float2 p3 = unpack2(acc[r][3]);
        float4 o0 = make_float4(p0.x + blo.x, p0.y + blo.y, p1.x + blo.z, p1.y + blo.w);
        float4 o1 = make_float4(p2.x + bhi.x, p2.y + bhi.y, p3.x + bhi.z, p3.y + bhi.w);
        if (SILU_OUT) {
            o0.x = silu_f(o0.x); o0.y = silu_f(o0.y); o0.z = silu_f(o0.z); o0.w = silu_f(o0.w);
            o1.x = silu_f(o1.x); o1.y = silu_f(o1.y); o1.z = silu_f(o1.z); o1.w = silu_f(o1.w);
        }
        float* yp = Y + (size_t)(row0 + row) * 128 + tx * 8;
        if (ACCUM) {
            float4 u0 = *(float4*)yp;
            float4 u1 = *(float4*)(yp + 4);
            o0.x += u0.x; o0.y += u0.y; o0.z += u0.z; o0.w += u0.w;
            o1.x += u1.x; o1.y += u1.y; o1.z += u1.z; o1.w += u1.w;
        }
        *(float4*)yp = o0;
        *(float4*)(yp + 4) = o1;
    }
}

// ---------------- fused radial MLP on the distance table ----------------
#define RAD_SMEM ((16384 + 8192 + 2048 + 128 + 1024) * 4)
__global__ void __launch_bounds__(256, 2) rad_mlp_kernel(const float* __restrict__ rbf_in,
                                                         const float* __restrict__ rW1,
                                                         const float* __restrict__ rb1,
                                                         const float* __restrict__ rW2,
                                                         const float* __restrict__ rb2,
                                                         float* __restrict__ Y, int nrows)
{
    extern __shared__ float sm[];
    float* W2s = sm;
    float* Hs  = sm + 16384;
    float* W1s = sm + 16384 + 8192;
    float* b1s = W1s + 2048;
    float* Rs  = b1s + 128;
    const int tid = threadIdx.x;
    const int row0 = blockIdx.x * 64;
    for (int i = tid; i < 4096; i += 256) ((float4*)W2s)[i] = ((const float4*)rW2)[i];
    for (int i = tid; i < 512;  i += 256) ((float4*)W1s)[i] = ((const float4*)rW1)[i];
    if (tid < 32) ((float4*)b1s)[tid] = ((const float4*)rb1)[tid];
    const int rows = min(64, nrows - row0);
    if (tid < 256) {
        int i = tid;
        int r = i >> 2;
        float4 v = make_float4(0.f, 0.f, 0.f, 0.f);
        if (r < rows) v = ((const float4*)(rbf_in + (size_t)(row0 + r) * 16))[i & 3];
        ((float4*)Rs)[i] = v;
    }
    __syncthreads();
    {
        const int tx5 = tid & 31, ty5 = tid >> 5;
        float4 b1v = *(const float4*)&b1s[tx5 * 4];
#pragma unroll
        for (int i = 0; i < 8; i++) {
            int r = ty5 * 8 + i;
            float4 a4 = b1v;
#pragma unroll
            for (int k = 0; k < 16; k++) {
                float a = Rs[r * 16 + k];
                float4 w = *(const float4*)&W1s[k * 128 + tx5 * 4];
                a4.x += a * w.x; a4.y += a * w.y; a4.z += a * w.z; a4.w += a * w.w;
            }
            a4.x = silu_f(a4.x); a4.y = silu_f(a4.y); a4.z = silu_f(a4.z); a4.w = silu_f(a4.w);
            *(float4*)&Hs[r * 128 + tx5 * 4] = a4;
        }
    }
    __syncthreads();
    const int tx = tid & 15, ty = tid >> 4;
    u64 acc[4][4];
#pragma unroll
    for (int r = 0; r < 4; r++)
#pragma unroll
        for (int c = 0; c < 4; c++) acc[r][c] = 0ull;
    gemm_core8(W2s, Hs, acc, tx, ty);
    float4 blo = *(const float4*)(rb2 + tx * 8);
    float4 bhi = *(const float4*)(rb2 + tx * 8 + 4);
#pragma unroll
    for (int r = 0; r < 4; r++) {
        int row = ty * 4 + r;
        if (row >= rows) break;
        float2 p0 = unpack2(acc[r][0]);
        float2 p1 = unpack2(acc[r][1]);
        float2 p2 = unpack2(acc[r][2]);
        float2 p3 = unpack2(acc[r][3]);
        float* yp = Y + (size_t)(row0 + row) * 128 + tx * 8;
        *(float4*)yp       = make_float4(p0.x + blo.x, p0.y + blo.y, p1.x + blo.z, p1.y + blo.w);
        *(float4*)(yp + 4) = make_float4(p2.x + bhi.x, p2.y + bhi.y, p3.x + bhi.z, p3.y + bhi.w);
    }
}

// ---------------- bf16-split tensor GEMM: Y += silu(A @ W + b), A = hi+lo bf16 ----------------
#define MMA_SMEM (4 * 128 * 136 * 2)
__device__ __forceinline__ void mma_bf16(float* c, const u32* a, const u32* b)
{
    asm volatile("mma.sync.aligned.m16n8k16.row.col.f32.bf16.bf16.f32 "
                 "{%0,%1,%2,%3}, {%4,%5,%6,%7}, {%8,%9}, {%0,%1,%2,%3};"
                 : "+f"(c[0]), "+f"(c[1]), "+f"(c[2]), "+f"(c[3])
                 : "r"(a[0]), "r"(a[1]), "r"(a[2]), "r"(a[3]), "r"(b[0]), "r"(b[1]));
}

__global__ void __launch_bounds__(256, 1) mma_gemm_kernel(
    const __nv_bfloat16* __restrict__ Ahi, const __nv_bfloat16* __restrict__ Alo,
    const float* __restrict__ W, const float* __restrict__ bias,
    float* __restrict__ Y)
{
    extern __shared__ __nv_bfloat16 smb[];
    __nv_bfloat16* sAh = smb;                 // [128][136]
    __nv_bfloat16* sAl = smb + 128 * 136;
    __nv_bfloat16* sBh = smb + 2 * 128 * 136; // [n=128][k=136]
    __nv_bfloat16* sBl = smb + 3 * 128 * 136;
    const int tid = threadIdx.x;
    const int row0 = blockIdx.x * 128;

    // A tiles (dense [row][128] bf16 -> padded stride 136)
    {
        const uint4* Ah4 = (const uint4*)(Ahi + (size_t)row0 * 128);
        const uint4* Al4 = (const uint4*)(Alo + (size_t)row0 * 128);
        for (int i = tid; i < 2048; i += 256) {
            int r = i >> 4, c = i & 15;
            *(uint4*)&sAh[r * 136 + c * 8] = Ah4[r * 16 + c];
            *(uint4*)&sAl[r * 136 + c * 8] = Al4[r * 16 + c];
        }
    }
    // W split + transpose: W[k][n] fp32 -> sB[n][k] bf16 hi/lo
    for (int i = tid; i < 16384; i += 256) {
        int k = i >> 7, n = i & 127;
        float w = W[i];
        __nv_bfloat16 h = __float2bfloat16(w);
        float r = w - __bfloat162float(h);
        sBh[n * 136 + k] = h;
        sBl[n * 136 + k] = __float2bfloat16(r);
    }
    __syncthreads();

    const int lane = tid & 31, wid = tid >> 5;
    const int wm = wid >> 1, wn = wid & 1;      // 4x2 warp grid -> 32x64 warp tiles
    const int gid = lane >> 2, tg = lane & 3;

    float acc[2][8][4];
#pragma unroll
    for (int a = 0; a < 2; a++)
#pragma unroll
        for (int b = 0; b < 8; b++)
#pragma unroll
            for (int c = 0; c < 4; c++) acc[a][b][c] = 0.0f;

#pragma unroll
    for (int ks = 0; ks < 8; ks++) {
        const int kb = ks * 16;
        u32 ah[2][4], al[2][4];
#pragma unroll
        for (int fm = 0; fm < 2; fm++) {
            int r = wm * 32 + fm * 16 + gid;
            ah[fm][0] = *(const u32*)&sAh[(r)     * 136 + kb + tg * 2];
            ah[fm][1] = *(const u32*)&sAh[(r + 8) * 136 + kb + tg * 2];
            ah[fm][2] = *(const u32*)&sAh[(r)     * 136 + kb + 8 + tg * 2];
            ah[fm][3] = *(const u32*)&sAh[(r + 8) * 136 + kb + 8 + tg * 2];
            al[fm][0] = *(const u32*)&sAl[(r)     * 136 + kb + tg * 2];
            al[fm][1] = *(const u32*)&sAl[(r + 8) * 136 + kb + tg * 2];
            al[fm][2] = *(const u32*)&sAl[(r)     * 136 + kb + 8 + tg * 2];
            al[fm][3] = *(const u32*)&sAl[(r + 8) * 136 + kb + 8 + tg * 2];
        }
        u32 bh[8][2], bl[8][2];
#pragma unroll
        for (int fn = 0; fn < 8; fn++) {
            int n = wn * 64 + fn * 8 + gid;
            bh[fn][0] = *(const u32*)&sBh[n * 136 + kb + tg * 2];
            bh[fn][1] = *(const u32*)&sBh[n * 136 + kb + 8 + tg * 2];
            bl[fn][0] = *(const u32*)&sBl[n * 136 + kb + tg * 2];
            bl[fn][1] = *(const u32*)&sBl[n * 136 + kb + 8 + tg * 2];
        }
#pragma unroll
        for (int fm = 0; fm < 2; fm++)
#pragma unroll
            for (int fn = 0; fn < 8; fn++) {
                mma_bf16(acc[fm][fn], ah[fm], bh[fn]);   // hi*hi
                mma_bf16(acc[fm][fn], ah[fm], bl[fn]);   // hi*lo
                mma_bf16(acc[fm][fn], al[fm], bh[fn]);   // lo*hi
            }
    }

    // epilogue: Y += silu(acc + bias)
#pragma unroll
    for (int fm = 0; fm < 2; fm++) {
        int row = row0 + wm * 32 + fm * 16 + gid;
#pragma unroll
        for (int fn = 0; fn < 8; fn++) {
            int col = wn * 64 + fn * 8 + tg * 2;
            float2 b2 = *(const float2*)(bias + col);
            float* y0 = Y + (size_t)row * 128 + col;
            float2 v0 = *(float2*)y0;
            v0.x += silu_f(acc[fm][fn][0] + b2.x);
            v0.y += silu_f(acc[fm][fn][1] + b2.y);
            *(float2*)y0 = v0;
            float* y1 = Y + (size_t)(row + 8) * 128 + col;
            float2 v1 = *(float2*)y1;
            v1.x += silu_f(acc[fm][fn][2] + b2.x);
            v1.y += silu_f(acc[fm][fn][3] + b2.y);
            *(float2*)y1 = v1;
        }
    }
}

// ---------------- triplet: mkf = m[kj]*radf(d[kj])*ang[ji] (bf16 split out) + agg atomics ----------------
__global__ void triplet_kernel(const int* __restrict__ trip, const int* __restrict__ ei,
                               const float* __restrict__ dist)
{
    int gw = (blockIdx.x * blockDim.x + threadIdx.x) >> 5;
    int lane = threadIdx.x & 31;
    if (gw >= NEDGE) return;
    int ji = trip[gw * 3 + 0];
    int kj = trip[gw * 3 + 1];
    float aw = g_ang[ji];
    float4 mv = ((const float4*)(g_m + (size_t)kj * HID))[lane];
    float4 rv = tab_lerp(dist[kj], lane);
    float4 o = make_float4(mv.x * rv.x * aw, mv.y * rv.y * aw, mv.z * rv.z * aw, mv.w * rv.w * aw);

    // bf16 hi/lo split store
    __nv_bfloat162 h01, h23, l01, l23;
    h01.x = __float2bfloat16(o.x); h01.y = __float2bfloat16(o.y);
    h23.x = __float2bfloat16(o.z); h23.y = __float2bfloat16(o.w);
    l01.x = __float2bfloat16(o.x - __bfloat162float(h01.x));
    l01.y = __float2bfloat16(o.y - __bfloat162float(h01.y));
    l23.x = __float2bfloat16(o.z - __bfloat162float(h23.x));
    l23.y = __float2bfloat16(o.w - __bfloat162float(h23.y));
    __nv_bfloat162* dh = (__nv_bfloat162*)(g_mkf_hi + (size_t)gw * HID);
    __nv_bfloat162* dl = (__nv_bfloat162*)(g_mkf_lo + (size_t)gw * HID);
    dh[lane * 2] = h01; dh[lane * 2 + 1] = h23;
    dl[lane * 2] = l01; dl[lane * 2 + 1] = l23;

    int dd = ei[NEDGE + gw];
    float* p = g_agg + (size_t)dd * HID + lane * 4;
    atomicAdd(p + 0, o.x); atomicAdd(p + 1, o.y); atomicAdd(p + 2, o.z); atomicAdd(p + 3, o.w);
}

// ---------------- edge scatter: x[dst[e]] += h[src[e]] * radf(d[e]) ----------------
__global__ void scatter_kernel(const int* __restrict__ ei, const float* __restrict__ dist)
{
    int gw = (blockIdx.x * blockDim.x + threadIdx.x) >> 5;
    int lane = threadIdx.x & 31;
    if (gw >= NEDGE) return;
    int s  = ei[gw];
    int dd = ei[NEDGE + gw];
    float4 hv = ((const float4*)(g_h + (size_t)s * HID))[lane];
    float4 wv = tab_lerp(dist[gw], lane);
    float* p = g_x + (size_t)dd * HID + lane * 4;
    atomicAdd(p + 0, hv.x * wv.x); atomicAdd(p + 1, hv.y * wv.y);
    atomicAdd(p + 2, hv.z * wv.z); atomicAdd(p + 3, hv.w * wv.w);
}

// ---------------- output projection ----------------
template<bool ACCUM>
__global__ void outproj_kernel(const float* __restrict__ w, const float* __restrict__ b,
                               float* __restrict__ out)
{
    int idx = blockIdx.x * blockDim.x + threadIdx.x;
    int a = idx >> 5, lane = idx & 31;
    if (a >= NATOM) return;
    float4 xv = ((const float4*)(g_x + (size_t)a * HID))[lane];
    float4 wv = ((const float4*)w)[lane];
    float s = xv.x * wv.x + xv.y * wv.y + xv.z * wv.z + xv.w * wv.w;
#pragma unroll
    for (int off = 16; off > 0; off >>= 1) s += __shfl_xor_sync(0xFFFFFFFFu, s, off);
    if (lane == 0) {
        float v = s + b[0];
        if (ACCUM) out[a] += v; else out[a] = v;
    }
}

// ---------------- host launcher ----------------
extern "C" void kernel_launch(void* const* d_in, const int* in_sizes, int n_in,
                              void* d_out, int out_size)
{
    const int*   Z        = (const int*)d_in[0];
    const int*   ei       = (const int*)d_in[1];
    const float* dist     = (const float*)d_in[2];
    const float* dirs     = (const float*)d_in[3];
    const int*   trip     = (const int*)d_in[4];
    const float* atom_emb = (const float*)d_in[5];
    const float* embed_w  = (const float*)d_in[6];
    const float* embed_b  = (const float*)d_in[7];
    const float* ib_rad_w1 = (const float*)d_in[8];
    const float* ib_rad_b1 = (const float*)d_in[9];
    const float* ib_rad_w2 = (const float*)d_in[10];
    const float* ib_rad_b2 = (const float*)d_in[11];
    const float* ib_sph_w  = (const float*)d_in[12];
    const float* ib_sph_b  = (const float*)d_in[13];
    const float* ib_upd_w1 = (const float*)d_in[14];
    const float* ib_upd_b1 = (const float*)d_in[15];
    const float* ib_upd_w2 = (const float*)d_in[16];
    const float* ib_upd_b2 = (const float*)d_in[17];
    const float* ib_out_w  = (const float*)d_in[18];
    const float* ib_out_b  = (const float*)d_in[19];
    const float* ob_rad_w1 = (const float*)d_in[20];
    const float* ob_rad_b1 = (const float*)d_in[21];
    const float* ob_rad_w2 = (const float*)d_in[22];
    const float* ob_rad_b2 = (const float*)d_in[23];
    const float* ob_dense_w = (const float*)d_in[24];
    const float* ob_dense_b = (const float*)d_in[25];
    const float* ob_out_w  = (const float*)d_in[26];
    const float* ob_out_b  = (const float*)d_in[27];
    float* out = (float*)d_out;

    float *p_m, *p_h, *p_agg, *p_x, *p_tmp, *p_tabrbf, *p_tab;
    __nv_bfloat16 *p_mkf_hi, *p_mkf_lo;
    cudaGetSymbolAddress((void**)&p_m,    g_m);
    cudaGetSymbolAddress((void**)&p_mkf_hi, g_mkf_hi);
    cudaGetSymbolAddress((void**)&p_mkf_lo, g_mkf_lo);
    cudaGetSymbolAddress((void**)&p_h,    g_h);
    cudaGetSymbolAddress((void**)&p_agg,  g_agg);
    cudaGetSymbolAddress((void**)&p_x,    g_x);
    cudaGetSymbolAddress((void**)&p_tmp,  g_tmp);
    cudaGetSymbolAddress((void**)&p_tabrbf, g_tabrbf);
    cudaGetSymbolAddress((void**)&p_tab,  g_tab);

    cudaFuncSetAttribute(gemm128<false,false,false>, cudaFuncAttributeMaxDynamicSharedMemorySize, GEMM_SMEM);
    cudaFuncSetAttribute(gemm128<false,false,true >, cudaFuncAttributeMaxDynamicSharedMemorySize, GEMM_SMEM);
    cudaFuncSetAttribute(gemm128<true ,false,true >, cudaFuncAttributeMaxDynamicSharedMemorySize, GEMM_SMEM);
    cudaFuncSetAttribute(gemm128<false,true ,false>, cudaFuncAttributeMaxDynamicSharedMemorySize, GEMM_SMEM);
    cudaFuncSetAttribute(rad_mlp_kernel, cudaFuncAttributeMaxDynamicSharedMemorySize, RAD_SMEM);
    cudaFuncSetAttribute(mma_gemm_kernel, cudaFuncAttributeMaxDynamicSharedMemorySize, MMA_SMEM);

    const int GT = NTAB / 64;             // 256  (table gemm blocks)
    const int GA = (NATOM + 63) / 64;     // 157
    const int GW = NEDGE * 32 / 256;      // 40000 (warp-per-edge kernels)
    const int GM = NEDGE / 128;           // 2500 (mma gemm blocks)

    prep_kernel<<<(NEDGE + 255) / 256, 256>>>(dist, dirs);
    tab_prep_kernel<<<NTAB / 256, 256>>>();
    m_init_kernel<<<NEDGE / 8, 256>>>(embed_w, embed_b);
    h_init_kernel<<<(NATOM * 32 + 255) / 256, 256>>>(Z, atom_emb);

    // ---- output block 0 (writes out) ----
    rad_mlp_kernel<<<GT, 256, RAD_SMEM>>>(p_tabrbf, ob_rad_w1, ob_rad_b1, ob_rad_w2, ob_rad_b2, p_tab, NTAB);
    cudaMemsetAsync(p_x, 0, (size_t)NATOM * HID * sizeof(float));
    scatter_kernel<<<GW, 256>>>(ei, dist);
    for (int j = 0; j < 3; j++)
        gemm128<false,true,false><<<GA, 256, GEMM_SMEM>>>(p_x, ob_dense_w + (size_t)j * 16384,
                                                          ob_dense_b + j * 128, p_x, NATOM);
    outproj_kernel<false><<<(NATOM * 32 + 255) / 256, 256>>>(ob_out_w, ob_out_b, out);

    for (int i = 0; i < 4; i++) {
        // radial table + angles
        rad_mlp_kernel<<<GT, 256, RAD_SMEM>>>(p_tabrbf,
                                              ib_rad_w1 + (size_t)i * 2048, ib_rad_b1 + i * 128,
                                              ib_rad_w2 + (size_t)i * 16384, ib_rad_b2 + i * 128,
                                              p_tab, NTAB);
        angle_kernel<<<(NEDGE + 255) / 256, 256>>>(ib_sph_w + i * 56, ib_sph_b + i * 8);
        // triplet interaction + aggregation
        cudaMemsetAsync(p_agg, 0, (size_t)NATOM * HID * sizeof(float));
        triplet_kernel<<<GW, 256>>>(trip, ei, dist);
        // h update: h += silu([h,agg] @ W1 + b1) @ W2 + b2
        gemm128<false,false,false><<<GA, 256, GEMM_SMEM>>>(p_h,  ib_upd_w1 + (size_t)i * 32768,
                                                           ib_upd_b1 + i * 128, p_tmp, NATOM);
        gemm128<false,false,true ><<<GA, 256, GEMM_SMEM>>>(p_agg, ib_upd_w1 + (size_t)i * 32768 + 16384,
                                                           nullptr, p_tmp, NATOM);
        gemm128<true ,false,true ><<<GA, 256, GEMM_SMEM>>>(p_tmp, ib_upd_w2 + (size_t)i * 16384,
                                                           ib_upd_b2 + i * 128, p_h, NATOM);
        // m update (tensor cores): m += sum_j silu(mkf @ Wj + bj)
        for (int j = 0; j < 3; j++)
            mma_gemm_kernel<<<GM, 256, MMA_SMEM>>>(p_mkf_hi, p_mkf_lo,
                ib_out_w + ((size_t)(i * 3 + j)) * 16384, ib_out_b + (i * 3 + j) * 128, p_m);
        // ---- output block i+1 (accumulates into out) ----
        int ob = i + 1;
        rad_mlp_kernel<<<GT, 256, RAD_SMEM>>>(p_tabrbf,
                                              ob_rad_w1 + (size_t)ob * 2048, ob_rad_b1 + ob * 128,
                                              ob_rad_w2 + (size_t)ob * 16384, ob_rad_b2 + ob * 128,
                                              p_tab, NTAB);
        cudaMemsetAsync(p_x, 0, (size_t)NATOM * HID * sizeof(float));
        scatter_kernel<<<GW, 256>>>(ei, dist);
        for (int j = 0; j < 3; j++)
            gemm128<false,true,false><<<GA, 256, GEMM_SMEM>>>(p_x,
                ob_dense_w + ((size_t)(ob * 3 + j)) * 16384, ob_dense_b + (ob * 3 + j) * 128, p_x, NATOM);
        outproj_kernel<true><<<(NATOM * 32 + 255) / 256, 256>>>(ob_out_w + ob * 128, ob_out_b + ob, out);
    }
}

// round 5
// speedup vs baseline: 2.0405x; 1.4140x over previous
#include <cuda_runtime.h>
#include <cuda_bf16.h>
#include <math_constants.h>

#define NEDGE 320000
#define NATOM 10000
#define HID   128
#define CUT   5.0f
#define NTAB  16384

typedef unsigned long long u64;
typedef unsigned int u32;

// ---------------- scratch (static device memory; no allocations) ----------------
__device__ __align__(16) float g_rbf[(size_t)NEDGE * 16];
__device__ __align__(16) float g_sbf[(size_t)NEDGE * 7];
__device__ __align__(16) float g_m   [(size_t)NEDGE * HID];
__device__ __align__(16) __nv_bfloat16 g_mkf_hi[(size_t)NEDGE * HID];
__device__ __align__(16) __nv_bfloat16 g_mkf_lo[(size_t)NEDGE * HID];
__device__ __align__(16) float g_ang [NEDGE];
__device__ __align__(16) float g_h   [(size_t)NATOM * HID];
__device__ __align__(16) float g_agg [(size_t)NATOM * HID];
__device__ __align__(16) float g_x   [(size_t)NATOM * HID];
__device__ __align__(16) float g_tmp [(size_t)NATOM * HID];
__device__ __align__(16) float g_tabrbf[(size_t)NTAB * 16];
__device__ __align__(16) float g_tab [(size_t)NTAB * HID];

__device__ __forceinline__ float silu_f(float x) { return x / (1.0f + __expf(-x)); }

__device__ __forceinline__ void red_add_v4(float* p, float4 v)
{
    asm volatile("red.global.add.v4.f32 [%0], {%1,%2,%3,%4};"
                 :: "l"(p), "f"(v.x), "f"(v.y), "f"(v.z), "f"(v.w) : "memory");
}

// ---------------- packed f32x2 helpers (Blackwell 2-wide fp32 FMA) ----------------
__device__ __forceinline__ u64 pack2(float a) {
    u64 r; asm("mov.b64 %0, {%1, %1};" : "=l"(r) : "f"(a)); return r;
}
__device__ __forceinline__ void fma2(u64& d, u64 a, u64 b) {
    asm("fma.rn.f32x2 %0, %1, %2, %3;" : "=l"(d) : "l"(a), "l"(b), "l"(d));
}
__device__ __forceinline__ float2 unpack2(u64 v) {
    float2 f; asm("mov.b64 {%0, %1}, %2;" : "=f"(f.x), "=f"(f.y) : "l"(v)); return f;
}

// ---------------- bessel rbf ----------------
__device__ __forceinline__ void rbf_eval(float d, float* out16)
{
    float x = d * (1.0f / CUT);
    float x2 = x * x;
    float x6 = x2 * x2 * x2;
    float x7 = x6 * x;
    float x8 = x7 * x;
    float env = 1.0f - 28.0f * x6 + 48.0f * x7 - 21.0f * x8;
    if (!(d < CUT)) env = 0.0f;
    float s = sqrtf(2.0f / CUT) / d * env;
    float base = (float)CUDART_PI_F / CUT * d;
#pragma unroll
    for (int k = 0; k < 16; k++)
        out16[k] = s * sinf(base * (float)(k + 1));
}

__global__ void prep_kernel(const float* __restrict__ dist, const float* __restrict__ dirs)
{
    int e = blockIdx.x * blockDim.x + threadIdx.x;
    if (e >= NEDGE) return;
    float r16[16];
    rbf_eval(dist[e], r16);
#pragma unroll
    for (int k = 0; k < 16; k++) g_rbf[(size_t)e * 16 + k] = r16[k];

    float dx = dirs[e * 3 + 0], dy = dirs[e * 3 + 1], dz = dirs[e * 3 + 2];
    size_t o = (size_t)e * 7;
    g_sbf[o + 0] = 1.0f; g_sbf[o + 1] = dy; g_sbf[o + 2] = dz; g_sbf[o + 3] = dx;
    g_sbf[o + 4] = dx * dy; g_sbf[o + 5] = dy * dz; g_sbf[o + 6] = 3.0f * dz * dz - 1.0f;
}

__global__ void tab_prep_kernel()
{
    int i = blockIdx.x * blockDim.x + threadIdx.x;
    if (i >= NTAB) return;
    float d = fmaxf((float)i * (CUT / (float)(NTAB - 1)), 1e-4f);
    float r16[16];
    rbf_eval(d, r16);
#pragma unroll
    for (int k = 0; k < 16; k++) g_tabrbf[(size_t)i * 16 + k] = r16[k];
}

// lerp a float4 slice of the radial table at distance d (lane = 16B slice index)
__device__ __forceinline__ float4 tab_lerp(float d, int lane)
{
    float t = d * ((float)(NTAB - 1) / CUT);
    int i0 = min((int)t, NTAB - 2);
    float f = t - (float)i0;
    float4 lo = ((const float4*)(g_tab + (size_t)i0 * HID))[lane];
    float4 hi = ((const float4*)(g_tab + (size_t)(i0 + 1) * HID))[lane];
    float4 o;
    o.x = lo.x + (hi.x - lo.x) * f;
    o.y = lo.y + (hi.y - lo.y) * f;
    o.z = lo.z + (hi.z - lo.z) * f;
    o.w = lo.w + (hi.w - lo.w) * f;
    return o;
}

// ---------------- m init ----------------
__global__ void m_init_kernel(const float* __restrict__ embed_w, const float* __restrict__ embed_b)
{
    __shared__ float Ws[16 * 128];
    __shared__ float bs[128];
    __shared__ float rs[8 * 16];
    int tid = threadIdx.x;
    for (int i = tid; i < 2048; i += 256)
        Ws[i] = embed_w[(i >> 7) * 384 + 256 + (i & 127)];
    if (tid < 128) bs[tid] = embed_b[256 + tid];
    int e0 = blockIdx.x * 8;
    if (tid < 128) rs[tid] = g_rbf[(size_t)e0 * 16 + tid];
    __syncthreads();
    int w = tid >> 5, lane = tid & 31;
    int e = e0 + w;
    float4 acc = *(const float4*)&bs[lane * 4];
#pragma unroll
    for (int k = 0; k < 16; k++) {
        float a = rs[w * 16 + k];
        float4 wv = *(const float4*)&Ws[k * 128 + lane * 4];
        acc.x += a * wv.x; acc.y += a * wv.y; acc.z += a * wv.z; acc.w += a * wv.w;
    }
    ((float4*)(g_m + (size_t)e * HID))[lane] = acc;
}

__global__ void h_init_kernel(const int* __restrict__ Z, const float* __restrict__ emb)
{
    int idx = blockIdx.x * blockDim.x + threadIdx.x;
    int a = idx >> 5, lane = idx & 31;
    if (a >= NATOM) return;
    int z = Z[a] - 1;
    ((float4*)(g_h + (size_t)a * HID))[lane] =
        ((const float4*)(emb + (size_t)z * HID))[lane];
}

__global__ void angle_kernel(const float* __restrict__ sphW, const float* __restrict__ sphB)
{
    __shared__ float wbar[8];
    __shared__ float bbar;
    if (threadIdx.x < 7) {
        float s = 0.0f;
#pragma unroll
        for (int j = 0; j < 8; j++) s += sphW[threadIdx.x * 8 + j];
        wbar[threadIdx.x] = s * 0.125f;
    }
    if (threadIdx.x == 7) {
        float s = 0.0f;
#pragma unroll
        for (int j = 0; j < 8; j++) s += sphB[j];
        bbar = s * 0.125f;
    }
    __syncthreads();
    int e = blockIdx.x * blockDim.x + threadIdx.x;
    if (e >= NEDGE) return;
    float acc = bbar;
    size_t o = (size_t)e * 7;
#pragma unroll
    for (int k = 0; k < 7; k++) acc += g_sbf[o + k] * wbar[k];
    g_ang[e] = 1.0f / (1.0f + __expf(-acc));
}

// ---------------- SIMT GEMM core (f32x2, 4 rows x 8 cols per thread) ----------------
__device__ __forceinline__ void gemm_core8(const float* __restrict__ Ws,
                                           const float* __restrict__ Xs,
                                           u64 acc[4][4], int tx, int ty)
{
#pragma unroll 2
    for (int k0 = 0; k0 < 128; k0 += 4) {
        float4 av[4];
#pragma unroll
        for (int r = 0; r < 4; r++)
            av[r] = *(const float4*)(Xs + (ty * 4 + r) * 128 + k0);
#pragma unroll
        for (int kk = 0; kk < 4; kk++) {
            ulonglong2 b01 = *(const ulonglong2*)(Ws + (k0 + kk) * 128 + tx * 8);
            ulonglong2 b23 = *(const ulonglong2*)(Ws + (k0 + kk) * 128 + tx * 8 + 4);
#pragma unroll
            for (int r = 0; r < 4; r++) {
                float aval = ((const float*)&av[r])[kk];
                u64 ap = pack2(aval);
                fma2(acc[r][0], ap, b01.x);
                fma2(acc[r][1], ap, b01.y);
                fma2(acc[r][2], ap, b23.x);
                fma2(acc[r][3], ap, b23.y);
            }
        }
    }
}

// ---------------- generic SIMT 128x128 GEMM (atom-level work) ----------------
#define GEMM_SMEM ((16384 + 8192) * 4)
template<bool PRE_SILU, bool SILU_OUT, bool ACCUM>
__global__ void __launch_bounds__(256, 2) gemm128(const float* __restrict__ X,
                                                  const float* __restrict__ W,
                                                  const float* __restrict__ bias,
                                                  float* __restrict__ Y, int nrows)
{
    extern __shared__ float sm[];
    float* Ws = sm;            // 128*128
    float* Xs = sm + 16384;    // 64*128
    const int tid = threadIdx.x;
    const int row0 = blockIdx.x * 64;
    for (int i = tid; i < 4096; i += 256) ((float4*)Ws)[i] = ((const float4*)W)[i];
    const int rows = min(64, nrows - row0);
    for (int i = tid; i < 2048; i += 256) {
        int r = i >> 5, c = i & 31;
        float4 v = make_float4(0.f, 0.f, 0.f, 0.f);
        if (r < rows) v = ((const float4*)(X + (size_t)(row0 + r) * 128))[c];
        if (PRE_SILU) { v.x = silu_f(v.x); v.y = silu_f(v.y); v.z = silu_f(v.z); v.w = silu_f(v.w); }
        ((float4*)Xs)[i] = v;
    }
    __syncthreads();
    const int tx = tid & 15, ty = tid >> 4;
    u64 acc[4][4];
#pragma unroll
    for (int r = 0; r < 4; r++)
#pragma unroll
        for (int c = 0; c < 4; c++) acc[r][c] = 0ull;
    gemm_core8(Ws, Xs, acc, tx, ty);

    float4 blo = make_float4(0.f, 0.f, 0.f, 0.f), bhi = blo;
    if (bias) {
        blo = *(const float4*)(bias + tx * 8);
        bhi = *(const float4*)(bias + tx * 8 + 4);
    }
#pragma unroll
    for (int r = 0; r < 4; r++) {
        int row = ty * 4 + r;
        if (row >= rows) break;
        float2 p0 = unpack2(acc[r][0]);
        float2 p1 = unpack2(acc[r][1]);
        float2 p2 = unpack2(acc[r][2]);
        float2 p3 = unpack2(acc[r][3]);
        float4 o0 = make_float4(p0.x + blo.x, p0.y + blo.y, p1.x + blo.z, p1.y + blo.w);
        float4 o1 = make_float4(p2.x + bhi.x, p2.y + bhi.y, p3.x + bhi.z, p3.y + bhi.w);
        if (SILU_OUT) {
            o0.x = silu_f(o0.x); o0.y = silu_f(o0.y); o0.z = silu_f(o0.z); o0.w = silu_f(o0.w);
            o1.x = silu_f(o1.x); o1.y = silu_f(o1.y); o1.z = silu_f(o1.z); o1.w = silu_f(o1.w);
        }
        float* yp = Y + (size_t)(row0 + row) * 128 + tx * 8;
        if (ACCUM) {
            float4 u0 = *(float4*)yp;
            float4 u1 = *(float4*)(yp + 4);
            o0.x += u0.x; o0.y += u0.y; o0.z += u0.z; o0.w += u0.w;
            o1.x += u1.x; o1.y += u1.y; o1.z += u1.z; o1.w += u1.w;
        }
        *(float4*)yp = o0;
        *(float4*)(yp + 4) = o1;
    }
}

// ---------------- fused radial MLP on the distance table ----------------
#define RAD_SMEM ((16384 + 8192 + 2048 + 128 + 1024) * 4)
__global__ void __launch_bounds__(256, 2) rad_mlp_kernel(const float* __restrict__ rbf_in,
                                                         const float* __restrict__ rW1,
                                                         const float* __restrict__ rb1,
                                                         const float* __restrict__ rW2,
                                                         const float* __restrict__ rb2,
                                                         float* __restrict__ Y, int nrows)
{
    extern __shared__ float sm[];
    float* W2s = sm;
    float* Hs  = sm + 16384;
    float* W1s = sm + 16384 + 8192;
    float* b1s = W1s + 2048;
    float* Rs  = b1s + 128;
    const int tid = threadIdx.x;
    const int row0 = blockIdx.x * 64;
    for (int i = tid; i < 4096; i += 256) ((float4*)W2s)[i] = ((const float4*)rW2)[i];
    for (int i = tid; i < 512;  i += 256) ((float4*)W1s)[i] = ((const float4*)rW1)[i];
    if (tid < 32) ((float4*)b1s)[tid] = ((const float4*)rb1)[tid];
    const int rows = min(64, nrows - row0);
    if (tid < 256) {
        int i = tid;
        int r = i >> 2;
        float4 v = make_float4(0.f, 0.f, 0.f, 0.f);
        if (r < rows) v = ((const float4*)(rbf_in + (size_t)(row0 + r) * 16))[i & 3];
        ((float4*)Rs)[i] = v;
    }
    __syncthreads();
    {
        const int tx5 = tid & 31, ty5 = tid >> 5;
        float4 b1v = *(const float4*)&b1s[tx5 * 4];
#pragma unroll
        for (int i = 0; i < 8; i++) {
            int r = ty5 * 8 + i;
            float4 a4 = b1v;
#pragma unroll
            for (int k = 0; k < 16; k++) {
                float a = Rs[r * 16 + k];
                float4 w = *(const float4*)&W1s[k * 128 + tx5 * 4];
                a4.x += a * w.x; a4.y += a * w.y; a4.z += a * w.z; a4.w += a * w.w;
            }
            a4.x = silu_f(a4.x); a4.y = silu_f(a4.y); a4.z = silu_f(a4.z); a4.w = silu_f(a4.w);
            *(float4*)&Hs[r * 128 + tx5 * 4] = a4;
        }
    }
    __syncthreads();
    const int tx = tid & 15, ty = tid >> 4;
    u64 acc[4][4];
#pragma unroll
    for (int r = 0; r < 4; r++)
#pragma unroll
        for (int c = 0; c < 4; c++) acc[r][c] = 0ull;
    gemm_core8(W2s, Hs, acc, tx, ty);
    float4 blo = *(const float4*)(rb2 + tx * 8);
    float4 bhi = *(const float4*)(rb2 + tx * 8 + 4);
#pragma unroll
    for (int r = 0; r < 4; r++) {
        int row = ty * 4 + r;
        if (row >= rows) break;
        float2 p0 = unpack2(acc[r][0]);
        float2 p1 = unpack2(acc[r][1]);
        float2 p2 = unpack2(acc[r][2]);
        float2 p3 = unpack2(acc[r][3]);
        float* yp = Y + (size_t)(row0 + row) * 128 + tx * 8;
        *(float4*)yp       = make_float4(p0.x + blo.x, p0.y + blo.y, p1.x + blo.z, p1.y + blo.w);
        *(float4*)(yp + 4) = make_float4(p2.x + bhi.x, p2.y + bhi.y, p3.x + bhi.z, p3.y + bhi.w);
    }
}

// ---------------- fused bf16-split tensor GEMM x3: m += sum_j silu(A @ Wj + bj) ----------------
#define MMA_SMEM (4 * 128 * 136 * 2)
__device__ __forceinline__ void mma_bf16(float* c, const u32* a, const u32* b)
{
    asm volatile("mma.sync.aligned.m16n8k16.row.col.f32.bf16.bf16.f32 "
                 "{%0,%1,%2,%3}, {%4,%5,%6,%7}, {%8,%9}, {%0,%1,%2,%3};"
                 : "+f"(c[0]), "+f"(c[1]), "+f"(c[2]), "+f"(c[3])
                 : "r"(a[0]), "r"(a[1]), "r"(a[2]), "r"(a[3]), "r"(b[0]), "r"(b[1]));
}

__global__ void __launch_bounds__(256, 1) mma_gemm3_kernel(
    const __nv_bfloat16* __restrict__ Ahi, const __nv_bfloat16* __restrict__ Alo,
    const float* __restrict__ W3,      // [3][128][128]
    const float* __restrict__ bias3,   // [3][128]
    float* __restrict__ Y)
{
    extern __shared__ __nv_bfloat16 smb[];
    __nv_bfloat16* sAh = smb;                 // [128][136]
    __nv_bfloat16* sAl = smb + 128 * 136;
    __nv_bfloat16* sBh = smb + 2 * 128 * 136; // [n=128][k=136]
    __nv_bfloat16* sBl = smb + 3 * 128 * 136;
    const int tid = threadIdx.x;
    const int row0 = blockIdx.x * 128;

    // A tiles (loaded ONCE for all 3 weight matrices)
    {
        const uint4* Ah4 = (const uint4*)(Ahi + (size_t)row0 * 128);
        const uint4* Al4 = (const uint4*)(Alo + (size_t)row0 * 128);
        for (int i = tid; i < 2048; i += 256) {
            int r = i >> 4, c = i & 15;
            *(uint4*)&sAh[r * 136 + c * 8] = Ah4[r * 16 + c];
            *(uint4*)&sAl[r * 136 + c * 8] = Al4[r * 16 + c];
        }
    }

    const int lane = tid & 31, wid = tid >> 5;
    const int wm = wid >> 1, wn = wid & 1;      // 4x2 warp grid -> 32x64 warp tiles
    const int gid = lane >> 2, tg = lane & 3;

    float msum[2][8][4];
#pragma unroll
    for (int a = 0; a < 2; a++)
#pragma unroll
        for (int b = 0; b < 8; b++)
#pragma unroll
            for (int c = 0; c < 4; c++) msum[a][b][c] = 0.0f;

    for (int j = 0; j < 3; j++) {
        __syncthreads();   // previous iteration finished reading sB (and A ready on j=0)
        const float* W = W3 + (size_t)j * 16384;
        for (int i = tid; i < 16384; i += 256) {
            int k = i >> 7, n = i & 127;
            float w = W[i];
            __nv_bfloat16 h = __float2bfloat16(w);
            float r = w - __bfloat162float(h);
            sBh[n * 136 + k] = h;
            sBl[n * 136 + k] = __float2bfloat16(r);
        }
        __syncthreads();

        float acc[2][8][4];
#pragma unroll
        for (int a = 0; a < 2; a++)
#pragma unroll
            for (int b = 0; b < 8; b++)
#pragma unroll
                for (int c = 0; c < 4; c++) acc[a][b][c] = 0.0f;

#pragma unroll
        for (int ks = 0; ks < 8; ks++) {
            const int kb = ks * 16;
            u32 ah[2][4], al[2][4];
#pragma unroll
            for (int fm = 0; fm < 2; fm++) {
                int r = wm * 32 + fm * 16 + gid;
                ah[fm][0] = *(const u32*)&sAh[(r)     * 136 + kb + tg * 2];
                ah[fm][1] = *(const u32*)&sAh[(r + 8) * 136 + kb + tg * 2];
                ah[fm][2] = *(const u32*)&sAh[(r)     * 136 + kb + 8 + tg * 2];
                ah[fm][3] = *(const u32*)&sAh[(r + 8) * 136 + kb + 8 + tg * 2];
                al[fm][0] = *(const u32*)&sAl[(r)     * 136 + kb + tg * 2];
                al[fm][1] = *(const u32*)&sAl[(r + 8) * 136 + kb + tg * 2];
                al[fm][2] = *(const u32*)&sAl[(r)     * 136 + kb + 8 + tg * 2];
                al[fm][3] = *(const u32*)&sAl[(r + 8) * 136 + kb + 8 + tg * 2];
            }
            u32 bh[8][2], bl[8][2];
#pragma unroll
            for (int fn = 0; fn < 8; fn++) {
                int n = wn * 64 + fn * 8 + gid;
                bh[fn][0] = *(const u32*)&sBh[n * 136 + kb + tg * 2];
                bh[fn][1] = *(const u32*)&sBh[n * 136 + kb + 8 + tg * 2];
                bl[fn][0] = *(const u32*)&sBl[n * 136 + kb + tg * 2];
                bl[fn][1] = *(const u32*)&sBl[n * 136 + kb + 8 + tg * 2];
            }
#pragma unroll
            for (int fm = 0; fm < 2; fm++)
#pragma unroll
                for (int fn = 0; fn < 8; fn++) {
                    mma_bf16(acc[fm][fn], ah[fm], bh[fn]);   // hi*hi
                    mma_bf16(acc[fm][fn], ah[fm], bl[fn]);   // hi*lo
                    mma_bf16(acc[fm][fn], al[fm], bh[fn]);   // lo*hi
                }
        }

        // msum += silu(acc + bias_j)
        const float* bias = bias3 + j * 128;
#pragma unroll
        for (int fm = 0; fm < 2; fm++)
#pragma unroll
            for (int fn = 0; fn < 8; fn++) {
                int col = wn * 64 + fn * 8 + tg * 2;
                float2 b2 = *(const float2*)(bias + col);
                msum[fm][fn][0] += silu_f(acc[fm][fn][0] + b2.x);
                msum[fm][fn][1] += silu_f(acc[fm][fn][1] + b2.y);
                msum[fm][fn][2] += silu_f(acc[fm][fn][2] + b2.x);
                msum[fm][fn][3] += silu_f(acc[fm][fn][3] + b2.y);
            }
    }

    // single read-modify-write of Y (m)
#pragma unroll
    for (int fm = 0; fm < 2; fm++) {
        int row = row0 + wm * 32 + fm * 16 + gid;
#pragma unroll
        for (int fn = 0; fn < 8; fn++) {
            int col = wn * 64 + fn * 8 + tg * 2;
            float* y0 = Y + (size_t)row * 128 + col;
            float2 v0 = *(float2*)y0;
            v0.x += msum[fm][fn][0];
            v0.y += msum[fm][fn][1];
            *(float2*)y0 = v0;
            float* y1 = Y + (size_t)(row + 8) * 128 + col;
            float2 v1 = *(float2*)y1;
            v1.x += msum[fm][fn][2];
            v1.y += msum[fm][fn][3];
            *(float2*)y1 = v1;
        }
    }
}

// ---------------- triplet: mkf = m[kj]*radf(d[kj])*ang[ji] (bf16 split out) + agg red.v4 ----------------
__global__ void triplet_kernel(const int* __restrict__ trip, const int* __restrict__ ei,
                               const float* __restrict__ dist)
{
    int gw = (blockIdx.x * blockDim.x + threadIdx.x) >> 5;
    int lane = threadIdx.x & 31;
    if (gw >= NEDGE) return;
    int ji = trip[gw * 3 + 0];
    int kj = trip[gw * 3 + 1];
    float aw = g_ang[ji];
    float4 mv = ((const float4*)(g_m + (size_t)kj * HID))[lane];
    float4 rv = tab_lerp(dist[kj], lane);
    float4 o = make_float4(mv.x * rv.x * aw, mv.y * rv.y * aw, mv.z * rv.z * aw, mv.w * rv.w * aw);

    // bf16 hi/lo split store
    __nv_bfloat162 h01, h23, l01, l23;
    h01.x = __float2bfloat16(o.x); h01.y = __float2bfloat16(o.y);
    h23.x = __float2bfloat16(o.z); h23.y = __float2bfloat16(o.w);
    l01.x = __float2bfloat16(o.x - __bfloat162float(h01.x));
    l01.y = __float2bfloat16(o.y - __bfloat162float(h01.y));
    l23.x = __float2bfloat16(o.z - __bfloat162float(h23.x));
    l23.y = __float2bfloat16(o.w - __bfloat162float(h23.y));
    __nv_bfloat162* dh = (__nv_bfloat162*)(g_mkf_hi + (size_t)gw * HID);
    __nv_bfloat162* dl = (__nv_bfloat162*)(g_mkf_lo + (size_t)gw * HID);
    dh[lane * 2] = h01; dh[lane * 2 + 1] = h23;
    dl[lane * 2] = l01; dl[lane * 2 + 1] = l23;

    int dd = ei[NEDGE + gw];
    red_add_v4(g_agg + (size_t)dd * HID + lane * 4, o);
}

// ---------------- edge scatter: x[dst[e]] += h[src[e]] * radf(d[e]) (red.v4) ----------------
__global__ void scatter_kernel(const int* __restrict__ ei, const float* __restrict__ dist)
{
    int gw = (blockIdx.x * blockDim.x + threadIdx.x) >> 5;
    int lane = threadIdx.x & 31;
    if (gw >= NEDGE) return;
    int s  = ei[gw];
    int dd = ei[NEDGE + gw];
    float4 hv = ((const float4*)(g_h + (size_t)s * HID))[lane];
    float4 wv = tab_lerp(dist[gw], lane);
    float4 o = make_float4(hv.x * wv.x, hv.y * wv.y, hv.z * wv.z, hv.w * wv.w);
    red_add_v4(g_x + (size_t)dd * HID + lane * 4, o);
}

// ---------------- output projection ----------------
template<bool ACCUM>
__global__ void outproj_kernel(const float* __restrict__ w, const float* __restrict__ b,
                               float* __restrict__ out)
{
    int idx = blockIdx.x * blockDim.x + threadIdx.x;
    int a = idx >> 5, lane = idx & 31;
    if (a >= NATOM) return;
    float4 xv = ((const float4*)(g_x + (size_t)a * HID))[lane];
    float4 wv = ((const float4*)w)[lane];
    float s = xv.x * wv.x + xv.y * wv.y + xv.z * wv.z + xv.w * wv.w;
#pragma unroll
    for (int off = 16; off > 0; off >>= 1) s += __shfl_xor_sync(0xFFFFFFFFu, s, off);
    if (lane == 0) {
        float v = s + b[0];
        if (ACCUM) out[a] += v; else out[a] = v;
    }
}

// ---------------- host launcher ----------------
extern "C" void kernel_launch(void* const* d_in, const int* in_sizes, int n_in,
                              void* d_out, int out_size)
{
    const int*   Z        = (const int*)d_in[0];
    const int*   ei       = (const int*)d_in[1];
    const float* dist     = (const float*)d_in[2];
    const float* dirs     = (const float*)d_in[3];
    const int*   trip     = (const int*)d_in[4];
    const float* atom_emb = (const float*)d_in[5];
    const float* embed_w  = (const float*)d_in[6];
    const float* embed_b  = (const float*)d_in[7];
    const float* ib_rad_w1 = (const float*)d_in[8];
    const float* ib_rad_b1 = (const float*)d_in[9];
    const float* ib_rad_w2 = (const float*)d_in[10];
    const float* ib_rad_b2 = (const float*)d_in[11];
    const float* ib_sph_w  = (const float*)d_in[12];
    const float* ib_sph_b  = (const float*)d_in[13];
    const float* ib_upd_w1 = (const float*)d_in[14];
    const float* ib_upd_b1 = (const float*)d_in[15];
    const float* ib_upd_w2 = (const float*)d_in[16];
    const float* ib_upd_b2 = (const float*)d_in[17];
    const float* ib_out_w  = (const float*)d_in[18];
    const float* ib_out_b  = (const float*)d_in[19];
    const float* ob_rad_w1 = (const float*)d_in[20];
    const float* ob_rad_b1 = (const float*)d_in[21];
    const float* ob_rad_w2 = (const float*)d_in[22];
    const float* ob_rad_b2 = (const float*)d_in[23];
    const float* ob_dense_w = (const float*)d_in[24];
    const float* ob_dense_b = (const float*)d_in[25];
    const float* ob_out_w  = (const float*)d_in[26];
    const float* ob_out_b  = (const float*)d_in[27];
    float* out = (float*)d_out;

    float *p_m, *p_h, *p_agg, *p_x, *p_tmp, *p_tabrbf, *p_tab;
    __nv_bfloat16 *p_mkf_hi, *p_mkf_lo;
    cudaGetSymbolAddress((void**)&p_m,    g_m);
    cudaGetSymbolAddress((void**)&p_mkf_hi, g_mkf_hi);
    cudaGetSymbolAddress((void**)&p_mkf_lo, g_mkf_lo);
    cudaGetSymbolAddress((void**)&p_h,    g_h);
    cudaGetSymbolAddress((void**)&p_agg,  g_agg);
    cudaGetSymbolAddress((void**)&p_x,    g_x);
    cudaGetSymbolAddress((void**)&p_tmp,  g_tmp);
    cudaGetSymbolAddress((void**)&p_tabrbf, g_tabrbf);
    cudaGetSymbolAddress((void**)&p_tab,  g_tab);

    cudaFuncSetAttribute(gemm128<false,false,false>, cudaFuncAttributeMaxDynamicSharedMemorySize, GEMM_SMEM);
    cudaFuncSetAttribute(gemm128<false,false,true >, cudaFuncAttributeMaxDynamicSharedMemorySize, GEMM_SMEM);
    cudaFuncSetAttribute(gemm128<true ,false,true >, cudaFuncAttributeMaxDynamicSharedMemorySize, GEMM_SMEM);
    cudaFuncSetAttribute(gemm128<false,true ,false>, cudaFuncAttributeMaxDynamicSharedMemorySize, GEMM_SMEM);
    cudaFuncSetAttribute(rad_mlp_kernel, cudaFuncAttributeMaxDynamicSharedMemorySize, RAD_SMEM);
    cudaFuncSetAttribute(mma_gemm3_kernel, cudaFuncAttributeMaxDynamicSharedMemorySize, MMA_SMEM);

    const int GT = NTAB / 64;             // 256  (table gemm blocks)
    const int GA = (NATOM + 63) / 64;     // 157
    const int GW = NEDGE * 32 / 256;      // 40000 (warp-per-edge kernels)
    const int GM = NEDGE / 128;           // 2500 (mma gemm blocks)

    prep_kernel<<<(NEDGE + 255) / 256, 256>>>(dist, dirs);
    tab_prep_kernel<<<NTAB / 256, 256>>>();
    m_init_kernel<<<NEDGE / 8, 256>>>(embed_w, embed_b);
    h_init_kernel<<<(NATOM * 32 + 255) / 256, 256>>>(Z, atom_emb);

    // ---- output block 0 (writes out) ----
    rad_mlp_kernel<<<GT, 256, RAD_SMEM>>>(p_tabrbf, ob_rad_w1, ob_rad_b1, ob_rad_w2, ob_rad_b2, p_tab, NTAB);
    cudaMemsetAsync(p_x, 0, (size_t)NATOM * HID * sizeof(float));
    scatter_kernel<<<GW, 256>>>(ei, dist);
    for (int j = 0; j < 3; j++)
        gemm128<false,true,false><<<GA, 256, GEMM_SMEM>>>(p_x, ob_dense_w + (size_t)j * 16384,
                                                          ob_dense_b + j * 128, p_x, NATOM);
    outproj_kernel<false><<<(NATOM * 32 + 255) / 256, 256>>>(ob_out_w, ob_out_b, out);

    for (int i = 0; i < 4; i++) {
        // radial table + angles
        rad_mlp_kernel<<<GT, 256, RAD_SMEM>>>(p_tabrbf,
                                              ib_rad_w1 + (size_t)i * 2048, ib_rad_b1 + i * 128,
                                              ib_rad_w2 + (size_t)i * 16384, ib_rad_b2 + i * 128,
                                              p_tab, NTAB);
        angle_kernel<<<(NEDGE + 255) / 256, 256>>>(ib_sph_w + i * 56, ib_sph_b + i * 8);
        // triplet interaction + aggregation
        cudaMemsetAsync(p_agg, 0, (size_t)NATOM * HID * sizeof(float));
        triplet_kernel<<<GW, 256>>>(trip, ei, dist);
        // h update: h += silu([h,agg] @ W1 + b1) @ W2 + b2
        gemm128<false,false,false><<<GA, 256, GEMM_SMEM>>>(p_h,  ib_upd_w1 + (size_t)i * 32768,
                                                           ib_upd_b1 + i * 128, p_tmp, NATOM);
        gemm128<false,false,true ><<<GA, 256, GEMM_SMEM>>>(p_agg, ib_upd_w1 + (size_t)i * 32768 + 16384,
                                                           nullptr, p_tmp, NATOM);
        gemm128<true ,false,true ><<<GA, 256, GEMM_SMEM>>>(p_tmp, ib_upd_w2 + (size_t)i * 16384,
                                                           ib_upd_b2 + i * 128, p_h, NATOM);
        // m update (tensor cores, fused x3): m += sum_j silu(mkf @ Wj + bj)
        mma_gemm3_kernel<<<GM, 256, MMA_SMEM>>>(p_mkf_hi, p_mkf_lo,
            ib_out_w + (size_t)i * 3 * 16384, ib_out_b + i * 3 * 128, p_m);
        // ---- output block i+1 (accumulates into out) ----
        int ob = i + 1;
        rad_mlp_kernel<<<GT, 256, RAD_SMEM>>>(p_tabrbf,
                                              ob_rad_w1 + (size_t)ob * 2048, ob_rad_b1 + ob * 128,
                                              ob_rad_w2 + (size_t)ob * 16384, ob_rad_b2 + ob * 128,
                                              p_tab, NTAB);
        cudaMemsetAsync(p_x, 0, (size_t)NATOM * HID * sizeof(float));
        scatter_kernel<<<GW, 256>>>(ei, dist);
        for (int j = 0; j < 3; j++)
            gemm128<false,true,false><<<GA, 256, GEMM_SMEM>>>(p_x,
                ob_dense_w + ((size_t)(ob * 3 + j)) * 16384, ob_dense_b + (ob * 3 + j) * 128, p_x, NATOM);
        outproj_kernel<true><<<(NATOM * 32 + 255) / 256, 256>>>(ob_out_w + ob * 128, ob_out_b + ob, out);
    }
}

// round 6
// speedup vs baseline: 2.5114x; 1.2308x over previous
#include <cuda_runtime.h>
#include <cuda_bf16.h>
#include <math_constants.h>

#define NEDGE 320000
#define NATOM 10000
#define HID   128
#define CUT   5.0f
#define NTAB  16384

typedef unsigned long long u64;
typedef unsigned int u32;

// ---------------- scratch (static device memory; no allocations) ----------------
__device__ __align__(16) float g_m   [(size_t)NEDGE * HID];
__device__ __align__(16) __nv_bfloat16 g_mkf_hi[(size_t)NEDGE * HID];
__device__ __align__(16) __nv_bfloat16 g_mkf_lo[(size_t)NEDGE * HID];
__device__ __align__(16) float g_ang [NEDGE];
__device__ __align__(16) float g_h   [(size_t)NATOM * HID];
__device__ __align__(16) float g_agg [(size_t)NATOM * HID];
__device__ __align__(16) float g_x   [(size_t)NATOM * HID];
__device__ __align__(16) float g_tabrbf[(size_t)NTAB * 16];
__device__ __align__(16) float g_tab [(size_t)NTAB * HID];
__device__ __align__(16) float g_tabm[(size_t)NTAB * HID];
__device__ __align__(16) __nv_bfloat16 g_wbh[(size_t)12 * HID * HID];  // ib_out_w hi, [n][k]
__device__ __align__(16) __nv_bfloat16 g_wbl[(size_t)12 * HID * HID];  // ib_out_w lo, [n][k]

__device__ __forceinline__ float silu_f(float x) { return x / (1.0f + __expf(-x)); }

__device__ __forceinline__ void red_add_v4(float* p, float4 v)
{
    asm volatile("red.global.add.v4.f32 [%0], {%1,%2,%3,%4};"
                 :: "l"(p), "f"(v.x), "f"(v.y), "f"(v.z), "f"(v.w) : "memory");
}

// ---------------- packed f32x2 helpers ----------------
__device__ __forceinline__ u64 pack2(float a) {
    u64 r; asm("mov.b64 %0, {%1, %1};" : "=l"(r) : "f"(a)); return r;
}
__device__ __forceinline__ void fma2(u64& d, u64 a, u64 b) {
    asm("fma.rn.f32x2 %0, %1, %2, %3;" : "=l"(d) : "l"(a), "l"(b), "l"(d));
}
__device__ __forceinline__ float2 unpack2(u64 v) {
    float2 f; asm("mov.b64 {%0, %1}, %2;" : "=f"(f.x), "=f"(f.y) : "l"(v)); return f;
}

// ---------------- bessel rbf ----------------
__device__ __forceinline__ void rbf_eval(float d, float* out16)
{
    float x = d * (1.0f / CUT);
    float x2 = x * x;
    float x6 = x2 * x2 * x2;
    float x7 = x6 * x;
    float x8 = x7 * x;
    float env = 1.0f - 28.0f * x6 + 48.0f * x7 - 21.0f * x8;
    if (!(d < CUT)) env = 0.0f;
    float s = sqrtf(2.0f / CUT) / d * env;
    float base = (float)CUDART_PI_F / CUT * d;
#pragma unroll
    for (int k = 0; k < 16; k++)
        out16[k] = s * sinf(base * (float)(k + 1));
}

__global__ void tab_prep_kernel()
{
    int i = blockIdx.x * blockDim.x + threadIdx.x;
    if (i >= NTAB) return;
    float d = fmaxf((float)i * (CUT / (float)(NTAB - 1)), 1e-4f);
    float r16[16];
    rbf_eval(d, r16);
#pragma unroll
    for (int k = 0; k < 16; k++) g_tabrbf[(size_t)i * 16 + k] = r16[k];
}

// lerp a float4 slice of a [NTAB][128] table at distance d (lane = 16B slice index)
__device__ __forceinline__ float4 tab_lerp_t(const float* tab, float d, int lane)
{
    float t = d * ((float)(NTAB - 1) / CUT);
    int i0 = min((int)t, NTAB - 2);
    float f = t - (float)i0;
    float4 lo = ((const float4*)(tab + (size_t)i0 * HID))[lane];
    float4 hi = ((const float4*)(tab + (size_t)(i0 + 1) * HID))[lane];
    float4 o;
    o.x = lo.x + (hi.x - lo.x) * f;
    o.y = lo.y + (hi.y - lo.y) * f;
    o.z = lo.z + (hi.z - lo.z) * f;
    o.w = lo.w + (hi.w - lo.w) * f;
    return o;
}

// ---------------- m table: tabm = tabrbf @ embed_w[:,256:384] + embed_b[256:] ----------------
__global__ void tabm_kernel(const float* __restrict__ embed_w, const float* __restrict__ embed_b)
{
    __shared__ float Ws[16 * 128];
    __shared__ float bs[128];
    __shared__ float rs[8 * 16];
    int tid = threadIdx.x;
    for (int i = tid; i < 2048; i += 256)
        Ws[i] = embed_w[(i >> 7) * 384 + 256 + (i & 127)];
    if (tid < 128) bs[tid] = embed_b[256 + tid];
    int e0 = blockIdx.x * 8;
    if (tid < 128) rs[tid] = g_tabrbf[(size_t)e0 * 16 + tid];
    __syncthreads();
    int w = tid >> 5, lane = tid & 31;
    int e = e0 + w;
    float4 acc = *(const float4*)&bs[lane * 4];
#pragma unroll
    for (int k = 0; k < 16; k++) {
        float a = rs[w * 16 + k];
        float4 wv = *(const float4*)&Ws[k * 128 + lane * 4];
        acc.x += a * wv.x; acc.y += a * wv.y; acc.z += a * wv.z; acc.w += a * wv.w;
    }
    ((float4*)(g_tabm + (size_t)e * HID))[lane] = acc;
}

// ---------------- m interp: m[e] = lerp(tabm, d[e]) ----------------
__global__ void m_interp_kernel(const float* __restrict__ dist)
{
    int gw = (blockIdx.x * blockDim.x + threadIdx.x) >> 5;
    int lane = threadIdx.x & 31;
    if (gw >= NEDGE) return;
    float4 o = tab_lerp_t(g_tabm, dist[gw], lane);
    ((float4*)(g_m + (size_t)gw * HID))[lane] = o;
}

// ---------------- pre-split ib_out_w -> bf16 hi/lo, transposed [n][k] ----------------
__global__ void wsplit_kernel(const float* __restrict__ W)   // [12][128][128] (k-major)
{
    int i = blockIdx.x * blockDim.x + threadIdx.x;
    if (i >= 12 * HID * HID) return;
    int mat = i >> 14;
    int r = i & 16383;
    int k = r >> 7, n = r & 127;
    float w = W[i];
    __nv_bfloat16 h = __float2bfloat16(w);
    float rr = w - __bfloat162float(h);
    size_t o = (size_t)mat * 16384 + n * 128 + k;
    g_wbh[o] = h;
    g_wbl[o] = __float2bfloat16(rr);
}

// ---------------- h init ----------------
__global__ void h_init_kernel(const int* __restrict__ Z, const float* __restrict__ emb)
{
    int idx = blockIdx.x * blockDim.x + threadIdx.x;
    int a = idx >> 5, lane = idx & 31;
    if (a >= NATOM) return;
    int z = Z[a] - 1;
    ((float4*)(g_h + (size_t)a * HID))[lane] =
        ((const float4*)(emb + (size_t)z * HID))[lane];
}

// ---------------- angle: ang[e] = sigmoid(sbf(dirs[e]) . wbar + bbar) ----------------
__global__ void angle_kernel(const float* __restrict__ sphW, const float* __restrict__ sphB,
                             const float* __restrict__ dirs)
{
    __shared__ float wbar[8];
    __shared__ float bbar;
    if (threadIdx.x < 7) {
        float s = 0.0f;
#pragma unroll
        for (int j = 0; j < 8; j++) s += sphW[threadIdx.x * 8 + j];
        wbar[threadIdx.x] = s * 0.125f;
    }
    if (threadIdx.x == 7) {
        float s = 0.0f;
#pragma unroll
        for (int j = 0; j < 8; j++) s += sphB[j];
        bbar = s * 0.125f;
    }
    __syncthreads();
    int e = blockIdx.x * blockDim.x + threadIdx.x;
    if (e >= NEDGE) return;
    float dx = dirs[e * 3 + 0], dy = dirs[e * 3 + 1], dz = dirs[e * 3 + 2];
    float acc = bbar + wbar[0] + wbar[1] * dy + wbar[2] * dz + wbar[3] * dx
              + wbar[4] * dx * dy + wbar[5] * dy * dz + wbar[6] * (3.0f * dz * dz - 1.0f);
    g_ang[e] = 1.0f / (1.0f + __expf(-acc));
}

// ---------------- SIMT GEMM core (f32x2, 4 rows x 8 cols per thread) ----------------
__device__ __forceinline__ void gemm_core8(const float* __restrict__ Ws,
                                           const float* __restrict__ Xs,
                                           u64 acc[4][4], int tx, int ty)
{
#pragma unroll 2
    for (int k0 = 0; k0 < 128; k0 += 4) {
        float4 av[4];
#pragma unroll
        for (int r = 0; r < 4; r++)
            av[r] = *(const float4*)(Xs + (ty * 4 + r) * 128 + k0);
#pragma unroll
        for (int kk = 0; kk < 4; kk++) {
            ulonglong2 b01 = *(const ulonglong2*)(Ws + (k0 + kk) * 128 + tx * 8);
            ulonglong2 b23 = *(const ulonglong2*)(Ws + (k0 + kk) * 128 + tx * 8 + 4);
#pragma unroll
            for (int r = 0; r < 4; r++) {
                float aval = ((const float*)&av[r])[kk];
                u64 ap = pack2(aval);
                fma2(acc[r][0], ap, b01.x);
                fma2(acc[r][1], ap, b01.y);
                fma2(acc[r][2], ap, b23.x);
                fma2(acc[r][3], ap, b23.y);
            }
        }
    }
}

// ---------------- fused radial MLP on the distance table ----------------
#define RAD_SMEM ((16384 + 8192 + 2048 + 128 + 1024) * 4)
__global__ void __launch_bounds__(256, 2) rad_mlp_kernel(const float* __restrict__ rbf_in,
                                                         const float* __restrict__ rW1,
                                                         const float* __restrict__ rb1,
                                                         const float* __restrict__ rW2,
                                                         const float* __restrict__ rb2,
                                                         float* __restrict__ Y, int nrows)
{
    extern __shared__ float sm[];
    float* W2s = sm;
    float* Hs  = sm + 16384;
    float* W1s = sm + 16384 + 8192;
    float* b1s = W1s + 2048;
    float* Rs  = b1s + 128;
    const int tid = threadIdx.x;
    const int row0 = blockIdx.x * 64;
    for (int i = tid; i < 4096; i += 256) ((float4*)W2s)[i] = ((const float4*)rW2)[i];
    for (int i = tid; i < 512;  i += 256) ((float4*)W1s)[i] = ((const float4*)rW1)[i];
    if (tid < 32) ((float4*)b1s)[tid] = ((const float4*)rb1)[tid];
    const int rows = min(64, nrows - row0);
    {
        int i = tid;
        int r = i >> 2;
        float4 v = make_float4(0.f, 0.f, 0.f, 0.f);
        if (r < rows) v = ((const float4*)(rbf_in + (size_t)(row0 + r) * 16))[i & 3];
        ((float4*)Rs)[i] = v;
    }
    __syncthreads();
    {
        const int tx5 = tid & 31, ty5 = tid >> 5;
        float4 b1v = *(const float4*)&b1s[tx5 * 4];
#pragma unroll
        for (int i = 0; i < 8; i++) {
            int r = ty5 * 8 + i;
            float4 a4 = b1v;
#pragma unroll
            for (int k = 0; k < 16; k++) {
                float a = Rs[r * 16 + k];
                float4 w = *(const float4*)&W1s[k * 128 + tx5 * 4];
                a4.x += a * w.x; a4.y += a * w.y; a4.z += a * w.z; a4.w += a * w.w;
            }
            a4.x = silu_f(a4.x); a4.y = silu_f(a4.y); a4.z = silu_f(a4.z); a4.w = silu_f(a4.w);
            *(float4*)&Hs[r * 128 + tx5 * 4] = a4;
        }
    }
    __syncthreads();
    const int tx = tid & 15, ty = tid >> 4;
    u64 acc[4][4];
#pragma unroll
    for (int r = 0; r < 4; r++)
#pragma unroll
        for (int c = 0; c < 4; c++) acc[r][c] = 0ull;
    gemm_core8(W2s, Hs, acc, tx, ty);
    float4 blo = *(const float4*)(rb2 + tx * 8);
    float4 bhi = *(const float4*)(rb2 + tx * 8 + 4);
#pragma unroll
    for (int r = 0; r < 4; r++) {
        int row = ty * 4 + r;
        if (row >= rows) break;
        float2 p0 = unpack2(acc[r][0]);
        float2 p1 = unpack2(acc[r][1]);
        float2 p2 = unpack2(acc[r][2]);
        float2 p3 = unpack2(acc[r][3]);
        float* yp = Y + (size_t)(row0 + row) * 128 + tx * 8;
        *(float4*)yp       = make_float4(p0.x + blo.x, p0.y + blo.y, p1.x + blo.z, p1.y + blo.w);
        *(float4*)(yp + 4) = make_float4(p2.x + bhi.x, p2.y + bhi.y, p3.x + bhi.z, p3.y + bhi.w);
    }
}

// ---------------- fused h update: h += silu([h,agg]@W1 + b1) @ W2 + b2 ----------------
#define HUPD_SMEM ((16384 + 8192) * 4)
__global__ void __launch_bounds__(256, 2) hupdate_kernel(const float* __restrict__ w1,
                                                         const float* __restrict__ b1,
                                                         const float* __restrict__ w2,
                                                         const float* __restrict__ b2,
                                                         int nrows)
{
    extern __shared__ float sm[];
    float* Ws = sm;            // 128x128
    float* Xs = sm + 16384;    // 64x128
    const int tid = threadIdx.x;
    const int row0 = blockIdx.x * 64;
    const int rows = min(64, nrows - row0);
    const int tx = tid & 15, ty = tid >> 4;

    // stage A: acc = h @ W1[:128]
    for (int i = tid; i < 2048; i += 256) {
        int r = i >> 5, c = i & 31;
        float4 v = make_float4(0.f, 0.f, 0.f, 0.f);
        if (r < rows) v = ((const float4*)(g_h + (size_t)(row0 + r) * 128))[c];
        ((float4*)Xs)[i] = v;
    }
    for (int i = tid; i < 4096; i += 256) ((float4*)Ws)[i] = ((const float4*)w1)[i];
    __syncthreads();
    u64 acc[4][4];
#pragma unroll
    for (int r = 0; r < 4; r++)
#pragma unroll
        for (int c = 0; c < 4; c++) acc[r][c] = 0ull;
    gemm_core8(Ws, Xs, acc, tx, ty);
    __syncthreads();

    // stage B: acc += agg @ W1[128:]
    for (int i = tid; i < 2048; i += 256) {
        int r = i >> 5, c = i & 31;
        float4 v = make_float4(0.f, 0.f, 0.f, 0.f);
        if (r < rows) v = ((const float4*)(g_agg + (size_t)(row0 + r) * 128))[c];
        ((float4*)Xs)[i] = v;
    }
    for (int i = tid; i < 4096; i += 256) ((float4*)Ws)[i] = ((const float4*)(w1 + 16384))[i];
    __syncthreads();
    gemm_core8(Ws, Xs, acc, tx, ty);
    __syncthreads();

    // Xs = silu(acc + b1); load W2 concurrently
    {
        float4 blo = *(const float4*)(b1 + tx * 8);
        float4 bhi = *(const float4*)(b1 + tx * 8 + 4);
#pragma unroll
        for (int r = 0; r < 4; r++) {
            int row = ty * 4 + r;
            float2 p0 = unpack2(acc[r][0]);
            float2 p1 = unpack2(acc[r][1]);
            float2 p2 = unpack2(acc[r][2]);
            float2 p3 = unpack2(acc[r][3]);
            float4 o0 = make_float4(silu_f(p0.x + blo.x), silu_f(p0.y + blo.y),
                                    silu_f(p1.x + blo.z), silu_f(p1.y + blo.w));
            float4 o1 = make_float4(silu_f(p2.x + bhi.x), silu_f(p2.y + bhi.y),
                                    silu_f(p3.x + bhi.z), silu_f(p3.y + bhi.w));
            *(float4*)&Xs[row * 128 + tx * 8]     = o0;
            *(float4*)&Xs[row * 128 + tx * 8 + 4] = o1;
        }
    }
    for (int i = tid; i < 4096; i += 256) ((float4*)Ws)[i] = ((const float4*)w2)[i];
    __syncthreads();

    // stage C: h += Xs @ W2 + b2
#pragma unroll
    for (int r = 0; r < 4; r++)
#pragma unroll
        for (int c = 0; c < 4; c++) acc[r][c] = 0ull;
    gemm_core8(Ws, Xs, acc, tx, ty);
    {
        float4 blo = *(const float4*)(b2 + tx * 8);
        float4 bhi = *(const float4*)(b2 + tx * 8 + 4);
#pragma unroll
        for (int r = 0; r < 4; r++) {
            int row = ty * 4 + r;
            if (row >= rows) break;
            float2 p0 = unpack2(acc[r][0]);
            float2 p1 = unpack2(acc[r][1]);
            float2 p2 = unpack2(acc[r][2]);
            float2 p3 = unpack2(acc[r][3]);
            float* hp = g_h + (size_t)(row0 + row) * 128 + tx * 8;
            float4 u0 = *(float4*)hp;
            float4 u1 = *(float4*)(hp + 4);
            u0.x += p0.x + blo.x; u0.y += p0.y + blo.y; u0.z += p1.x + blo.z; u0.w += p1.y + blo.w;
            u1.x += p2.x + bhi.x; u1.y += p2.y + bhi.y; u1.z += p3.x + bhi.z; u1.w += p3.y + bhi.w;
            *(float4*)hp = u0;
            *(float4*)(hp + 4) = u1;
        }
    }
}

// ---------------- fused output block: out (+)= ((3x silu dense)(x)) @ ow + ob ----------------
#define OUT_SMEM ((16384 + 8192 + 128) * 4)
template<bool ACCUM>
__global__ void __launch_bounds__(256, 2) outblock_kernel(const float* __restrict__ dw,   // [3][128][128]
                                                          const float* __restrict__ db,   // [3][128]
                                                          const float* __restrict__ ow,   // [128]
                                                          const float* __restrict__ obias,// [1]
                                                          float* __restrict__ out, int nrows)
{
    extern __shared__ float sm[];
    float* Ws   = sm;             // 128x128
    float* Xs   = sm + 16384;     // 64x128
    float* wout = sm + 16384 + 8192;
    const int tid = threadIdx.x;
    const int row0 = blockIdx.x * 64;
    const int rows = min(64, nrows - row0);
    const int tx = tid & 15, ty = tid >> 4;

    if (tid < 32) ((float4*)wout)[tid] = ((const float4*)ow)[tid];
    for (int i = tid; i < 2048; i += 256) {
        int r = i >> 5, c = i & 31;
        float4 v = make_float4(0.f, 0.f, 0.f, 0.f);
        if (r < rows) v = ((const float4*)(g_x + (size_t)(row0 + r) * 128))[c];
        ((float4*)Xs)[i] = v;
    }

    for (int j = 0; j < 3; j++) {
        __syncthreads();                       // Xs stable; previous gemm done
        for (int i = tid; i < 4096; i += 256)
            ((float4*)Ws)[i] = ((const float4*)(dw + (size_t)j * 16384))[i];
        __syncthreads();
        u64 acc[4][4];
#pragma unroll
        for (int r = 0; r < 4; r++)
#pragma unroll
            for (int c = 0; c < 4; c++) acc[r][c] = 0ull;
        gemm_core8(Ws, Xs, acc, tx, ty);
        __syncthreads();                       // all Xs reads done before overwrite
        float4 blo = *(const float4*)(db + j * 128 + tx * 8);
        float4 bhi = *(const float4*)(db + j * 128 + tx * 8 + 4);
#pragma unroll
        for (int r = 0; r < 4; r++) {
            int row = ty * 4 + r;
            float2 p0 = unpack2(acc[r][0]);
            float2 p1 = unpack2(acc[r][1]);
            float2 p2 = unpack2(acc[r][2]);
            float2 p3 = unpack2(acc[r][3]);
            *(float4*)&Xs[row * 128 + tx * 8] =
                make_float4(silu_f(p0.x + blo.x), silu_f(p0.y + blo.y),
                            silu_f(p1.x + blo.z), silu_f(p1.y + blo.w));
            *(float4*)&Xs[row * 128 + tx * 8 + 4] =
                make_float4(silu_f(p2.x + bhi.x), silu_f(p2.y + bhi.y),
                            silu_f(p3.x + bhi.z), silu_f(p3.y + bhi.w));
        }
    }
    __syncthreads();

    // outproj: warp w handles rows w*8..w*8+7
    const int wid = tid >> 5, lane = tid & 31;
    float bias0 = obias[0];
    float4 wv = *(const float4*)&wout[lane * 4];
#pragma unroll
    for (int r8 = 0; r8 < 8; r8++) {
        int row = wid * 8 + r8;
        float4 xv = *(const float4*)&Xs[row * 128 + lane * 4];
        float s = xv.x * wv.x + xv.y * wv.y + xv.z * wv.z + xv.w * wv.w;
#pragma unroll
        for (int off = 16; off > 0; off >>= 1) s += __shfl_xor_sync(0xFFFFFFFFu, s, off);
        if (lane == 0 && row < rows) {
            float v = s + bias0;
            if (ACCUM) out[row0 + row] += v; else out[row0 + row] = v;
        }
    }
}

// ---------------- fused bf16-split tensor GEMM x3 (pre-split W): m += sum_j silu(A @ Wj + bj) ----------------
#define MMA_SMEM (4 * 128 * 136 * 2)
__device__ __forceinline__ void mma_bf16(float* c, const u32* a, const u32* b)
{
    asm volatile("mma.sync.aligned.m16n8k16.row.col.f32.bf16.bf16.f32 "
                 "{%0,%1,%2,%3}, {%4,%5,%6,%7}, {%8,%9}, {%0,%1,%2,%3};"
                 : "+f"(c[0]), "+f"(c[1]), "+f"(c[2]), "+f"(c[3])
                 : "r"(a[0]), "r"(a[1]), "r"(a[2]), "r"(a[3]), "r"(b[0]), "r"(b[1]));
}

__global__ void __launch_bounds__(256, 1) mma_gemm3_kernel(
    const __nv_bfloat16* __restrict__ Ahi, const __nv_bfloat16* __restrict__ Alo,
    const __nv_bfloat16* __restrict__ Wh3,  // [3][128*128] pre-split hi, [n][k]
    const __nv_bfloat16* __restrict__ Wl3,  // [3][128*128] pre-split lo
    const float* __restrict__ bias3,        // [3][128]
    float* __restrict__ Y)
{
    extern __shared__ __nv_bfloat16 smb[];
    __nv_bfloat16* sAh = smb;                 // [128][136]
    __nv_bfloat16* sAl = smb + 128 * 136;
    __nv_bfloat16* sBh = smb + 2 * 128 * 136; // [n=128][k=136]
    __nv_bfloat16* sBl = smb + 3 * 128 * 136;
    const int tid = threadIdx.x;
    const int row0 = blockIdx.x * 128;

    {
        const uint4* Ah4 = (const uint4*)(Ahi + (size_t)row0 * 128);
        const uint4* Al4 = (const uint4*)(Alo + (size_t)row0 * 128);
        for (int i = tid; i < 2048; i += 256) {
            int r = i >> 4, c = i & 15;
            *(uint4*)&sAh[r * 136 + c * 8] = Ah4[r * 16 + c];
            *(uint4*)&sAl[r * 136 + c * 8] = Al4[r * 16 + c];
        }
    }

    const int lane = tid & 31, wid = tid >> 5;
    const int wm = wid >> 1, wn = wid & 1;
    const int gid = lane >> 2, tg = lane & 3;

    float msum[2][8][4];
#pragma unroll
    for (int a = 0; a < 2; a++)
#pragma unroll
        for (int b = 0; b < 8; b++)
#pragma unroll
            for (int c = 0; c < 4; c++) msum[a][b][c] = 0.0f;

    for (int j = 0; j < 3; j++) {
        __syncthreads();
        {
            const uint4* Wh4 = (const uint4*)(Wh3 + (size_t)j * 16384);
            const uint4* Wl4 = (const uint4*)(Wl3 + (size_t)j * 16384);
            for (int i = tid; i < 2048; i += 256) {
                int r = i >> 4, c = i & 15;
                *(uint4*)&sBh[r * 136 + c * 8] = Wh4[r * 16 + c];
                *(uint4*)&sBl[r * 136 + c * 8] = Wl4[r * 16 + c];
            }
        }
        __syncthreads();

        float acc[2][8][4];
#pragma unroll
        for (int a = 0; a < 2; a++)
#pragma unroll
            for (int b = 0; b < 8; b++)
#pragma unroll
                for (int c = 0; c < 4; c++) acc[a][b][c] = 0.0f;

#pragma unroll
        for (int ks = 0; ks < 8; ks++) {
            const int kb = ks * 16;
            u32 ah[2][4], al[2][4];
#pragma unroll
            for (int fm = 0; fm < 2; fm++) {
                int r = wm * 32 + fm * 16 + gid;
                ah[fm][0] = *(const u32*)&sAh[(r)     * 136 + kb + tg * 2];
                ah[fm][1] = *(const u32*)&sAh[(r + 8) * 136 + kb + tg * 2];
                ah[fm][2] = *(const u32*)&sAh[(r)     * 136 + kb + 8 + tg * 2];
                ah[fm][3] = *(const u32*)&sAh[(r + 8) * 136 + kb + 8 + tg * 2];
                al[fm][0] = *(const u32*)&sAl[(r)     * 136 + kb + tg * 2];
                al[fm][1] = *(const u32*)&sAl[(r + 8) * 136 + kb + tg * 2];
                al[fm][2] = *(const u32*)&sAl[(r)     * 136 + kb + 8 + tg * 2];
                al[fm][3] = *(const u32*)&sAl[(r + 8) * 136 + kb + 8 + tg * 2];
            }
            u32 bh[8][2], bl[8][2];
#pragma unroll
            for (int fn = 0; fn < 8; fn++) {
                int n = wn * 64 + fn * 8 + gid;
                bh[fn][0] = *(const u32*)&sBh[n * 136 + kb + tg * 2];
                bh[fn][1] = *(const u32*)&sBh[n * 136 + kb + 8 + tg * 2];
                bl[fn][0] = *(const u32*)&sBl[n * 136 + kb + tg * 2];
                bl[fn][1] = *(const u32*)&sBl[n * 136 + kb + 8 + tg * 2];
            }
#pragma unroll
            for (int fm = 0; fm < 2; fm++)
#pragma unroll
                for (int fn = 0; fn < 8; fn++) {
                    mma_bf16(acc[fm][fn], ah[fm], bh[fn]);
                    mma_bf16(acc[fm][fn], ah[fm], bl[fn]);
                    mma_bf16(acc[fm][fn], al[fm], bh[fn]);
                }
        }

        const float* bias = bias3 + j * 128;
#pragma unroll
        for (int fm = 0; fm < 2; fm++)
#pragma unroll
            for (int fn = 0; fn < 8; fn++) {
                int col = wn * 64 + fn * 8 + tg * 2;
                float2 b2 = *(const float2*)(bias + col);
                msum[fm][fn][0] += silu_f(acc[fm][fn][0] + b2.x);
                msum[fm][fn][1] += silu_f(acc[fm][fn][1] + b2.y);
                msum[fm][fn][2] += silu_f(acc[fm][fn][2] + b2.x);
                msum[fm][fn][3] += silu_f(acc[fm][fn][3] + b2.y);
            }
    }

#pragma unroll
    for (int fm = 0; fm < 2; fm++) {
        int row = row0 + wm * 32 + fm * 16 + gid;
#pragma unroll
        for (int fn = 0; fn < 8; fn++) {
            int col = wn * 64 + fn * 8 + tg * 2;
            float* y0 = Y + (size_t)row * 128 + col;
            float2 v0 = *(float2*)y0;
            v0.x += msum[fm][fn][0];
            v0.y += msum[fm][fn][1];
            *(float2*)y0 = v0;
            float* y1 = Y + (size_t)(row + 8) * 128 + col;
            float2 v1 = *(float2*)y1;
            v1.x += msum[fm][fn][2];
            v1.y += msum[fm][fn][3];
            *(float2*)y1 = v1;
        }
    }
}

// ---------------- triplet: mkf = m[kj]*radf(d[kj])*ang[ji] (bf16 split out) + agg red.v4 ----------------
__global__ void triplet_kernel(const int* __restrict__ trip, const int* __restrict__ ei,
                               const float* __restrict__ dist)
{
    int gw = (blockIdx.x * blockDim.x + threadIdx.x) >> 5;
    int lane = threadIdx.x & 31;
    if (gw >= NEDGE) return;
    int ji = trip[gw * 3 + 0];
    int kj = trip[gw * 3 + 1];
    float aw = g_ang[ji];
    float4 mv = ((const float4*)(g_m + (size_t)kj * HID))[lane];
    float4 rv = tab_lerp_t(g_tab, dist[kj], lane);
    float4 o = make_float4(mv.x * rv.x * aw, mv.y * rv.y * aw, mv.z * rv.z * aw, mv.w * rv.w * aw);

    __nv_bfloat162 h01, h23, l01, l23;
    h01.x = __float2bfloat16(o.x); h01.y = __float2bfloat16(o.y);
    h23.x = __float2bfloat16(o.z); h23.y = __float2bfloat16(o.w);
    l01.x = __float2bfloat16(o.x - __bfloat162float(h01.x));
    l01.y = __float2bfloat16(o.y - __bfloat162float(h01.y));
    l23.x = __float2bfloat16(o.z - __bfloat162float(h23.x));
    l23.y = __float2bfloat16(o.w - __bfloat162float(h23.y));
    __nv_bfloat162* dh = (__nv_bfloat162*)(g_mkf_hi + (size_t)gw * HID);
    __nv_bfloat162* dl = (__nv_bfloat162*)(g_mkf_lo + (size_t)gw * HID);
    dh[lane * 2] = h01; dh[lane * 2 + 1] = h23;
    dl[lane * 2] = l01; dl[lane * 2 + 1] = l23;

    int dd = ei[NEDGE + gw];
    red_add_v4(g_agg + (size_t)dd * HID + lane * 4, o);
}

// ---------------- edge scatter: x[dst[e]] += h[src[e]] * radf(d[e]) ----------------
__global__ void scatter_kernel(const int* __restrict__ ei, const float* __restrict__ dist)
{
    int gw = (blockIdx.x * blockDim.x + threadIdx.x) >> 5;
    int lane = threadIdx.x & 31;
    if (gw >= NEDGE) return;
    int s  = ei[gw];
    int dd = ei[NEDGE + gw];
    float4 hv = ((const float4*)(g_h + (size_t)s * HID))[lane];
    float4 wv = tab_lerp_t(g_tab, dist[gw], lane);
    float4 o = make_float4(hv.x * wv.x, hv.y * wv.y, hv.z * wv.z, hv.w * wv.w);
    red_add_v4(g_x + (size_t)dd * HID + lane * 4, o);
}

// ---------------- host launcher ----------------
extern "C" void kernel_launch(void* const* d_in, const int* in_sizes, int n_in,
                              void* d_out, int out_size)
{
    const int*   Z        = (const int*)d_in[0];
    const int*   ei       = (const int*)d_in[1];
    const float* dist     = (const float*)d_in[2];
    const float* dirs     = (const float*)d_in[3];
    const int*   trip     = (const int*)d_in[4];
    const float* atom_emb = (const float*)d_in[5];
    const float* embed_w  = (const float*)d_in[6];
    const float* embed_b  = (const float*)d_in[7];
    const float* ib_rad_w1 = (const float*)d_in[8];
    const float* ib_rad_b1 = (const float*)d_in[9];
    const float* ib_rad_w2 = (const float*)d_in[10];
    const float* ib_rad_b2 = (const float*)d_in[11];
    const float* ib_sph_w  = (const float*)d_in[12];
    const float* ib_sph_b  = (const float*)d_in[13];
    const float* ib_upd_w1 = (const float*)d_in[14];
    const float* ib_upd_b1 = (const float*)d_in[15];
    const float* ib_upd_w2 = (const float*)d_in[16];
    const float* ib_upd_b2 = (const float*)d_in[17];
    const float* ib_out_w  = (const float*)d_in[18];
    const float* ib_out_b  = (const float*)d_in[19];
    const float* ob_rad_w1 = (const float*)d_in[20];
    const float* ob_rad_b1 = (const float*)d_in[21];
    const float* ob_rad_w2 = (const float*)d_in[22];
    const float* ob_rad_b2 = (const float*)d_in[23];
    const float* ob_dense_w = (const float*)d_in[24];
    const float* ob_dense_b = (const float*)d_in[25];
    const float* ob_out_w  = (const float*)d_in[26];
    const float* ob_out_b  = (const float*)d_in[27];
    float* out = (float*)d_out;

    float *p_m, *p_agg, *p_x, *p_tabrbf, *p_tab;
    __nv_bfloat16 *p_mkf_hi, *p_mkf_lo, *p_wbh, *p_wbl;
    cudaGetSymbolAddress((void**)&p_m,    g_m);
    cudaGetSymbolAddress((void**)&p_mkf_hi, g_mkf_hi);
    cudaGetSymbolAddress((void**)&p_mkf_lo, g_mkf_lo);
    cudaGetSymbolAddress((void**)&p_agg,  g_agg);
    cudaGetSymbolAddress((void**)&p_x,    g_x);
    cudaGetSymbolAddress((void**)&p_tabrbf, g_tabrbf);
    cudaGetSymbolAddress((void**)&p_tab,  g_tab);
    cudaGetSymbolAddress((void**)&p_wbh,  g_wbh);
    cudaGetSymbolAddress((void**)&p_wbl,  g_wbl);

    cudaFuncSetAttribute(rad_mlp_kernel, cudaFuncAttributeMaxDynamicSharedMemorySize, RAD_SMEM);
    cudaFuncSetAttribute(mma_gemm3_kernel, cudaFuncAttributeMaxDynamicSharedMemorySize, MMA_SMEM);
    cudaFuncSetAttribute(hupdate_kernel, cudaFuncAttributeMaxDynamicSharedMemorySize, HUPD_SMEM);
    cudaFuncSetAttribute(outblock_kernel<false>, cudaFuncAttributeMaxDynamicSharedMemorySize, OUT_SMEM);
    cudaFuncSetAttribute(outblock_kernel<true >, cudaFuncAttributeMaxDynamicSharedMemorySize, OUT_SMEM);

    const int GT = NTAB / 64;             // 256
    const int GA = (NATOM + 63) / 64;     // 157
    const int GW = NEDGE * 32 / 256;      // 40000
    const int GM = NEDGE / 128;           // 2500

    // ---- prologue ----
    tab_prep_kernel<<<NTAB / 256, 256>>>();
    tabm_kernel<<<NTAB / 8, 256>>>(embed_w, embed_b);
    wsplit_kernel<<<(12 * HID * HID + 255) / 256, 256>>>(ib_out_w);
    h_init_kernel<<<(NATOM * 32 + 255) / 256, 256>>>(Z, atom_emb);
    m_interp_kernel<<<GW, 256>>>(dist);

    // ---- output block 0 ----
    rad_mlp_kernel<<<GT, 256, RAD_SMEM>>>(p_tabrbf, ob_rad_w1, ob_rad_b1, ob_rad_w2, ob_rad_b2, p_tab, NTAB);
    cudaMemsetAsync(p_x, 0, (size_t)NATOM * HID * sizeof(float));
    scatter_kernel<<<GW, 256>>>(ei, dist);
    outblock_kernel<false><<<GA, 256, OUT_SMEM>>>(ob_dense_w, ob_dense_b, ob_out_w, ob_out_b, out, NATOM);

    for (int i = 0; i < 4; i++) {
        rad_mlp_kernel<<<GT, 256, RAD_SMEM>>>(p_tabrbf,
                                              ib_rad_w1 + (size_t)i * 2048, ib_rad_b1 + i * 128,
                                              ib_rad_w2 + (size_t)i * 16384, ib_rad_b2 + i * 128,
                                              p_tab, NTAB);
        angle_kernel<<<(NEDGE + 255) / 256, 256>>>(ib_sph_w + i * 56, ib_sph_b + i * 8, dirs);
        cudaMemsetAsync(p_agg, 0, (size_t)NATOM * HID * sizeof(float));
        triplet_kernel<<<GW, 256>>>(trip, ei, dist);
        hupdate_kernel<<<GA, 256, HUPD_SMEM>>>(ib_upd_w1 + (size_t)i * 32768, ib_upd_b1 + i * 128,
                                               ib_upd_w2 + (size_t)i * 16384, ib_upd_b2 + i * 128, NATOM);
        mma_gemm3_kernel<<<GM, 256, MMA_SMEM>>>(p_mkf_hi, p_mkf_lo,
            p_wbh + (size_t)i * 3 * 16384, p_wbl + (size_t)i * 3 * 16384,
            ib_out_b + i * 3 * 128, p_m);
        // ---- output block i+1 ----
        int ob = i + 1;
        rad_mlp_kernel<<<GT, 256, RAD_SMEM>>>(p_tabrbf,
                                              ob_rad_w1 + (size_t)ob * 2048, ob_rad_b1 + ob * 128,
                                              ob_rad_w2 + (size_t)ob * 16384, ob_rad_b2 + ob * 128,
                                              p_tab, NTAB);
        cudaMemsetAsync(p_x, 0, (size_t)NATOM * HID * sizeof(float));
        scatter_kernel<<<GW, 256>>>(ei, dist);
        outblock_kernel<true><<<GA, 256, OUT_SMEM>>>(ob_dense_w + (size_t)ob * 3 * 16384,
                                                     ob_dense_b + ob * 3 * 128,
                                                     ob_out_w + ob * 128, ob_out_b + ob, out, NATOM);
    }
}

// round 7
// speedup vs baseline: 3.1181x; 1.2416x over previous
#include <cuda_runtime.h>
#include <cuda_bf16.h>
#include <math_constants.h>

#define NEDGE 320000
#define NATOM 10000
#define HID   128
#define CUT   5.0f
#define NTAB  16384

typedef unsigned long long u64;
typedef unsigned int u32;

// ---------------- scratch (static device memory; no allocations) ----------------
__device__ __align__(16) float g_m   [(size_t)NEDGE * HID];
__device__ __align__(16) __nv_bfloat16 g_mkf_hi[(size_t)NEDGE * HID];
__device__ __align__(16) __nv_bfloat16 g_mkf_lo[(size_t)NEDGE * HID];
__device__ __align__(16) float g_ang [NEDGE];
__device__ __align__(16) float g_h   [(size_t)NATOM * HID];
__device__ __align__(16) float g_agg [(size_t)NATOM * HID];
__device__ __align__(16) float g_x   [(size_t)NATOM * HID];
__device__ __align__(16) float g_tabrbf[(size_t)NTAB * 16];
__device__ __align__(16) float g_tab_ib[(size_t)NTAB * HID];
__device__ __align__(16) float g_tab_ob[(size_t)NTAB * HID];
__device__ __align__(16) float g_tabm[(size_t)NTAB * HID];
__device__ __align__(16) __nv_bfloat16 g_wbh[(size_t)9 * HID * HID];  // ib_out_w hi, [n][k]
__device__ __align__(16) __nv_bfloat16 g_wbl[(size_t)9 * HID * HID];  // ib_out_w lo, [n][k]

__device__ __forceinline__ float silu_f(float x) { return x / (1.0f + __expf(-x)); }

__device__ __forceinline__ void red_add_v4(float* p, float4 v)
{
    asm volatile("red.global.add.v4.f32 [%0], {%1,%2,%3,%4};"
                 :: "l"(p), "f"(v.x), "f"(v.y), "f"(v.z), "f"(v.w) : "memory");
}

// ---------------- packed f32x2 helpers ----------------
__device__ __forceinline__ u64 pack2(float a) {
    u64 r; asm("mov.b64 %0, {%1, %1};" : "=l"(r) : "f"(a)); return r;
}
__device__ __forceinline__ void fma2(u64& d, u64 a, u64 b) {
    asm("fma.rn.f32x2 %0, %1, %2, %3;" : "=l"(d) : "l"(a), "l"(b), "l"(d));
}
__device__ __forceinline__ float2 unpack2(u64 v) {
    float2 f; asm("mov.b64 {%0, %1}, %2;" : "=f"(f.x), "=f"(f.y) : "l"(v)); return f;
}

// ---------------- bessel rbf ----------------
__device__ __forceinline__ void rbf_eval(float d, float* out16)
{
    float x = d * (1.0f / CUT);
    float x2 = x * x;
    float x6 = x2 * x2 * x2;
    float x7 = x6 * x;
    float x8 = x7 * x;
    float env = 1.0f - 28.0f * x6 + 48.0f * x7 - 21.0f * x8;
    if (!(d < CUT)) env = 0.0f;
    float s = sqrtf(2.0f / CUT) / d * env;
    float base = (float)CUDART_PI_F / CUT * d;
#pragma unroll
    for (int k = 0; k < 16; k++)
        out16[k] = s * sinf(base * (float)(k + 1));
}

__global__ void tab_prep_kernel()
{
    int i = blockIdx.x * blockDim.x + threadIdx.x;
    if (i >= NTAB) return;
    float d = fmaxf((float)i * (CUT / (float)(NTAB - 1)), 1e-4f);
    float r16[16];
    rbf_eval(d, r16);
#pragma unroll
    for (int k = 0; k < 16; k++) g_tabrbf[(size_t)i * 16 + k] = r16[k];
}

__device__ __forceinline__ float4 tab_lerp_t(const float* tab, float d, int lane)
{
    float t = d * ((float)(NTAB - 1) / CUT);
    int i0 = min((int)t, NTAB - 2);
    float f = t - (float)i0;
    float4 lo = ((const float4*)(tab + (size_t)i0 * HID))[lane];
    float4 hi = ((const float4*)(tab + (size_t)(i0 + 1) * HID))[lane];
    float4 o;
    o.x = lo.x + (hi.x - lo.x) * f;
    o.y = lo.y + (hi.y - lo.y) * f;
    o.z = lo.z + (hi.z - lo.z) * f;
    o.w = lo.w + (hi.w - lo.w) * f;
    return o;
}

// ---------------- m table: tabm = tabrbf @ embed_w[:,256:384] + embed_b[256:] ----------------
__global__ void tabm_kernel(const float* __restrict__ embed_w, const float* __restrict__ embed_b)
{
    __shared__ float Ws[16 * 128];
    __shared__ float bs[128];
    __shared__ float rs[8 * 16];
    int tid = threadIdx.x;
    for (int i = tid; i < 2048; i += 256)
        Ws[i] = embed_w[(i >> 7) * 384 + 256 + (i & 127)];
    if (tid < 128) bs[tid] = embed_b[256 + tid];
    int e0 = blockIdx.x * 8;
    if (tid < 128) rs[tid] = g_tabrbf[(size_t)e0 * 16 + tid];
    __syncthreads();
    int w = tid >> 5, lane = tid & 31;
    int e = e0 + w;
    float4 acc = *(const float4*)&bs[lane * 4];
#pragma unroll
    for (int k = 0; k < 16; k++) {
        float a = rs[w * 16 + k];
        float4 wv = *(const float4*)&Ws[k * 128 + lane * 4];
        acc.x += a * wv.x; acc.y += a * wv.y; acc.z += a * wv.z; acc.w += a * wv.w;
    }
    ((float4*)(g_tabm + (size_t)e * HID))[lane] = acc;
}

__global__ void m_interp_kernel(const float* __restrict__ dist)
{
    int gw = (blockIdx.x * blockDim.x + threadIdx.x) >> 5;
    int lane = threadIdx.x & 31;
    if (gw >= NEDGE) return;
    float4 o = tab_lerp_t(g_tabm, dist[gw], lane);
    ((float4*)(g_m + (size_t)gw * HID))[lane] = o;
}

// ---------------- pre-split ib_out_w (mats 0..8) -> bf16 hi/lo, transposed [n][k] ----------------
__global__ void wsplit_kernel(const float* __restrict__ W)
{
    int i = blockIdx.x * blockDim.x + threadIdx.x;
    if (i >= 9 * HID * HID) return;
    int mat = i >> 14;
    int r = i & 16383;
    int k = r >> 7, n = r & 127;
    float w = W[i];
    __nv_bfloat16 h = __float2bfloat16(w);
    float rr = w - __bfloat162float(h);
    size_t o = (size_t)mat * 16384 + n * 128 + k;
    g_wbh[o] = h;
    g_wbl[o] = __float2bfloat16(rr);
}

__global__ void h_init_kernel(const int* __restrict__ Z, const float* __restrict__ emb)
{
    int idx = blockIdx.x * blockDim.x + threadIdx.x;
    int a = idx >> 5, lane = idx & 31;
    if (a >= NATOM) return;
    int z = Z[a] - 1;
    ((float4*)(g_h + (size_t)a * HID))[lane] =
        ((const float4*)(emb + (size_t)z * HID))[lane];
}

__global__ void angle_kernel(const float* __restrict__ sphW, const float* __restrict__ sphB,
                             const float* __restrict__ dirs)
{
    __shared__ float wbar[8];
    __shared__ float bbar;
    if (threadIdx.x < 7) {
        float s = 0.0f;
#pragma unroll
        for (int j = 0; j < 8; j++) s += sphW[threadIdx.x * 8 + j];
        wbar[threadIdx.x] = s * 0.125f;
    }
    if (threadIdx.x == 7) {
        float s = 0.0f;
#pragma unroll
        for (int j = 0; j < 8; j++) s += sphB[j];
        bbar = s * 0.125f;
    }
    __syncthreads();
    int e = blockIdx.x * blockDim.x + threadIdx.x;
    if (e >= NEDGE) return;
    float dx = dirs[e * 3 + 0], dy = dirs[e * 3 + 1], dz = dirs[e * 3 + 2];
    float acc = bbar + wbar[0] + wbar[1] * dy + wbar[2] * dz + wbar[3] * dx
              + wbar[4] * dx * dy + wbar[5] * dy * dz + wbar[6] * (3.0f * dz * dz - 1.0f);
    g_ang[e] = 1.0f / (1.0f + __expf(-acc));
}

// ---------------- SIMT GEMM core (f32x2, 4 rows x 8 cols per thread) ----------------
__device__ __forceinline__ void gemm_core8(const float* __restrict__ Ws,
                                           const float* __restrict__ Xs,
                                           u64 acc[4][4], int tx, int ty)
{
#pragma unroll 2
    for (int k0 = 0; k0 < 128; k0 += 4) {
        float4 av[4];
#pragma unroll
        for (int r = 0; r < 4; r++)
            av[r] = *(const float4*)(Xs + (ty * 4 + r) * 128 + k0);
#pragma unroll
        for (int kk = 0; kk < 4; kk++) {
            ulonglong2 b01 = *(const ulonglong2*)(Ws + (k0 + kk) * 128 + tx * 8);
            ulonglong2 b23 = *(const ulonglong2*)(Ws + (k0 + kk) * 128 + tx * 8 + 4);
#pragma unroll
            for (int r = 0; r < 4; r++) {
                float aval = ((const float*)&av[r])[kk];
                u64 ap = pack2(aval);
                fma2(acc[r][0], ap, b01.x);
                fma2(acc[r][1], ap, b01.y);
                fma2(acc[r][2], ap, b23.x);
                fma2(acc[r][3], ap, b23.y);
            }
        }
    }
}

// ---------------- fused radial MLP on the distance table ----------------
#define RAD_SMEM ((16384 + 8192 + 2048 + 128 + 1024) * 4)
__global__ void __launch_bounds__(256, 2) rad_mlp_kernel(const float* __restrict__ rbf_in,
                                                         const float* __restrict__ rW1,
                                                         const float* __restrict__ rb1,
                                                         const float* __restrict__ rW2,
                                                         const float* __restrict__ rb2,
                                                         float* __restrict__ Y, int nrows)
{
    extern __shared__ float sm[];
    float* W2s = sm;
    float* Hs  = sm + 16384;
    float* W1s = sm + 16384 + 8192;
    float* b1s = W1s + 2048;
    float* Rs  = b1s + 128;
    const int tid = threadIdx.x;
    const int row0 = blockIdx.x * 64;
    for (int i = tid; i < 4096; i += 256) ((float4*)W2s)[i] = ((const float4*)rW2)[i];
    for (int i = tid; i < 512;  i += 256) ((float4*)W1s)[i] = ((const float4*)rW1)[i];
    if (tid < 32) ((float4*)b1s)[tid] = ((const float4*)rb1)[tid];
    const int rows = min(64, nrows - row0);
    {
        int i = tid;
        int r = i >> 2;
        float4 v = make_float4(0.f, 0.f, 0.f, 0.f);
        if (r < rows) v = ((const float4*)(rbf_in + (size_t)(row0 + r) * 16))[i & 3];
        ((float4*)Rs)[i] = v;
    }
    __syncthreads();
    {
        const int tx5 = tid & 31, ty5 = tid >> 5;
        float4 b1v = *(const float4*)&b1s[tx5 * 4];
#pragma unroll
        for (int i = 0; i < 8; i++) {
            int r = ty5 * 8 + i;
            float4 a4 = b1v;
#pragma unroll
            for (int k = 0; k < 16; k++) {
                float a = Rs[r * 16 + k];
                float4 w = *(const float4*)&W1s[k * 128 + tx5 * 4];
                a4.x += a * w.x; a4.y += a * w.y; a4.z += a * w.z; a4.w += a * w.w;
            }
            a4.x = silu_f(a4.x); a4.y = silu_f(a4.y); a4.z = silu_f(a4.z); a4.w = silu_f(a4.w);
            *(float4*)&Hs[r * 128 + tx5 * 4] = a4;
        }
    }
    __syncthreads();
    const int tx = tid & 15, ty = tid >> 4;
    u64 acc[4][4];
#pragma unroll
    for (int r = 0; r < 4; r++)
#pragma unroll
        for (int c = 0; c < 4; c++) acc[r][c] = 0ull;
    gemm_core8(W2s, Hs, acc, tx, ty);
    float4 blo = *(const float4*)(rb2 + tx * 8);
    float4 bhi = *(const float4*)(rb2 + tx * 8 + 4);
#pragma unroll
    for (int r = 0; r < 4; r++) {
        int row = ty * 4 + r;
        if (row >= rows) break;
        float2 p0 = unpack2(acc[r][0]);
        float2 p1 = unpack2(acc[r][1]);
        float2 p2 = unpack2(acc[r][2]);
        float2 p3 = unpack2(acc[r][3]);
        float* yp = Y + (size_t)(row0 + row) * 128 + tx * 8;
        *(float4*)yp       = make_float4(p0.x + blo.x, p0.y + blo.y, p1.x + blo.z, p1.y + blo.w);
        *(float4*)(yp + 4) = make_float4(p2.x + bhi.x, p2.y + bhi.y, p3.x + bhi.z, p3.y + bhi.w);
    }
}

// ---------------- fused h update: h += silu([h,agg]@W1 + b1) @ W2 + b2 ----------------
#define HUPD_SMEM ((16384 + 8192) * 4)
__global__ void __launch_bounds__(256, 2) hupdate_kernel(const float* __restrict__ w1,
                                                         const float* __restrict__ b1,
                                                         const float* __restrict__ w2,
                                                         const float* __restrict__ b2,
                                                         int nrows)
{
    extern __shared__ float sm[];
    float* Ws = sm;
    float* Xs = sm + 16384;
    const int tid = threadIdx.x;
    const int row0 = blockIdx.x * 64;
    const int rows = min(64, nrows - row0);
    const int tx = tid & 15, ty = tid >> 4;

    for (int i = tid; i < 2048; i += 256) {
        int r = i >> 5, c = i & 31;
        float4 v = make_float4(0.f, 0.f, 0.f, 0.f);
        if (r < rows) v = ((const float4*)(g_h + (size_t)(row0 + r) * 128))[c];
        ((float4*)Xs)[i] = v;
    }
    for (int i = tid; i < 4096; i += 256) ((float4*)Ws)[i] = ((const float4*)w1)[i];
    __syncthreads();
    u64 acc[4][4];
#pragma unroll
    for (int r = 0; r < 4; r++)
#pragma unroll
        for (int c = 0; c < 4; c++) acc[r][c] = 0ull;
    gemm_core8(Ws, Xs, acc, tx, ty);
    __syncthreads();

    for (int i = tid; i < 2048; i += 256) {
        int r = i >> 5, c = i & 31;
        float4 v = make_float4(0.f, 0.f, 0.f, 0.f);
        if (r < rows) v = ((const float4*)(g_agg + (size_t)(row0 + r) * 128))[c];
        ((float4*)Xs)[i] = v;
    }
    for (int i = tid; i < 4096; i += 256) ((float4*)Ws)[i] = ((const float4*)(w1 + 16384))[i];
    __syncthreads();
    gemm_core8(Ws, Xs, acc, tx, ty);
    __syncthreads();

    {
        float4 blo = *(const float4*)(b1 + tx * 8);
        float4 bhi = *(const float4*)(b1 + tx * 8 + 4);
#pragma unroll
        for (int r = 0; r < 4; r++) {
            int row = ty * 4 + r;
            float2 p0 = unpack2(acc[r][0]);
            float2 p1 = unpack2(acc[r][1]);
            float2 p2 = unpack2(acc[r][2]);
            float2 p3 = unpack2(acc[r][3]);
            *(float4*)&Xs[row * 128 + tx * 8] =
                make_float4(silu_f(p0.x + blo.x), silu_f(p0.y + blo.y),
                            silu_f(p1.x + blo.z), silu_f(p1.y + blo.w));
            *(float4*)&Xs[row * 128 + tx * 8 + 4] =
                make_float4(silu_f(p2.x + bhi.x), silu_f(p2.y + bhi.y),
                            silu_f(p3.x + bhi.z), silu_f(p3.y + bhi.w));
        }
    }
    for (int i = tid; i < 4096; i += 256) ((float4*)Ws)[i] = ((const float4*)w2)[i];
    __syncthreads();

#pragma unroll
    for (int r = 0; r < 4; r++)
#pragma unroll
        for (int c = 0; c < 4; c++) acc[r][c] = 0ull;
    gemm_core8(Ws, Xs, acc, tx, ty);
    {
        float4 blo = *(const float4*)(b2 + tx * 8);
        float4 bhi = *(const float4*)(b2 + tx * 8 + 4);
#pragma unroll
        for (int r = 0; r < 4; r++) {
            int row = ty * 4 + r;
            if (row >= rows) break;
            float2 p0 = unpack2(acc[r][0]);
            float2 p1 = unpack2(acc[r][1]);
            float2 p2 = unpack2(acc[r][2]);
            float2 p3 = unpack2(acc[r][3]);
            float* hp = g_h + (size_t)(row0 + row) * 128 + tx * 8;
            float4 u0 = *(float4*)hp;
            float4 u1 = *(float4*)(hp + 4);
            u0.x += p0.x + blo.x; u0.y += p0.y + blo.y; u0.z += p1.x + blo.z; u0.w += p1.y + blo.w;
            u1.x += p2.x + bhi.x; u1.y += p2.y + bhi.y; u1.z += p3.x + bhi.z; u1.w += p3.y + bhi.w;
            *(float4*)hp = u0;
            *(float4*)(hp + 4) = u1;
        }
    }
}

// ---------------- fused output block ----------------
#define OUT_SMEM ((16384 + 8192 + 128) * 4)
template<bool ACCUM>
__global__ void __launch_bounds__(256, 2) outblock_kernel(const float* __restrict__ dw,
                                                          const float* __restrict__ db,
                                                          const float* __restrict__ ow,
                                                          const float* __restrict__ obias,
                                                          float* __restrict__ out, int nrows)
{
    extern __shared__ float sm[];
    float* Ws   = sm;
    float* Xs   = sm + 16384;
    float* wout = sm + 16384 + 8192;
    const int tid = threadIdx.x;
    const int row0 = blockIdx.x * 64;
    const int rows = min(64, nrows - row0);
    const int tx = tid & 15, ty = tid >> 4;

    if (tid < 32) ((float4*)wout)[tid] = ((const float4*)ow)[tid];
    for (int i = tid; i < 2048; i += 256) {
        int r = i >> 5, c = i & 31;
        float4 v = make_float4(0.f, 0.f, 0.f, 0.f);
        if (r < rows) v = ((const float4*)(g_x + (size_t)(row0 + r) * 128))[c];
        ((float4*)Xs)[i] = v;
    }

    for (int j = 0; j < 3; j++) {
        __syncthreads();
        for (int i = tid; i < 4096; i += 256)
            ((float4*)Ws)[i] = ((const float4*)(dw + (size_t)j * 16384))[i];
        __syncthreads();
        u64 acc[4][4];
#pragma unroll
        for (int r = 0; r < 4; r++)
#pragma unroll
            for (int c = 0; c < 4; c++) acc[r][c] = 0ull;
        gemm_core8(Ws, Xs, acc, tx, ty);
        __syncthreads();
        float4 blo = *(const float4*)(db + j * 128 + tx * 8);
        float4 bhi = *(const float4*)(db + j * 128 + tx * 8 + 4);
#pragma unroll
        for (int r = 0; r < 4; r++) {
            int row = ty * 4 + r;
            float2 p0 = unpack2(acc[r][0]);
            float2 p1 = unpack2(acc[r][1]);
            float2 p2 = unpack2(acc[r][2]);
            float2 p3 = unpack2(acc[r][3]);
            *(float4*)&Xs[row * 128 + tx * 8] =
                make_float4(silu_f(p0.x + blo.x), silu_f(p0.y + blo.y),
                            silu_f(p1.x + blo.z), silu_f(p1.y + blo.w));
            *(float4*)&Xs[row * 128 + tx * 8 + 4] =
                make_float4(silu_f(p2.x + bhi.x), silu_f(p2.y + bhi.y),
                            silu_f(p3.x + bhi.z), silu_f(p3.y + bhi.w));
        }
    }
    __syncthreads();

    const int wid = tid >> 5, lane = tid & 31;
    float bias0 = obias[0];
    float4 wv = *(const float4*)&wout[lane * 4];
#pragma unroll
    for (int r8 = 0; r8 < 8; r8++) {
        int row = wid * 8 + r8;
        float4 xv = *(const float4*)&Xs[row * 128 + lane * 4];
        float s = xv.x * wv.x + xv.y * wv.y + xv.z * wv.z + xv.w * wv.w;
#pragma unroll
        for (int off = 16; off > 0; off >>= 1) s += __shfl_xor_sync(0xFFFFFFFFu, s, off);
        if (lane == 0 && row < rows) {
            float v = s + bias0;
            if (ACCUM) out[row0 + row] += v; else out[row0 + row] = v;
        }
    }
}

// ---------------- fused bf16-split tensor GEMM x3 (pre-split W) ----------------
#define MMA_SMEM (4 * 128 * 136 * 2)
__device__ __forceinline__ void mma_bf16(float* c, const u32* a, const u32* b)
{
    asm volatile("mma.sync.aligned.m16n8k16.row.col.f32.bf16.bf16.f32 "
                 "{%0,%1,%2,%3}, {%4,%5,%6,%7}, {%8,%9}, {%0,%1,%2,%3};"
                 : "+f"(c[0]), "+f"(c[1]), "+f"(c[2]), "+f"(c[3])
                 : "r"(a[0]), "r"(a[1]), "r"(a[2]), "r"(a[3]), "r"(b[0]), "r"(b[1]));
}

__global__ void __launch_bounds__(256, 1) mma_gemm3_kernel(
    const __nv_bfloat16* __restrict__ Ahi, const __nv_bfloat16* __restrict__ Alo,
    const __nv_bfloat16* __restrict__ Wh3, const __nv_bfloat16* __restrict__ Wl3,
    const float* __restrict__ bias3, float* __restrict__ Y)
{
    extern __shared__ __nv_bfloat16 smb[];
    __nv_bfloat16* sAh = smb;
    __nv_bfloat16* sAl = smb + 128 * 136;
    __nv_bfloat16* sBh = smb + 2 * 128 * 136;
    __nv_bfloat16* sBl = smb + 3 * 128 * 136;
    const int tid = threadIdx.x;
    const int row0 = blockIdx.x * 128;

    {
        const uint4* Ah4 = (const uint4*)(Ahi + (size_t)row0 * 128);
        const uint4* Al4 = (const uint4*)(Alo + (size_t)row0 * 128);
        for (int i = tid; i < 2048; i += 256) {
            int r = i >> 4, c = i & 15;
            *(uint4*)&sAh[r * 136 + c * 8] = Ah4[r * 16 + c];
            *(uint4*)&sAl[r * 136 + c * 8] = Al4[r * 16 + c];
        }
    }

    const int lane = tid & 31, wid = tid >> 5;
    const int wm = wid >> 1, wn = wid & 1;
    const int gid = lane >> 2, tg = lane & 3;

    float msum[2][8][4];
#pragma unroll
    for (int a = 0; a < 2; a++)
#pragma unroll
        for (int b = 0; b < 8; b++)
#pragma unroll
            for (int c = 0; c < 4; c++) msum[a][b][c] = 0.0f;

    for (int j = 0; j < 3; j++) {
        __syncthreads();
        {
            const uint4* Wh4 = (const uint4*)(Wh3 + (size_t)j * 16384);
            const uint4* Wl4 = (const uint4*)(Wl3 + (size_t)j * 16384);
            for (int i = tid; i < 2048; i += 256) {
                int r = i >> 4, c = i & 15;
                *(uint4*)&sBh[r * 136 + c * 8] = Wh4[r * 16 + c];
                *(uint4*)&sBl[r * 136 + c * 8] = Wl4[r * 16 + c];
            }
        }
        __syncthreads();

        float acc[2][8][4];
#pragma unroll
        for (int a = 0; a < 2; a++)
#pragma unroll
            for (int b = 0; b < 8; b++)
#pragma unroll
                for (int c = 0; c < 4; c++) acc[a][b][c] = 0.0f;

#pragma unroll
        for (int ks = 0; ks < 8; ks++) {
            const int kb = ks * 16;
            u32 ah[2][4], al[2][4];
#pragma unroll
            for (int fm = 0; fm < 2; fm++) {
                int r = wm * 32 + fm * 16 + gid;
                ah[fm][0] = *(const u32*)&sAh[(r)     * 136 + kb + tg * 2];
                ah[fm][1] = *(const u32*)&sAh[(r + 8) * 136 + kb + tg * 2];
                ah[fm][2] = *(const u32*)&sAh[(r)     * 136 + kb + 8 + tg * 2];
                ah[fm][3] = *(const u32*)&sAh[(r + 8) * 136 + kb + 8 + tg * 2];
                al[fm][0] = *(const u32*)&sAl[(r)     * 136 + kb + tg * 2];
                al[fm][1] = *(const u32*)&sAl[(r + 8) * 136 + kb + tg * 2];
                al[fm][2] = *(const u32*)&sAl[(r)     * 136 + kb + 8 + tg * 2];
                al[fm][3] = *(const u32*)&sAl[(r + 8) * 136 + kb + 8 + tg * 2];
            }
            u32 bh[8][2], bl[8][2];
#pragma unroll
            for (int fn = 0; fn < 8; fn++) {
                int n = wn * 64 + fn * 8 + gid;
                bh[fn][0] = *(const u32*)&sBh[n * 136 + kb + tg * 2];
                bh[fn][1] = *(const u32*)&sBh[n * 136 + kb + 8 + tg * 2];
                bl[fn][0] = *(const u32*)&sBl[n * 136 + kb + tg * 2];
                bl[fn][1] = *(const u32*)&sBl[n * 136 + kb + 8 + tg * 2];
            }
#pragma unroll
            for (int fm = 0; fm < 2; fm++)
#pragma unroll
                for (int fn = 0; fn < 8; fn++) {
                    mma_bf16(acc[fm][fn], ah[fm], bh[fn]);
                    mma_bf16(acc[fm][fn], ah[fm], bl[fn]);
                    mma_bf16(acc[fm][fn], al[fm], bh[fn]);
                }
        }

        const float* bias = bias3 + j * 128;
#pragma unroll
        for (int fm = 0; fm < 2; fm++)
#pragma unroll
            for (int fn = 0; fn < 8; fn++) {
                int col = wn * 64 + fn * 8 + tg * 2;
                float2 b2 = *(const float2*)(bias + col);
                msum[fm][fn][0] += silu_f(acc[fm][fn][0] + b2.x);
                msum[fm][fn][1] += silu_f(acc[fm][fn][1] + b2.y);
                msum[fm][fn][2] += silu_f(acc[fm][fn][2] + b2.x);
                msum[fm][fn][3] += silu_f(acc[fm][fn][3] + b2.y);
            }
    }

#pragma unroll
    for (int fm = 0; fm < 2; fm++) {
        int row = row0 + wm * 32 + fm * 16 + gid;
#pragma unroll
        for (int fn = 0; fn < 8; fn++) {
            int col = wn * 64 + fn * 8 + tg * 2;
            float* y0 = Y + (size_t)row * 128 + col;
            float2 v0 = *(float2*)y0;
            v0.x += msum[fm][fn][0];
            v0.y += msum[fm][fn][1];
            *(float2*)y0 = v0;
            float* y1 = Y + (size_t)(row + 8) * 128 + col;
            float2 v1 = *(float2*)y1;
            v1.x += msum[fm][fn][2];
            v1.y += msum[fm][fn][3];
            *(float2*)y1 = v1;
        }
    }
}

// ---------------- triplet ----------------
__global__ void triplet_kernel(const int* __restrict__ trip, const int* __restrict__ ei,
                               const float* __restrict__ dist)
{
    int gw = (blockIdx.x * blockDim.x + threadIdx.x) >> 5;
    int lane = threadIdx.x & 31;
    if (gw >= NEDGE) return;
    int ji = trip[gw * 3 + 0];
    int kj = trip[gw * 3 + 1];
    float aw = g_ang[ji];
    float4 mv = ((const float4*)(g_m + (size_t)kj * HID))[lane];
    float4 rv = tab_lerp_t(g_tab_ib, dist[kj], lane);
    float4 o = make_float4(mv.x * rv.x * aw, mv.y * rv.y * aw, mv.z * rv.z * aw, mv.w * rv.w * aw);

    __nv_bfloat162 h01, h23, l01, l23;
    h01.x = __float2bfloat16(o.x); h01.y = __float2bfloat16(o.y);
    h23.x = __float2bfloat16(o.z); h23.y = __float2bfloat16(o.w);
    l01.x = __float2bfloat16(o.x - __bfloat162float(h01.x));
    l01.y = __float2bfloat16(o.y - __bfloat162float(h01.y));
    l23.x = __float2bfloat16(o.z - __bfloat162float(h23.x));
    l23.y = __float2bfloat16(o.w - __bfloat162float(h23.y));
    __nv_bfloat162* dh = (__nv_bfloat162*)(g_mkf_hi + (size_t)gw * HID);
    __nv_bfloat162* dl = (__nv_bfloat162*)(g_mkf_lo + (size_t)gw * HID);
    dh[lane * 2] = h01; dh[lane * 2 + 1] = h23;
    dl[lane * 2] = l01; dl[lane * 2 + 1] = l23;

    int dd = ei[NEDGE + gw];
    red_add_v4(g_agg + (size_t)dd * HID + lane * 4, o);
}

// ---------------- edge scatter ----------------
__global__ void scatter_kernel(const int* __restrict__ ei, const float* __restrict__ dist)
{
    int gw = (blockIdx.x * blockDim.x + threadIdx.x) >> 5;
    int lane = threadIdx.x & 31;
    if (gw >= NEDGE) return;
    int s  = ei[gw];
    int dd = ei[NEDGE + gw];
    float4 hv = ((const float4*)(g_h + (size_t)s * HID))[lane];
    float4 wv = tab_lerp_t(g_tab_ob, dist[gw], lane);
    float4 o = make_float4(hv.x * wv.x, hv.y * wv.y, hv.z * wv.z, hv.w * wv.w);
    red_add_v4(g_x + (size_t)dd * HID + lane * 4, o);
}

// ---------------- host launcher ----------------
extern "C" void kernel_launch(void* const* d_in, const int* in_sizes, int n_in,
                              void* d_out, int out_size)
{
    const int*   Z        = (const int*)d_in[0];
    const int*   ei       = (const int*)d_in[1];
    const float* dist     = (const float*)d_in[2];
    const float* dirs     = (const float*)d_in[3];
    const int*   trip     = (const int*)d_in[4];
    const float* atom_emb = (const float*)d_in[5];
    const float* embed_w  = (const float*)d_in[6];
    const float* embed_b  = (const float*)d_in[7];
    const float* ib_rad_w1 = (const float*)d_in[8];
    const float* ib_rad_b1 = (const float*)d_in[9];
    const float* ib_rad_w2 = (const float*)d_in[10];
    const float* ib_rad_b2 = (const float*)d_in[11];
    const float* ib_sph_w  = (const float*)d_in[12];
    const float* ib_sph_b  = (const float*)d_in[13];
    const float* ib_upd_w1 = (const float*)d_in[14];
    const float* ib_upd_b1 = (const float*)d_in[15];
    const float* ib_upd_w2 = (const float*)d_in[16];
    const float* ib_upd_b2 = (const float*)d_in[17];
    const float* ib_out_w  = (const float*)d_in[18];
    const float* ib_out_b  = (const float*)d_in[19];
    const float* ob_rad_w1 = (const float*)d_in[20];
    const float* ob_rad_b1 = (const float*)d_in[21];
    const float* ob_rad_w2 = (const float*)d_in[22];
    const float* ob_rad_b2 = (const float*)d_in[23];
    const float* ob_dense_w = (const float*)d_in[24];
    const float* ob_dense_b = (const float*)d_in[25];
    const float* ob_out_w  = (const float*)d_in[26];
    const float* ob_out_b  = (const float*)d_in[27];
    float* out = (float*)d_out;

    float *p_agg, *p_x, *p_tabrbf, *p_tab_ib, *p_tab_ob, *p_m;
    __nv_bfloat16 *p_mkf_hi, *p_mkf_lo, *p_wbh, *p_wbl;
    cudaGetSymbolAddress((void**)&p_m,    g_m);
    cudaGetSymbolAddress((void**)&p_mkf_hi, g_mkf_hi);
    cudaGetSymbolAddress((void**)&p_mkf_lo, g_mkf_lo);
    cudaGetSymbolAddress((void**)&p_agg,  g_agg);
    cudaGetSymbolAddress((void**)&p_x,    g_x);
    cudaGetSymbolAddress((void**)&p_tabrbf, g_tabrbf);
    cudaGetSymbolAddress((void**)&p_tab_ib, g_tab_ib);
    cudaGetSymbolAddress((void**)&p_tab_ob, g_tab_ob);
    cudaGetSymbolAddress((void**)&p_wbh,  g_wbh);
    cudaGetSymbolAddress((void**)&p_wbl,  g_wbl);

    cudaFuncSetAttribute(rad_mlp_kernel, cudaFuncAttributeMaxDynamicSharedMemorySize, RAD_SMEM);
    cudaFuncSetAttribute(mma_gemm3_kernel, cudaFuncAttributeMaxDynamicSharedMemorySize, MMA_SMEM);
    cudaFuncSetAttribute(hupdate_kernel, cudaFuncAttributeMaxDynamicSharedMemorySize, HUPD_SMEM);
    cudaFuncSetAttribute(outblock_kernel<false>, cudaFuncAttributeMaxDynamicSharedMemorySize, OUT_SMEM);
    cudaFuncSetAttribute(outblock_kernel<true >, cudaFuncAttributeMaxDynamicSharedMemorySize, OUT_SMEM);

    const int GT = NTAB / 64;
    const int GA = (NATOM + 63) / 64;
    const int GW = NEDGE * 32 / 256;
    const int GM = NEDGE / 128;

    // second stream + events (created fresh; host-side ops, not captured as work)
    cudaStream_t sB;
    cudaStreamCreateWithFlags(&sB, cudaStreamNonBlocking);
    cudaEvent_t eTab, eB[5], eTrip[4];
    cudaEventCreateWithFlags(&eTab, cudaEventDisableTiming);
    for (int i = 0; i < 5; i++) cudaEventCreateWithFlags(&eB[i], cudaEventDisableTiming);
    for (int i = 0; i < 4; i++) cudaEventCreateWithFlags(&eTrip[i], cudaEventDisableTiming);

    // ---- prologue (A = legacy default stream) ----
    tab_prep_kernel<<<NTAB / 256, 256>>>();
    cudaEventRecord(eTab, 0);

    // ---- B prologue (fork) ----
    cudaStreamWaitEvent(sB, eTab, 0);
    wsplit_kernel<<<(9 * HID * HID + 255) / 256, 256, 0, sB>>>(ib_out_w);
    h_init_kernel<<<(NATOM * 32 + 255) / 256, 256, 0, sB>>>(Z, atom_emb);
    rad_mlp_kernel<<<GT, 256, RAD_SMEM, sB>>>(p_tabrbf,
        ib_rad_w1, ib_rad_b1, ib_rad_w2, ib_rad_b2, p_tab_ib, NTAB);
    angle_kernel<<<(NEDGE + 255) / 256, 256, 0, sB>>>(ib_sph_w, ib_sph_b, dirs);
    cudaEventRecord(eB[0], sB);

    // ---- A prologue cont. + output block 0 ----
    tabm_kernel<<<NTAB / 8, 256>>>(embed_w, embed_b);
    m_interp_kernel<<<GW, 256>>>(dist);
    rad_mlp_kernel<<<GT, 256, RAD_SMEM>>>(p_tabrbf, ob_rad_w1, ob_rad_b1, ob_rad_w2, ob_rad_b2,
                                          p_tab_ob, NTAB);
    cudaMemsetAsync(p_x, 0, (size_t)NATOM * HID * sizeof(float));
    cudaStreamWaitEvent(0, eB[0], 0);   // h_init + (tab_ib, ang for triplet_0)
    scatter_kernel<<<GW, 256>>>(ei, dist);
    outblock_kernel<false><<<GA, 256, OUT_SMEM>>>(ob_dense_w, ob_dense_b, ob_out_w, ob_out_b, out, NATOM);

    for (int i = 0; i < 4; i++) {
        if (i > 0) cudaStreamWaitEvent(0, eB[i], 0);   // m updated, tab_ib_i, ang_i ready
        cudaMemsetAsync(p_agg, 0, (size_t)NATOM * HID * sizeof(float));
        triplet_kernel<<<GW, 256>>>(trip, ei, dist);
        cudaEventRecord(eTrip[i], 0);
        hupdate_kernel<<<GA, 256, HUPD_SMEM>>>(ib_upd_w1 + (size_t)i * 32768, ib_upd_b1 + i * 128,
                                               ib_upd_w2 + (size_t)i * 16384, ib_upd_b2 + i * 128, NATOM);

        // ---- B: m update + next-iter radial/angle, overlapped with A's output chain ----
        if (i < 3) {
            cudaStreamWaitEvent(sB, eTrip[i], 0);
            mma_gemm3_kernel<<<GM, 256, MMA_SMEM, sB>>>(p_mkf_hi, p_mkf_lo,
                p_wbh + (size_t)i * 3 * 16384, p_wbl + (size_t)i * 3 * 16384,
                ib_out_b + i * 3 * 128, p_m);
            rad_mlp_kernel<<<GT, 256, RAD_SMEM, sB>>>(p_tabrbf,
                ib_rad_w1 + (size_t)(i + 1) * 2048, ib_rad_b1 + (i + 1) * 128,
                ib_rad_w2 + (size_t)(i + 1) * 16384, ib_rad_b2 + (i + 1) * 128,
                p_tab_ib, NTAB);
            angle_kernel<<<(NEDGE + 255) / 256, 256, 0, sB>>>(ib_sph_w + (i + 1) * 56,
                                                              ib_sph_b + (i + 1) * 8, dirs);
            cudaEventRecord(eB[i + 1], sB);
        }

        // ---- A: output block i+1 ----
        int ob = i + 1;
        rad_mlp_kernel<<<GT, 256, RAD_SMEM>>>(p_tabrbf,
            ob_rad_w1 + (size_t)ob * 2048, ob_rad_b1 + ob * 128,
            ob_rad_w2 + (size_t)ob * 16384, ob_rad_b2 + ob * 128, p_tab_ob, NTAB);
        cudaMemsetAsync(p_x, 0, (size_t)NATOM * HID * sizeof(float));
        scatter_kernel<<<GW, 256>>>(ei, dist);
        outblock_kernel<true><<<GA, 256, OUT_SMEM>>>(ob_dense_w + (size_t)ob * 3 * 16384,
                                                     ob_dense_b + ob * 3 * 128,
                                                     ob_out_w + ob * 128, ob_out_b + ob, out, NATOM);
    }
    // B fully joined: last B work (eB[3]) is waited at loop top of i=3.
}